// round 1
// baseline (speedup 1.0000x reference)
#include <cuda_runtime.h>

// ---------------------------------------------------------------------------
// Problem constants (fixed by the reference)
// ---------------------------------------------------------------------------
static constexpr int NPAPER  = 200000;
static constexpr int NAUTHOR = 100000;
static constexpr int HID     = 128;     // 4 heads x 32 channels
static constexpr int ECITES  = 1000000;
static constexpr int EWRITES = 500000;
static constexpr int EWB     = 500000;

static constexpr size_t SZ_P = (size_t)NPAPER * HID;    // 25,600,000 floats
static constexpr size_t SZ_A = (size_t)NAUTHOR * HID;   // 12,800,000 floats
static constexpr size_t V_P  = (size_t)NPAPER * 4;      // per-node per-head
static constexpr size_t V_A  = (size_t)NAUTHOR * 4;

// scratch layout (floats)
static constexpr size_t O_XPA  = 0;
static constexpr size_t O_XAA  = O_XPA  + SZ_P;
static constexpr size_t O_XPB  = O_XAA  + SZ_A;
static constexpr size_t O_XAB  = O_XPB  + SZ_P;
static constexpr size_t O_HP0  = O_XAB  + SZ_A;   // xp @ W[0]
static constexpr size_t O_HP1  = O_HP0  + SZ_P;   // xp @ W[1]
static constexpr size_t O_HP2  = O_HP1  + SZ_P;   // xp @ W[2]
static constexpr size_t O_HA1  = O_HP2  + SZ_P;   // xa @ W[1]
static constexpr size_t O_HA2  = O_HA1  + SZ_A;   // xa @ W[2]
static constexpr size_t O_ASC  = O_HA2  + SZ_A;   // src logits, cites (paper)
static constexpr size_t O_ADC  = O_ASC  + V_P;    // dst logits, cites (paper)
static constexpr size_t O_ASW  = O_ADC  + V_P;    // src logits, writes (author)
static constexpr size_t O_ADW  = O_ASW  + V_A;    // dst logits, writes (paper)
static constexpr size_t O_ASB  = O_ADW  + V_P;    // src logits, wb (paper)
static constexpr size_t O_ADB  = O_ASB  + V_P;    // dst logits, wb (author)
static constexpr size_t O_MC   = O_ADB  + V_A;    // seg max, cites
static constexpr size_t O_SC   = O_MC   + V_P;    // seg sum, cites
static constexpr size_t O_MW   = O_SC   + V_P;
static constexpr size_t O_SW   = O_MW   + V_P;
static constexpr size_t O_MB   = O_SW   + V_P;    // author-sized
static constexpr size_t O_SB   = O_MB   + V_A;
static constexpr size_t O_ACCC = O_SB   + V_A;    // unnormalized out, cites
static constexpr size_t O_ACCW = O_ACCC + SZ_P;
static constexpr size_t O_ACCB = O_ACCW + SZ_P;   // author-sized
static constexpr size_t SCRATCH_FLOATS = O_ACCB + SZ_A;  // ~251.2M floats ~ 1.0 GB

__device__ float g_scratch[SCRATCH_FLOATS];

// ---------------------------------------------------------------------------
// SGEMM: C[M,N] = A[M,K] @ B[K,N] (+ bias[N]), fp32, row-major.
// K % BK == 0, N % BN == 0 (true for all calls). M guarded.
// ---------------------------------------------------------------------------
template <int BM, int BN, int BK, int TM, int TN>
__global__ void __launch_bounds__((BM / TM) * (BN / TN))
sgemm_k(const float* __restrict__ A, const float* __restrict__ B,
        const float* __restrict__ bias, float* __restrict__ C,
        int M, int N, int K) {
    constexpr int THREADS = (BM / TM) * (BN / TN);
    __shared__ float As[BK][BM + 4];
    __shared__ float Bs[BK][BN];

    const int tid  = threadIdx.x;
    const int row0 = blockIdx.x * BM;
    const int col0 = blockIdx.y * BN;
    const int tcol = (tid % (BN / TN)) * TN;
    const int trow = (tid / (BN / TN)) * TM;

    float acc[TM][TN];
#pragma unroll
    for (int m = 0; m < TM; m++)
#pragma unroll
        for (int n = 0; n < TN; n++) acc[m][n] = 0.f;

    for (int k0 = 0; k0 < K; k0 += BK) {
        constexpr int AV = (BM * BK) / (4 * THREADS);
#pragma unroll
        for (int i = 0; i < AV; i++) {
            int v  = tid + i * THREADS;
            int ar = v / (BK / 4);
            int ac = (v % (BK / 4)) * 4;
            int gr = row0 + ar;
            float4 val = make_float4(0.f, 0.f, 0.f, 0.f);
            if (gr < M)
                val = *reinterpret_cast<const float4*>(A + (size_t)gr * K + k0 + ac);
            As[ac + 0][ar] = val.x;
            As[ac + 1][ar] = val.y;
            As[ac + 2][ar] = val.z;
            As[ac + 3][ar] = val.w;
        }
        constexpr int BV = (BK * BN) / (4 * THREADS);
#pragma unroll
        for (int i = 0; i < BV; i++) {
            int v  = tid + i * THREADS;
            int br = v / (BN / 4);
            int bc = (v % (BN / 4)) * 4;
            *reinterpret_cast<float4*>(&Bs[br][bc]) =
                *reinterpret_cast<const float4*>(B + (size_t)(k0 + br) * N + col0 + bc);
        }
        __syncthreads();

#pragma unroll
        for (int kk = 0; kk < BK; kk++) {
            float a[TM], b[TN];
#pragma unroll
            for (int m = 0; m < TM; m++) a[m] = As[kk][trow + m];
#pragma unroll
            for (int n = 0; n < TN; n++) b[n] = Bs[kk][tcol + n];
#pragma unroll
            for (int m = 0; m < TM; m++)
#pragma unroll
                for (int n = 0; n < TN; n++) acc[m][n] = fmaf(a[m], b[n], acc[m][n]);
        }
        __syncthreads();
    }

#pragma unroll
    for (int m = 0; m < TM; m++) {
        int gr = row0 + trow + m;
        if (gr < M) {
#pragma unroll
            for (int n = 0; n < TN; n += 4) {
                int gc = col0 + tcol + n;
                float4 o;
                o.x = acc[m][n + 0];
                o.y = acc[m][n + 1];
                o.z = acc[m][n + 2];
                o.w = acc[m][n + 3];
                if (bias) {
                    o.x += bias[gc + 0];
                    o.y += bias[gc + 1];
                    o.z += bias[gc + 2];
                    o.w += bias[gc + 3];
                }
                *reinterpret_cast<float4*>(C + (size_t)gr * N + gc) = o;
            }
        }
    }
}

// ---------------------------------------------------------------------------
// Attention logits: out[n,h] = sum_c H[n, h*32+c] * att[h*32+c]
// One warp per node; lane = channel within head.
// ---------------------------------------------------------------------------
__global__ void attn_k(const float* __restrict__ Hb,
                       const float* __restrict__ att_s, const float* __restrict__ att_d,
                       float* __restrict__ out_s, float* __restrict__ out_d, int Nn) {
    int warp = (blockIdx.x * blockDim.x + threadIdx.x) >> 5;
    int lane = threadIdx.x & 31;
    if (warp >= Nn) return;
    const float* hr = Hb + (size_t)warp * HID;
    float h0 = hr[lane], h1 = hr[32 + lane], h2 = hr[64 + lane], h3 = hr[96 + lane];

    float s0 = 0.f, s1 = 0.f, s2 = 0.f, s3 = 0.f;
    float d0 = 0.f, d1 = 0.f, d2 = 0.f, d3 = 0.f;
    if (out_s) {
        s0 = h0 * att_s[lane];       s1 = h1 * att_s[32 + lane];
        s2 = h2 * att_s[64 + lane];  s3 = h3 * att_s[96 + lane];
    }
    if (out_d) {
        d0 = h0 * att_d[lane];       d1 = h1 * att_d[32 + lane];
        d2 = h2 * att_d[64 + lane];  d3 = h3 * att_d[96 + lane];
    }
#pragma unroll
    for (int off = 16; off > 0; off >>= 1) {
        s0 += __shfl_xor_sync(0xffffffffu, s0, off);
        s1 += __shfl_xor_sync(0xffffffffu, s1, off);
        s2 += __shfl_xor_sync(0xffffffffu, s2, off);
        s3 += __shfl_xor_sync(0xffffffffu, s3, off);
        d0 += __shfl_xor_sync(0xffffffffu, d0, off);
        d1 += __shfl_xor_sync(0xffffffffu, d1, off);
        d2 += __shfl_xor_sync(0xffffffffu, d2, off);
        d3 += __shfl_xor_sync(0xffffffffu, d3, off);
    }
    if (lane == 0) {
        if (out_s) {
            out_s[(size_t)warp * 4 + 0] = s0; out_s[(size_t)warp * 4 + 1] = s1;
            out_s[(size_t)warp * 4 + 2] = s2; out_s[(size_t)warp * 4 + 3] = s3;
        }
        if (out_d) {
            out_d[(size_t)warp * 4 + 0] = d0; out_d[(size_t)warp * 4 + 1] = d1;
            out_d[(size_t)warp * 4 + 2] = d2; out_d[(size_t)warp * 4 + 3] = d3;
        }
    }
}

// ---------------------------------------------------------------------------
// Float atomic max (signed-int / unsigned-min trick; init must be -inf/NaN bits)
// ---------------------------------------------------------------------------
__device__ __forceinline__ void atomicMaxF(float* addr, float val) {
    if (val >= 0.f) atomicMax((int*)addr, __float_as_int(val));
    else            atomicMin((unsigned int*)addr, __float_as_uint(val));
}

__device__ __forceinline__ float lrelu02(float v) { return v > 0.f ? v : 0.2f * v; }

// Pass A: per-dst per-head segment max of edge logits. One thread per edge.
__global__ void edge_max_k(const int* __restrict__ src, const int* __restrict__ dst,
                           const float* __restrict__ as_, const float* __restrict__ ad_,
                           float* __restrict__ m, int E) {
    int e = blockIdx.x * blockDim.x + threadIdx.x;
    if (e >= E) return;
    int s = src[e], d = dst[e];
    float4 a = *reinterpret_cast<const float4*>(as_ + (size_t)s * 4);
    float4 b = *reinterpret_cast<const float4*>(ad_ + (size_t)d * 4);
    float* md = m + (size_t)d * 4;
    atomicMaxF(md + 0, lrelu02(a.x + b.x));
    atomicMaxF(md + 1, lrelu02(a.y + b.y));
    atomicMaxF(md + 2, lrelu02(a.z + b.z));
    atomicMaxF(md + 3, lrelu02(a.w + b.w));
}

// Pass B+C fused: accumulate ex into s[dst] and ex*hs[src] into acc[dst].
// One warp per edge; lane = channel within head.
__global__ void edge_agg_k(const int* __restrict__ src, const int* __restrict__ dst,
                           const float* __restrict__ as_, const float* __restrict__ ad_,
                           const float* __restrict__ m, const float* __restrict__ Hs,
                           float* __restrict__ ssum, float* __restrict__ acc, int E) {
    int gid  = blockIdx.x * blockDim.x + threadIdx.x;
    int e    = gid >> 5;
    int lane = threadIdx.x & 31;
    if (e >= E) return;
    int sn = src[e], dn = dst[e];
    float4 a  = *reinterpret_cast<const float4*>(as_ + (size_t)sn * 4);
    float4 b  = *reinterpret_cast<const float4*>(ad_ + (size_t)dn * 4);
    float4 mm = *reinterpret_cast<const float4*>(m + (size_t)dn * 4);
    float x0 = __expf(lrelu02(a.x + b.x) - mm.x);
    float x1 = __expf(lrelu02(a.y + b.y) - mm.y);
    float x2 = __expf(lrelu02(a.z + b.z) - mm.z);
    float x3 = __expf(lrelu02(a.w + b.w) - mm.w);

    if (lane < 4) {
        float xv = (lane == 0) ? x0 : (lane == 1) ? x1 : (lane == 2) ? x2 : x3;
        atomicAdd(ssum + (size_t)dn * 4 + lane, xv);
    }
    const float* hr = Hs + (size_t)sn * HID;
    float* ar = acc + (size_t)dn * HID;
    atomicAdd(ar + lane,      hr[lane]      * x0);
    atomicAdd(ar + 32 + lane, hr[32 + lane] * x1);
    atomicAdd(ar + 64 + lane, hr[64 + lane] * x2);
    atomicAdd(ar + 96 + lane, hr[96 + lane] * x3);
}

// Combine: normalize per relation, sum relations + biases, optional leaky(0.01).
__global__ void combine2_k(const float* __restrict__ acc1, const float* __restrict__ s1,
                           const float* __restrict__ acc2, const float* __restrict__ s2,
                           const float* __restrict__ bb, float* __restrict__ out,
                           int Nn, int act) {
    size_t idx = (size_t)blockIdx.x * blockDim.x + threadIdx.x;
    if (idx >= (size_t)Nn * HID) return;
    int i = (int)(idx & 127);
    size_t n = idx >> 7;
    int h = i >> 5;
    float v = acc1[idx] / (s1[n * 4 + h] + 1e-16f)
            + acc2[idx] / (s2[n * 4 + h] + 1e-16f)
            + bb[i] + bb[128 + i];
    if (act) v = v > 0.f ? v : 0.01f * v;
    out[idx] = v;
}

__global__ void combine1_k(const float* __restrict__ acc1, const float* __restrict__ s1,
                           const float* __restrict__ bb, float* __restrict__ out,
                           int Nn, int act) {
    size_t idx = (size_t)blockIdx.x * blockDim.x + threadIdx.x;
    if (idx >= (size_t)Nn * HID) return;
    int i = (int)(idx & 127);
    size_t n = idx >> 7;
    int h = i >> 5;
    float v = acc1[idx] / (s1[n * 4 + h] + 1e-16f) + bb[i];
    if (act) v = v > 0.f ? v : 0.01f * v;
    out[idx] = v;
}

// ---------------------------------------------------------------------------
// Host orchestration
// ---------------------------------------------------------------------------
extern "C" void kernel_launch(void* const* d_in, const int* in_sizes, int n_in,
                              void* d_out, int out_size) {
    const float* x_paper  = (const float*)d_in[0];
    const float* x_author = (const float*)d_in[1];
    const float* Wp   = (const float*)d_in[2];
    const float* bp   = (const float*)d_in[3];
    const float* Wa   = (const float*)d_in[4];
    const float* ba   = (const float*)d_in[5];
    const float* W0   = (const float*)d_in[6];
    const float* as0  = (const float*)d_in[7];
    const float* ad0  = (const float*)d_in[8];
    const float* b0   = (const float*)d_in[9];
    const float* W1   = (const float*)d_in[10];
    const float* as1  = (const float*)d_in[11];
    const float* ad1  = (const float*)d_in[12];
    const float* b1   = (const float*)d_in[13];
    const float* Wlin = (const float*)d_in[14];
    const float* blin = (const float*)d_in[15];
    const int* src_c  = (const int*)d_in[16];
    const int* dst_c  = (const int*)d_in[17];
    const int* src_w  = (const int*)d_in[18];
    const int* dst_w  = (const int*)d_in[19];
    const int* src_b  = (const int*)d_in[20];
    const int* dst_b  = (const int*)d_in[21];

    float* S = nullptr;
    cudaGetSymbolAddress((void**)&S, g_scratch);

    float* XPA  = S + O_XPA;
    float* XAA  = S + O_XAA;
    float* XPB  = S + O_XPB;
    float* XAB  = S + O_XAB;
    float* HP0  = S + O_HP0;
    float* HP1  = S + O_HP1;
    float* HP2  = S + O_HP2;
    float* HA1  = S + O_HA1;
    float* HA2  = S + O_HA2;
    float* ASC  = S + O_ASC;
    float* ADC  = S + O_ADC;
    float* ASW  = S + O_ASW;
    float* ADW  = S + O_ADW;
    float* ASB  = S + O_ASB;
    float* ADB  = S + O_ADB;
    float* MC   = S + O_MC;
    float* SC   = S + O_SC;
    float* MW   = S + O_MW;
    float* SW   = S + O_SW;
    float* MB   = S + O_MB;
    float* SB   = S + O_SB;
    float* ACCC = S + O_ACCC;
    float* ACCW = S + O_ACCW;
    float* ACCB = S + O_ACCB;

    const dim3 gp((NPAPER + 127) / 128, 1);
    const dim3 ga((NAUTHOR + 127) / 128, 1);

    // ---- input projections ----
    sgemm_k<128, 128, 16, 8, 8><<<gp, 256>>>(x_paper,  Wp, bp, XPA, NPAPER,  128, 256);
    sgemm_k<128, 128, 16, 8, 8><<<ga, 256>>>(x_author, Wa, ba, XAA, NAUTHOR, 128, 128);

    for (int l = 0; l < 2; l++) {
        const float* W   = l ? W1  : W0;
        const float* as_ = l ? as1 : as0;
        const float* ad_ = l ? ad1 : ad0;
        const float* bb  = l ? b1  : b0;
        const float* xp  = l ? XPB : XPA;
        const float* xa  = l ? XAB : XAA;

        // feature transforms (layer 1: skip wb relation, its output is dead)
        sgemm_k<128, 128, 16, 8, 8><<<gp, 256>>>(xp, W + 0 * HID * HID, nullptr, HP0, NPAPER,  128, 128);
        sgemm_k<128, 128, 16, 8, 8><<<gp, 256>>>(xp, W + 1 * HID * HID, nullptr, HP1, NPAPER,  128, 128);
        sgemm_k<128, 128, 16, 8, 8><<<ga, 256>>>(xa, W + 1 * HID * HID, nullptr, HA1, NAUTHOR, 128, 128);
        if (!l) {
            sgemm_k<128, 128, 16, 8, 8><<<gp, 256>>>(xp, W + 2 * HID * HID, nullptr, HP2, NPAPER,  128, 128);
            sgemm_k<128, 128, 16, 8, 8><<<ga, 256>>>(xa, W + 2 * HID * HID, nullptr, HA2, NAUTHOR, 128, 128);
        }

        // attention logits
        const int abp = (NPAPER + 7) / 8, aba = (NAUTHOR + 7) / 8;
        attn_k<<<abp, 256>>>(HP0, as_ + 0,   ad_ + 0,   ASC, ADC, NPAPER);
        attn_k<<<aba, 256>>>(HA1, as_ + 128, nullptr,   ASW, nullptr, NAUTHOR);
        attn_k<<<abp, 256>>>(HP1, nullptr,   ad_ + 128, nullptr, ADW, NPAPER);
        if (!l) {
            attn_k<<<abp, 256>>>(HP2, as_ + 256, nullptr, ASB, nullptr, NPAPER);
            attn_k<<<aba, 256>>>(HA2, nullptr, ad_ + 256, nullptr, ADB, NAUTHOR);
        }

        // init segment buffers (0xFF fills = NaN/-inf bits: valid init for atomicMaxF)
        cudaMemsetAsync(MC, 0xFF, V_P * sizeof(float));
        cudaMemsetAsync(MW, 0xFF, V_P * sizeof(float));
        cudaMemsetAsync(SC, 0, V_P * sizeof(float));
        cudaMemsetAsync(SW, 0, V_P * sizeof(float));
        cudaMemsetAsync(ACCC, 0, SZ_P * sizeof(float));
        cudaMemsetAsync(ACCW, 0, SZ_P * sizeof(float));
        if (!l) {
            cudaMemsetAsync(MB, 0xFF, V_A * sizeof(float));
            cudaMemsetAsync(SB, 0, V_A * sizeof(float));
            cudaMemsetAsync(ACCB, 0, SZ_A * sizeof(float));
        }

        // pass A: segment max
        edge_max_k<<<(ECITES + 255) / 256, 256>>>(src_c, dst_c, ASC, ADC, MC, ECITES);
        edge_max_k<<<(EWRITES + 255) / 256, 256>>>(src_w, dst_w, ASW, ADW, MW, EWRITES);
        if (!l)
            edge_max_k<<<(EWB + 255) / 256, 256>>>(src_b, dst_b, ASB, ADB, MB, EWB);

        // pass B+C fused: exp-sum + weighted aggregation (one warp per edge)
        edge_agg_k<<<(int)(((size_t)ECITES * 32 + 255) / 256), 256>>>(
            src_c, dst_c, ASC, ADC, MC, HP0, SC, ACCC, ECITES);
        edge_agg_k<<<(int)(((size_t)EWRITES * 32 + 255) / 256), 256>>>(
            src_w, dst_w, ASW, ADW, MW, HA1, SW, ACCW, EWRITES);
        if (!l)
            edge_agg_k<<<(int)(((size_t)EWB * 32 + 255) / 256), 256>>>(
                src_b, dst_b, ASB, ADB, MB, HP2, SB, ACCB, EWB);

        // combine: normalize + sum relations + bias (+ leaky 0.01 between layers)
        combine2_k<<<(int)((SZ_P + 255) / 256), 256>>>(
            ACCC, SC, ACCW, SW, bb, l ? XPA : XPB, NPAPER, l == 0);
        if (!l)
            combine1_k<<<(int)((SZ_A + 255) / 256), 256>>>(
                ACCB, SB, bb + 256, XAB, NAUTHOR, 1);
    }

    // final classifier: [200000,128] @ [128,64] + blin
    sgemm_k<128, 64, 16, 8, 8><<<gp, 128>>>(XPA, Wlin, blin, (float*)d_out,
                                            NPAPER, 64, 128);
}

// round 2
// speedup vs baseline: 1.0319x; 1.0319x over previous
#include <cuda_runtime.h>

// ---------------------------------------------------------------------------
// Problem constants
// ---------------------------------------------------------------------------
static constexpr int NPAPER  = 200000;
static constexpr int NAUTHOR = 100000;
static constexpr int HID     = 128;     // 4 heads x 32 channels
static constexpr int ECITES  = 1000000;
static constexpr int EWRITES = 500000;
static constexpr int EWB     = 500000;

static constexpr size_t SZ_P = (size_t)NPAPER * HID;
static constexpr size_t SZ_A = (size_t)NAUTHOR * HID;
static constexpr size_t V_P  = (size_t)NPAPER * 4;
static constexpr size_t V_A  = (size_t)NAUTHOR * 4;

// scratch layout (floats). SC/SW/SB contiguous; ACCC/ACCW/ACCB contiguous
// so one memset clears each group.
static constexpr size_t O_XPA  = 0;
static constexpr size_t O_XAA  = O_XPA  + SZ_P;
static constexpr size_t O_XPB  = O_XAA  + SZ_A;
static constexpr size_t O_XAB  = O_XPB  + SZ_P;
static constexpr size_t O_HP0  = O_XAB  + SZ_A;
static constexpr size_t O_HP1  = O_HP0  + SZ_P;
static constexpr size_t O_HP2  = O_HP1  + SZ_P;
static constexpr size_t O_HA1  = O_HP2  + SZ_P;
static constexpr size_t O_HA2  = O_HA1  + SZ_A;
static constexpr size_t O_ASC  = O_HA2  + SZ_A;
static constexpr size_t O_ADC  = O_ASC  + V_P;
static constexpr size_t O_ASW  = O_ADC  + V_P;
static constexpr size_t O_ADW  = O_ASW  + V_A;
static constexpr size_t O_ASB  = O_ADW  + V_P;
static constexpr size_t O_ADB  = O_ASB  + V_P;
static constexpr size_t O_SC   = O_ADB  + V_A;
static constexpr size_t O_SW   = O_SC   + V_P;
static constexpr size_t O_SB   = O_SW   + V_P;
static constexpr size_t O_ACCC = O_SB   + V_A;
static constexpr size_t O_ACCW = O_ACCC + SZ_P;
static constexpr size_t O_ACCB = O_ACCW + SZ_P;
static constexpr size_t SCRATCH_FLOATS = O_ACCB + SZ_A;

__device__ float g_scratch[SCRATCH_FLOATS];

// ---------------------------------------------------------------------------
// Double-buffered SGEMM: C[M,N] = A[M,K] @ B[K,N] (+ bias), fp32 row-major.
// Register-prefetch pipeline: LDG next tile -> FFMA current -> STS next -> bar.
// One __syncthreads per K-tile. K % BK == 0, N % BN == 0; M guarded.
// ---------------------------------------------------------------------------
template <int BM, int BN, int BK, int TM, int TN>
__global__ void __launch_bounds__((BM / TM) * (BN / TN), 2)
sgemm_db(const float* __restrict__ A, const float* __restrict__ B,
         const float* __restrict__ bias, float* __restrict__ C,
         int M, int N, int K) {
    constexpr int THREADS = (BM / TM) * (BN / TN);
    constexpr int AV = (BM * BK) / (4 * THREADS);
    constexpr int BV = (BK * BN) / (4 * THREADS);
    __shared__ float As[2][BK][BM + 4];
    __shared__ float Bs[2][BK][BN];

    const int tid  = threadIdx.x;
    const int row0 = blockIdx.x * BM;
    const int col0 = blockIdx.y * BN;
    const int tcol = (tid % (BN / TN)) * TN;
    const int trow = (tid / (BN / TN)) * TM;

    float4 pa[AV], pb[BV];

    auto ldg_tile = [&](int k0) {
#pragma unroll
        for (int i = 0; i < AV; i++) {
            int v  = tid + i * THREADS;
            int ar = v / (BK / 4);
            int ac = (v % (BK / 4)) * 4;
            int gr = row0 + ar;
            pa[i] = (gr < M)
                ? *reinterpret_cast<const float4*>(A + (size_t)gr * K + k0 + ac)
                : make_float4(0.f, 0.f, 0.f, 0.f);
        }
#pragma unroll
        for (int i = 0; i < BV; i++) {
            int v  = tid + i * THREADS;
            int br = v / (BN / 4);
            int bc = (v % (BN / 4)) * 4;
            pb[i] = *reinterpret_cast<const float4*>(B + (size_t)(k0 + br) * N + col0 + bc);
        }
    };
    auto sts_tile = [&](int st) {
#pragma unroll
        for (int i = 0; i < AV; i++) {
            int v  = tid + i * THREADS;
            int ar = v / (BK / 4);
            int ac = (v % (BK / 4)) * 4;
            As[st][ac + 0][ar] = pa[i].x;
            As[st][ac + 1][ar] = pa[i].y;
            As[st][ac + 2][ar] = pa[i].z;
            As[st][ac + 3][ar] = pa[i].w;
        }
#pragma unroll
        for (int i = 0; i < BV; i++) {
            int v  = tid + i * THREADS;
            int br = v / (BN / 4);
            int bc = (v % (BN / 4)) * 4;
            *reinterpret_cast<float4*>(&Bs[st][br][bc]) = pb[i];
        }
    };

    float acc[TM][TN];
#pragma unroll
    for (int m = 0; m < TM; m++)
#pragma unroll
        for (int n = 0; n < TN; n++) acc[m][n] = 0.f;

    ldg_tile(0);
    sts_tile(0);
    __syncthreads();

    const int nt = K / BK;
    for (int t = 0; t < nt; t++) {
        const int cur = t & 1;
        if (t + 1 < nt) ldg_tile((t + 1) * BK);
#pragma unroll
        for (int kk = 0; kk < BK; kk++) {
            float a[TM], b[TN];
#pragma unroll
            for (int m = 0; m < TM; m++) a[m] = As[cur][kk][trow + m];
#pragma unroll
            for (int n = 0; n < TN; n++) b[n] = Bs[cur][kk][tcol + n];
#pragma unroll
            for (int m = 0; m < TM; m++)
#pragma unroll
                for (int n = 0; n < TN; n++) acc[m][n] = fmaf(a[m], b[n], acc[m][n]);
        }
        if (t + 1 < nt) sts_tile(cur ^ 1);
        __syncthreads();
    }

#pragma unroll
    for (int m = 0; m < TM; m++) {
        int gr = row0 + trow + m;
        if (gr < M) {
#pragma unroll
            for (int n = 0; n < TN; n += 4) {
                int gc = col0 + tcol + n;
                float4 o;
                o.x = acc[m][n + 0];
                o.y = acc[m][n + 1];
                o.z = acc[m][n + 2];
                o.w = acc[m][n + 3];
                if (bias) {
                    o.x += bias[gc + 0];
                    o.y += bias[gc + 1];
                    o.z += bias[gc + 2];
                    o.w += bias[gc + 3];
                }
                *reinterpret_cast<float4*>(C + (size_t)gr * N + gc) = o;
            }
        }
    }
}

// ---------------------------------------------------------------------------
// Attention logits: out[n,h] = sum_c H[n, h*32+c] * att[h*32+c]
// ---------------------------------------------------------------------------
__global__ void attn_k(const float* __restrict__ Hb,
                       const float* __restrict__ att_s, const float* __restrict__ att_d,
                       float* __restrict__ out_s, float* __restrict__ out_d, int Nn) {
    int warp = (blockIdx.x * blockDim.x + threadIdx.x) >> 5;
    int lane = threadIdx.x & 31;
    if (warp >= Nn) return;
    const float* hr = Hb + (size_t)warp * HID;
    float h0 = hr[lane], h1 = hr[32 + lane], h2 = hr[64 + lane], h3 = hr[96 + lane];

    float s0 = 0.f, s1 = 0.f, s2 = 0.f, s3 = 0.f;
    float d0 = 0.f, d1 = 0.f, d2 = 0.f, d3 = 0.f;
    if (out_s) {
        s0 = h0 * att_s[lane];       s1 = h1 * att_s[32 + lane];
        s2 = h2 * att_s[64 + lane];  s3 = h3 * att_s[96 + lane];
    }
    if (out_d) {
        d0 = h0 * att_d[lane];       d1 = h1 * att_d[32 + lane];
        d2 = h2 * att_d[64 + lane];  d3 = h3 * att_d[96 + lane];
    }
#pragma unroll
    for (int off = 16; off > 0; off >>= 1) {
        s0 += __shfl_xor_sync(0xffffffffu, s0, off);
        s1 += __shfl_xor_sync(0xffffffffu, s1, off);
        s2 += __shfl_xor_sync(0xffffffffu, s2, off);
        s3 += __shfl_xor_sync(0xffffffffu, s3, off);
        d0 += __shfl_xor_sync(0xffffffffu, d0, off);
        d1 += __shfl_xor_sync(0xffffffffu, d1, off);
        d2 += __shfl_xor_sync(0xffffffffu, d2, off);
        d3 += __shfl_xor_sync(0xffffffffu, d3, off);
    }
    if (lane == 0) {
        if (out_s) {
            out_s[(size_t)warp * 4 + 0] = s0; out_s[(size_t)warp * 4 + 1] = s1;
            out_s[(size_t)warp * 4 + 2] = s2; out_s[(size_t)warp * 4 + 3] = s3;
        }
        if (out_d) {
            out_d[(size_t)warp * 4 + 0] = d0; out_d[(size_t)warp * 4 + 1] = d1;
            out_d[(size_t)warp * 4 + 2] = d2; out_d[(size_t)warp * 4 + 3] = d3;
        }
    }
}

__device__ __forceinline__ float lrelu02(float v) { return v > 0.f ? v : 0.2f * v; }

// Vectorized global reduction: one REDG for 4 consecutive floats (sm_90+).
__device__ __forceinline__ void red_add_v4(float* p, float a, float b, float c, float d) {
    asm volatile("red.global.add.v4.f32 [%0], {%1, %2, %3, %4};"
                 :: "l"(p), "f"(a), "f"(b), "f"(c), "f"(d) : "memory");
}

// ---------------------------------------------------------------------------
// Fused edge pass (no max-shift: softmax is shift-invariant and logits are
// O(1) here, so exp cannot overflow): accumulate exp(e) into ssum[dst] and
// exp(e)*hs[src] into acc[dst]. One warp per edge; lane owns 4 channels.
// ---------------------------------------------------------------------------
__global__ void edge_agg_k(const int* __restrict__ src, const int* __restrict__ dst,
                           const float* __restrict__ as_, const float* __restrict__ ad_,
                           const float* __restrict__ Hs,
                           float* __restrict__ ssum, float* __restrict__ acc, int E) {
    int e    = (blockIdx.x * blockDim.x + threadIdx.x) >> 5;
    int lane = threadIdx.x & 31;
    if (e >= E) return;
    int sn = src[e], dn = dst[e];
    float4 a = *reinterpret_cast<const float4*>(as_ + (size_t)sn * 4);
    float4 b = *reinterpret_cast<const float4*>(ad_ + (size_t)dn * 4);
    float x0 = __expf(lrelu02(a.x + b.x));
    float x1 = __expf(lrelu02(a.y + b.y));
    float x2 = __expf(lrelu02(a.z + b.z));
    float x3 = __expf(lrelu02(a.w + b.w));

    if (lane == 0) red_add_v4(ssum + (size_t)dn * 4, x0, x1, x2, x3);

    float xh = lane < 8 ? x0 : lane < 16 ? x1 : lane < 24 ? x2 : x3;
    float4 h = reinterpret_cast<const float4*>(Hs + (size_t)sn * HID)[lane];
    red_add_v4(acc + (size_t)dn * HID + lane * 4,
               h.x * xh, h.y * xh, h.z * xh, h.w * xh);
}

// Combine: normalize per relation, sum relations + biases, optional leaky(0.01).
__global__ void combine2_k(const float* __restrict__ acc1, const float* __restrict__ s1,
                           const float* __restrict__ acc2, const float* __restrict__ s2,
                           const float* __restrict__ bb, float* __restrict__ out,
                           int Nn, int act) {
    size_t idx = (size_t)blockIdx.x * blockDim.x + threadIdx.x;
    if (idx >= (size_t)Nn * HID) return;
    int i = (int)(idx & 127);
    size_t n = idx >> 7;
    int h = i >> 5;
    float v = acc1[idx] / (s1[n * 4 + h] + 1e-16f)
            + acc2[idx] / (s2[n * 4 + h] + 1e-16f)
            + bb[i] + bb[128 + i];
    if (act) v = v > 0.f ? v : 0.01f * v;
    out[idx] = v;
}

__global__ void combine1_k(const float* __restrict__ acc1, const float* __restrict__ s1,
                           const float* __restrict__ bb, float* __restrict__ out,
                           int Nn, int act) {
    size_t idx = (size_t)blockIdx.x * blockDim.x + threadIdx.x;
    if (idx >= (size_t)Nn * HID) return;
    int i = (int)(idx & 127);
    size_t n = idx >> 7;
    int h = i >> 5;
    float v = acc1[idx] / (s1[n * 4 + h] + 1e-16f) + bb[i];
    if (act) v = v > 0.f ? v : 0.01f * v;
    out[idx] = v;
}

// ---------------------------------------------------------------------------
// Host orchestration
// ---------------------------------------------------------------------------
extern "C" void kernel_launch(void* const* d_in, const int* in_sizes, int n_in,
                              void* d_out, int out_size) {
    const float* x_paper  = (const float*)d_in[0];
    const float* x_author = (const float*)d_in[1];
    const float* Wp   = (const float*)d_in[2];
    const float* bp   = (const float*)d_in[3];
    const float* Wa   = (const float*)d_in[4];
    const float* ba   = (const float*)d_in[5];
    const float* W0   = (const float*)d_in[6];
    const float* as0  = (const float*)d_in[7];
    const float* ad0  = (const float*)d_in[8];
    const float* b0   = (const float*)d_in[9];
    const float* W1   = (const float*)d_in[10];
    const float* as1  = (const float*)d_in[11];
    const float* ad1  = (const float*)d_in[12];
    const float* b1   = (const float*)d_in[13];
    const float* Wlin = (const float*)d_in[14];
    const float* blin = (const float*)d_in[15];
    const int* src_c  = (const int*)d_in[16];
    const int* dst_c  = (const int*)d_in[17];
    const int* src_w  = (const int*)d_in[18];
    const int* dst_w  = (const int*)d_in[19];
    const int* src_b  = (const int*)d_in[20];
    const int* dst_b  = (const int*)d_in[21];

    float* S = nullptr;
    cudaGetSymbolAddress((void**)&S, g_scratch);

    float* XPA  = S + O_XPA;
    float* XAA  = S + O_XAA;
    float* XPB  = S + O_XPB;
    float* XAB  = S + O_XAB;
    float* HP0  = S + O_HP0;
    float* HP1  = S + O_HP1;
    float* HP2  = S + O_HP2;
    float* HA1  = S + O_HA1;
    float* HA2  = S + O_HA2;
    float* ASC  = S + O_ASC;
    float* ADC  = S + O_ADC;
    float* ASW  = S + O_ASW;
    float* ADW  = S + O_ADW;
    float* ASB  = S + O_ASB;
    float* ADB  = S + O_ADB;
    float* SC   = S + O_SC;
    float* SW   = S + O_SW;
    float* SB   = S + O_SB;
    float* ACCC = S + O_ACCC;
    float* ACCW = S + O_ACCW;
    float* ACCB = S + O_ACCB;

    const dim3 gp((NPAPER + 127) / 128, 1);
    const dim3 ga((NAUTHOR + 127) / 128, 1);

    // ---- input projections ----
    sgemm_db<128, 128, 16, 8, 8><<<gp, 256>>>(x_paper,  Wp, bp, XPA, NPAPER,  128, 256);
    sgemm_db<128, 128, 16, 8, 8><<<ga, 256>>>(x_author, Wa, ba, XAA, NAUTHOR, 128, 128);

    for (int l = 0; l < 2; l++) {
        const float* W   = l ? W1  : W0;
        const float* as_ = l ? as1 : as0;
        const float* ad_ = l ? ad1 : ad0;
        const float* bb  = l ? b1  : b0;
        const float* xp  = l ? XPB : XPA;
        const float* xa  = l ? XAB : XAA;

        // feature transforms (layer 1: wb relation output is dead, skip it)
        sgemm_db<128, 128, 16, 8, 8><<<gp, 256>>>(xp, W + 0 * HID * HID, nullptr, HP0, NPAPER,  128, 128);
        sgemm_db<128, 128, 16, 8, 8><<<gp, 256>>>(xp, W + 1 * HID * HID, nullptr, HP1, NPAPER,  128, 128);
        sgemm_db<128, 128, 16, 8, 8><<<ga, 256>>>(xa, W + 1 * HID * HID, nullptr, HA1, NAUTHOR, 128, 128);
        if (!l) {
            sgemm_db<128, 128, 16, 8, 8><<<gp, 256>>>(xp, W + 2 * HID * HID, nullptr, HP2, NPAPER,  128, 128);
            sgemm_db<128, 128, 16, 8, 8><<<ga, 256>>>(xa, W + 2 * HID * HID, nullptr, HA2, NAUTHOR, 128, 128);
        }

        // attention logits
        const int abp = (NPAPER + 7) / 8, aba = (NAUTHOR + 7) / 8;
        attn_k<<<abp, 256>>>(HP0, as_ + 0,   ad_ + 0,   ASC, ADC, NPAPER);
        attn_k<<<aba, 256>>>(HA1, as_ + 128, nullptr,   ASW, nullptr, NAUTHOR);
        attn_k<<<abp, 256>>>(HP1, nullptr,   ad_ + 128, nullptr, ADW, NPAPER);
        if (!l) {
            attn_k<<<abp, 256>>>(HP2, as_ + 256, nullptr, ASB, nullptr, NPAPER);
            attn_k<<<aba, 256>>>(HA2, nullptr, ad_ + 256, nullptr, ADB, NAUTHOR);
        }

        // zero segment sums + accumulators (contiguous groups -> 2 memsets)
        if (!l) {
            cudaMemsetAsync(SC,   0, (2 * V_P + V_A) * sizeof(float));
            cudaMemsetAsync(ACCC, 0, (2 * SZ_P + SZ_A) * sizeof(float));
        } else {
            cudaMemsetAsync(SC,   0, 2 * V_P * sizeof(float));
            cudaMemsetAsync(ACCC, 0, 2 * SZ_P * sizeof(float));
        }

        // fused edge pass: exp-sum + weighted aggregation (one warp per edge)
        edge_agg_k<<<ECITES / 8, 256>>>(src_c, dst_c, ASC, ADC, HP0, SC, ACCC, ECITES);
        edge_agg_k<<<EWRITES / 8, 256>>>(src_w, dst_w, ASW, ADW, HA1, SW, ACCW, EWRITES);
        if (!l)
            edge_agg_k<<<EWB / 8, 256>>>(src_b, dst_b, ASB, ADB, HP2, SB, ACCB, EWB);

        // combine: normalize + sum relations + bias (+ leaky 0.01 between layers)
        combine2_k<<<(int)((SZ_P + 255) / 256), 256>>>(
            ACCC, SC, ACCW, SW, bb, l ? XPA : XPB, NPAPER, l == 0);
        if (!l)
            combine1_k<<<(int)((SZ_A + 255) / 256), 256>>>(
                ACCB, SB, bb + 256, XAB, NAUTHOR, 1);
    }

    // final classifier: [200000,128] @ [128,64] + blin
    sgemm_db<128, 64, 16, 8, 8><<<gp, 128>>>(XPA, Wlin, blin, (float*)d_out,
                                             NPAPER, 64, 128);
}

// round 4
// speedup vs baseline: 1.7952x; 1.7396x over previous
#include <cuda_runtime.h>
#include <cstdint>

// ---------------------------------------------------------------------------
// Problem constants
// ---------------------------------------------------------------------------
static constexpr int NPAPER  = 200000;
static constexpr int NAUTHOR = 100000;
static constexpr int HID     = 128;     // 4 heads x 32 channels
static constexpr int ECITES  = 1000000;
static constexpr int EWRITES = 500000;
static constexpr int EWB     = 500000;

static constexpr size_t SZ_P = (size_t)NPAPER * HID;
static constexpr size_t SZ_A = (size_t)NAUTHOR * HID;
static constexpr size_t V_P  = (size_t)NPAPER * 4;
static constexpr size_t V_A  = (size_t)NAUTHOR * 4;

static constexpr size_t O_XPA  = 0;
static constexpr size_t O_XAA  = O_XPA  + SZ_P;
static constexpr size_t O_XPB  = O_XAA  + SZ_A;
static constexpr size_t O_XAB  = O_XPB  + SZ_P;
static constexpr size_t O_HP0  = O_XAB  + SZ_A;
static constexpr size_t O_HP1  = O_HP0  + SZ_P;
static constexpr size_t O_HP2  = O_HP1  + SZ_P;
static constexpr size_t O_HA1  = O_HP2  + SZ_P;
static constexpr size_t O_HA2  = O_HA1  + SZ_A;
static constexpr size_t O_ASC  = O_HA2  + SZ_A;
static constexpr size_t O_ADC  = O_ASC  + V_P;
static constexpr size_t O_ASW  = O_ADC  + V_P;
static constexpr size_t O_ADW  = O_ASW  + V_A;
static constexpr size_t O_ASB  = O_ADW  + V_P;
static constexpr size_t O_ADB  = O_ASB  + V_P;
static constexpr size_t O_SC   = O_ADB  + V_A;
static constexpr size_t O_SW   = O_SC   + V_P;
static constexpr size_t O_SB   = O_SW   + V_P;
static constexpr size_t O_ACCC = O_SB   + V_A;
static constexpr size_t O_ACCW = O_ACCC + SZ_P;
static constexpr size_t O_ACCB = O_ACCW + SZ_P;
static constexpr size_t SCRATCH_FLOATS = O_ACCB + SZ_A;

__device__ float g_scratch[SCRATCH_FLOATS];

// ---------------------------------------------------------------------------
// tf32 helpers (plain sm_80+ PTX — no 'a'-suffix features)
// ---------------------------------------------------------------------------
__device__ __forceinline__ float f2tf32(float f) {
    uint32_t u;
    asm("cvt.rna.tf32.f32 %0, %1;" : "=r"(u) : "f"(f));
    return __uint_as_float(u);
}

__device__ __forceinline__ void mma_tf32(float* c, uint32_t a0, uint32_t a1,
                                         uint32_t a2, uint32_t a3,
                                         uint32_t b0, uint32_t b1) {
    asm volatile(
        "mma.sync.aligned.m16n8k8.row.col.f32.tf32.tf32.f32 "
        "{%0,%1,%2,%3}, {%4,%5,%6,%7}, {%8,%9}, {%0,%1,%2,%3};"
        : "+f"(c[0]), "+f"(c[1]), "+f"(c[2]), "+f"(c[3])
        : "r"(a0), "r"(a1), "r"(a2), "r"(a3), "r"(b0), "r"(b1));
}

// ---------------------------------------------------------------------------
// tf32 mma.sync GEMM: C[M,N] = A[M, KCH*128] @ W[KCH*128, N] (+ bias)
// Fused attention logits: out_s[row,h] = sum_c C_nobias[row, h*32+c]*att_s[h*32+c]
// CTA tile 128 x N, 256 threads, 8 warps in 4x2 grid (warp tile 32 x N/2).
// K staged in 64-wide chunks: As[128][68], Bs[64][N+8] (pads -> conflict-free).
// ---------------------------------------------------------------------------
template <int N, int KCH, bool LOGS, bool LOGD>
__global__ void __launch_bounds__(256, 2)
mma_gemm(const float* __restrict__ A, const float* __restrict__ W,
         const float* __restrict__ bias, float* __restrict__ C,
         const float* __restrict__ att_s, const float* __restrict__ att_d,
         float* __restrict__ out_s, float* __restrict__ out_d, int M) {
    constexpr int LDA_S = 68;          // As row stride (floats)
    constexpr int LDB_S = N + 8;       // Bs row stride (floats)
    constexpr int NF    = N / 16;      // n-frags per warp (warp cols = N/2)
    constexpr int KTOT  = KCH * 128;

    extern __shared__ float sm[];
    float* As = sm;                    // [128][LDA_S]
    float* Bs = sm + 128 * LDA_S;      // [64][LDB_S]

    const int tid  = threadIdx.x;
    const int wid  = tid >> 5;
    const int lane = tid & 31;
    const int wm   = wid >> 1;         // warp row 0..3
    const int wn   = wid & 1;          // warp col 0..1
    const int g    = lane >> 2;        // groupID
    const int tg   = lane & 3;         // thread-in-group
    const int row0 = blockIdx.x * 128;

    float acc[2][NF][4];
#pragma unroll
    for (int mf = 0; mf < 2; mf++)
#pragma unroll
        for (int nf = 0; nf < NF; nf++)
#pragma unroll
            for (int j = 0; j < 4; j++) acc[mf][nf][j] = 0.f;

    for (int kc = 0; kc < KCH * 2; kc++) {
        const int k0 = kc * 64;
        // ---- stage A chunk [128 x 64] with tf32 rounding ----
#pragma unroll
        for (int i = tid; i < 128 * 16; i += 256) {
            int r = i >> 4, c4 = i & 15;
            int gr = row0 + r;
            float4 v = make_float4(0.f, 0.f, 0.f, 0.f);
            if (gr < M)
                v = *reinterpret_cast<const float4*>(A + (size_t)gr * KTOT + k0 + c4 * 4);
            float4 t = make_float4(f2tf32(v.x), f2tf32(v.y), f2tf32(v.z), f2tf32(v.w));
            *reinterpret_cast<float4*>(As + r * LDA_S + c4 * 4) = t;
        }
        // ---- stage B chunk [64 x N] ----
#pragma unroll
        for (int i = tid; i < 64 * (N / 4); i += 256) {
            int k = i / (N / 4), n4 = i % (N / 4);
            float4 v = *reinterpret_cast<const float4*>(W + (size_t)(k0 + k) * N + n4 * 4);
            float4 t = make_float4(f2tf32(v.x), f2tf32(v.y), f2tf32(v.z), f2tf32(v.w));
            *reinterpret_cast<float4*>(Bs + k * LDB_S + n4 * 4) = t;
        }
        __syncthreads();

        // ---- 8 k-steps of m16n8k8 ----
#pragma unroll
        for (int s = 0; s < 8; s++) {
            const int kk = 8 * s;
            uint32_t b[NF][2];
#pragma unroll
            for (int nf = 0; nf < NF; nf++) {
                int col = wn * (N / 2) + nf * 8 + g;
                b[nf][0] = __float_as_uint(Bs[(kk + tg) * LDB_S + col]);
                b[nf][1] = __float_as_uint(Bs[(kk + tg + 4) * LDB_S + col]);
            }
#pragma unroll
            for (int mf = 0; mf < 2; mf++) {
                const int rb = wm * 32 + mf * 16;
                uint32_t a0 = __float_as_uint(As[(rb + g) * LDA_S + kk + tg]);
                uint32_t a1 = __float_as_uint(As[(rb + g + 8) * LDA_S + kk + tg]);
                uint32_t a2 = __float_as_uint(As[(rb + g) * LDA_S + kk + tg + 4]);
                uint32_t a3 = __float_as_uint(As[(rb + g + 8) * LDA_S + kk + tg + 4]);
#pragma unroll
                for (int nf = 0; nf < NF; nf++)
                    mma_tf32(acc[mf][nf], a0, a1, a2, a3, b[nf][0], b[nf][1]);
            }
        }
        __syncthreads();
    }

    // ---- epilogue: store C (+bias), fused logits ----
#pragma unroll
    for (int mf = 0; mf < 2; mf++) {
        const int r0 = row0 + wm * 32 + mf * 16 + g;
        const int r1 = r0 + 8;
        float sl[2][2] = {{0.f, 0.f}, {0.f, 0.f}};
        float dl[2][2] = {{0.f, 0.f}, {0.f, 0.f}};
#pragma unroll
        for (int nf = 0; nf < NF; nf++) {
            const int col = wn * (N / 2) + nf * 8 + tg * 2;
            float c0 = acc[mf][nf][0], c1 = acc[mf][nf][1];
            float c2 = acc[mf][nf][2], c3 = acc[mf][nf][3];
            if (LOGS) {
                int h = nf >> 2;
                float w0 = att_s[col], w1 = att_s[col + 1];
                sl[h][0] += c0 * w0 + c1 * w1;
                sl[h][1] += c2 * w0 + c3 * w1;
            }
            if (LOGD) {
                int h = nf >> 2;
                float w0 = att_d[col], w1 = att_d[col + 1];
                dl[h][0] += c0 * w0 + c1 * w1;
                dl[h][1] += c2 * w0 + c3 * w1;
            }
            float b0v = 0.f, b1v = 0.f;
            if (bias) { b0v = bias[col]; b1v = bias[col + 1]; }
            if (r0 < M) {
                float2 o = make_float2(c0 + b0v, c1 + b1v);
                *reinterpret_cast<float2*>(C + (size_t)r0 * N + col) = o;
            }
            if (r1 < M) {
                float2 o = make_float2(c2 + b0v, c3 + b1v);
                *reinterpret_cast<float2*>(C + (size_t)r1 * N + col) = o;
            }
        }
        if (LOGS || LOGD) {
#pragma unroll
            for (int h = 0; h < 2; h++)
#pragma unroll
                for (int rr = 0; rr < 2; rr++) {
                    if (LOGS) {
                        sl[h][rr] += __shfl_xor_sync(0xffffffffu, sl[h][rr], 1);
                        sl[h][rr] += __shfl_xor_sync(0xffffffffu, sl[h][rr], 2);
                    }
                    if (LOGD) {
                        dl[h][rr] += __shfl_xor_sync(0xffffffffu, dl[h][rr], 1);
                        dl[h][rr] += __shfl_xor_sync(0xffffffffu, dl[h][rr], 2);
                    }
                }
            if (tg == 0) {
#pragma unroll
                for (int h = 0; h < 2; h++)
#pragma unroll
                    for (int rr = 0; rr < 2; rr++) {
                        int row = rr ? r1 : r0;
                        if (row < M) {
                            int hg = wn * 2 + h;
                            if (LOGS) out_s[(size_t)row * 4 + hg] = sl[h][rr];
                            if (LOGD) out_d[(size_t)row * 4 + hg] = dl[h][rr];
                        }
                    }
            }
        }
    }
}

// ---------------------------------------------------------------------------
// Edge phase (unchanged from R2)
// ---------------------------------------------------------------------------
__device__ __forceinline__ float lrelu02(float v) { return v > 0.f ? v : 0.2f * v; }

__device__ __forceinline__ void red_add_v4(float* p, float a, float b, float c, float d) {
    asm volatile("red.global.add.v4.f32 [%0], {%1, %2, %3, %4};"
                 :: "l"(p), "f"(a), "f"(b), "f"(c), "f"(d) : "memory");
}

__global__ void edge_agg_k(const int* __restrict__ src, const int* __restrict__ dst,
                           const float* __restrict__ as_, const float* __restrict__ ad_,
                           const float* __restrict__ Hs,
                           float* __restrict__ ssum, float* __restrict__ acc, int E) {
    int e    = (blockIdx.x * blockDim.x + threadIdx.x) >> 5;
    int lane = threadIdx.x & 31;
    if (e >= E) return;
    int sn = src[e], dn = dst[e];
    float4 a = *reinterpret_cast<const float4*>(as_ + (size_t)sn * 4);
    float4 b = *reinterpret_cast<const float4*>(ad_ + (size_t)dn * 4);
    float x0 = __expf(lrelu02(a.x + b.x));
    float x1 = __expf(lrelu02(a.y + b.y));
    float x2 = __expf(lrelu02(a.z + b.z));
    float x3 = __expf(lrelu02(a.w + b.w));

    if (lane == 0) red_add_v4(ssum + (size_t)dn * 4, x0, x1, x2, x3);

    float xh = lane < 8 ? x0 : lane < 16 ? x1 : lane < 24 ? x2 : x3;
    float4 h = reinterpret_cast<const float4*>(Hs + (size_t)sn * HID)[lane];
    red_add_v4(acc + (size_t)dn * HID + lane * 4,
               h.x * xh, h.y * xh, h.z * xh, h.w * xh);
}

__global__ void combine2_k(const float* __restrict__ acc1, const float* __restrict__ s1,
                           const float* __restrict__ acc2, const float* __restrict__ s2,
                           const float* __restrict__ bb, float* __restrict__ out,
                           int Nn, int act) {
    size_t idx = (size_t)blockIdx.x * blockDim.x + threadIdx.x;
    if (idx >= (size_t)Nn * HID) return;
    int i = (int)(idx & 127);
    size_t n = idx >> 7;
    int h = i >> 5;
    float v = acc1[idx] / (s1[n * 4 + h] + 1e-16f)
            + acc2[idx] / (s2[n * 4 + h] + 1e-16f)
            + bb[i] + bb[128 + i];
    if (act) v = v > 0.f ? v : 0.01f * v;
    out[idx] = v;
}

__global__ void combine1_k(const float* __restrict__ acc1, const float* __restrict__ s1,
                           const float* __restrict__ bb, float* __restrict__ out,
                           int Nn, int act) {
    size_t idx = (size_t)blockIdx.x * blockDim.x + threadIdx.x;
    if (idx >= (size_t)Nn * HID) return;
    int i = (int)(idx & 127);
    size_t n = idx >> 7;
    int h = i >> 5;
    float v = acc1[idx] / (s1[n * 4 + h] + 1e-16f) + bb[i];
    if (act) v = v > 0.f ? v : 0.01f * v;
    out[idx] = v;
}

// ---------------------------------------------------------------------------
// Host orchestration
// ---------------------------------------------------------------------------
static inline int gemm_smem(int N) {
    return (128 * 68 + 64 * (N + 8)) * 4;
}

extern "C" void kernel_launch(void* const* d_in, const int* in_sizes, int n_in,
                              void* d_out, int out_size) {
    const float* x_paper  = (const float*)d_in[0];
    const float* x_author = (const float*)d_in[1];
    const float* Wp   = (const float*)d_in[2];
    const float* bp   = (const float*)d_in[3];
    const float* Wa   = (const float*)d_in[4];
    const float* ba   = (const float*)d_in[5];
    const float* W0   = (const float*)d_in[6];
    const float* as0  = (const float*)d_in[7];
    const float* ad0  = (const float*)d_in[8];
    const float* b0   = (const float*)d_in[9];
    const float* W1   = (const float*)d_in[10];
    const float* as1  = (const float*)d_in[11];
    const float* ad1  = (const float*)d_in[12];
    const float* b1   = (const float*)d_in[13];
    const float* Wlin = (const float*)d_in[14];
    const float* blin = (const float*)d_in[15];
    const int* src_c  = (const int*)d_in[16];
    const int* dst_c  = (const int*)d_in[17];
    const int* src_w  = (const int*)d_in[18];
    const int* dst_w  = (const int*)d_in[19];
    const int* src_b  = (const int*)d_in[20];
    const int* dst_b  = (const int*)d_in[21];

    float* S = nullptr;
    cudaGetSymbolAddress((void**)&S, g_scratch);

    float* XPA  = S + O_XPA;
    float* XAA  = S + O_XAA;
    float* XPB  = S + O_XPB;
    float* XAB  = S + O_XAB;
    float* HP0  = S + O_HP0;
    float* HP1  = S + O_HP1;
    float* HP2  = S + O_HP2;
    float* HA1  = S + O_HA1;
    float* HA2  = S + O_HA2;
    float* ASC  = S + O_ASC;
    float* ADC  = S + O_ADC;
    float* ASW  = S + O_ASW;
    float* ADW  = S + O_ADW;
    float* ASB  = S + O_ASB;
    float* ADB  = S + O_ADB;
    float* SC   = S + O_SC;
    float* SW   = S + O_SW;
    float* SB   = S + O_SB;
    float* ACCC = S + O_ACCC;
    float* ACCW = S + O_ACCW;
    float* ACCB = S + O_ACCB;

    const int sm128 = gemm_smem(128);
    const int sm64  = gemm_smem(64);
    cudaFuncSetAttribute(mma_gemm<128, 2, false, false>, cudaFuncAttributeMaxDynamicSharedMemorySize, sm128);
    cudaFuncSetAttribute(mma_gemm<128, 1, false, false>, cudaFuncAttributeMaxDynamicSharedMemorySize, sm128);
    cudaFuncSetAttribute(mma_gemm<128, 1, true,  true >, cudaFuncAttributeMaxDynamicSharedMemorySize, sm128);
    cudaFuncSetAttribute(mma_gemm<128, 1, true,  false>, cudaFuncAttributeMaxDynamicSharedMemorySize, sm128);
    cudaFuncSetAttribute(mma_gemm<128, 1, false, true >, cudaFuncAttributeMaxDynamicSharedMemorySize, sm128);
    cudaFuncSetAttribute(mma_gemm<64,  1, false, false>, cudaFuncAttributeMaxDynamicSharedMemorySize, sm64);

    const int TP = (NPAPER + 127) / 128;   // 1563
    const int TA = (NAUTHOR + 127) / 128;  // 782

    // ---- input projections ----
    mma_gemm<128, 2, false, false><<<TP, 256, sm128>>>(
        x_paper, Wp, bp, XPA, nullptr, nullptr, nullptr, nullptr, NPAPER);
    mma_gemm<128, 1, false, false><<<TA, 256, sm128>>>(
        x_author, Wa, ba, XAA, nullptr, nullptr, nullptr, nullptr, NAUTHOR);

    for (int l = 0; l < 2; l++) {
        const float* W   = l ? W1  : W0;
        const float* as_ = l ? as1 : as0;
        const float* ad_ = l ? ad1 : ad0;
        const float* bb  = l ? b1  : b0;
        const float* xp  = l ? XPB : XPA;
        const float* xa  = l ? XAB : XAA;

        // feature transforms + fused attention logits
        // (layer 1: wb relation output is dead -> skipped)
        mma_gemm<128, 1, true, true><<<TP, 256, sm128>>>(
            xp, W + 0 * HID * HID, nullptr, HP0, as_ + 0, ad_ + 0, ASC, ADC, NPAPER);
        mma_gemm<128, 1, false, true><<<TP, 256, sm128>>>(
            xp, W + 1 * HID * HID, nullptr, HP1, nullptr, ad_ + 128, nullptr, ADW, NPAPER);
        mma_gemm<128, 1, true, false><<<TA, 256, sm128>>>(
            xa, W + 1 * HID * HID, nullptr, HA1, as_ + 128, nullptr, ASW, nullptr, NAUTHOR);
        if (!l) {
            mma_gemm<128, 1, true, false><<<TP, 256, sm128>>>(
                xp, W + 2 * HID * HID, nullptr, HP2, as_ + 256, nullptr, ASB, nullptr, NPAPER);
            mma_gemm<128, 1, false, true><<<TA, 256, sm128>>>(
                xa, W + 2 * HID * HID, nullptr, HA2, nullptr, ad_ + 256, nullptr, ADB, NAUTHOR);
        }

        // zero segment sums + accumulators (contiguous groups)
        if (!l) {
            cudaMemsetAsync(SC,   0, (2 * V_P + V_A) * sizeof(float));
            cudaMemsetAsync(ACCC, 0, (2 * SZ_P + SZ_A) * sizeof(float));
        } else {
            cudaMemsetAsync(SC,   0, 2 * V_P * sizeof(float));
            cudaMemsetAsync(ACCC, 0, 2 * SZ_P * sizeof(float));
        }

        // fused edge pass: exp-sum + weighted aggregation (one warp per edge)
        edge_agg_k<<<ECITES / 8, 256>>>(src_c, dst_c, ASC, ADC, HP0, SC, ACCC, ECITES);
        edge_agg_k<<<EWRITES / 8, 256>>>(src_w, dst_w, ASW, ADW, HA1, SW, ACCW, EWRITES);
        if (!l)
            edge_agg_k<<<EWB / 8, 256>>>(src_b, dst_b, ASB, ADB, HP2, SB, ACCB, EWB);

        // combine: normalize + sum relations + bias (+ leaky 0.01 between layers)
        combine2_k<<<(int)((SZ_P + 255) / 256), 256>>>(
            ACCC, SC, ACCW, SW, bb, l ? XPA : XPB, NPAPER, l == 0);
        if (!l)
            combine1_k<<<(int)((SZ_A + 255) / 256), 256>>>(
                ACCB, SB, bb + 256, XAB, NAUTHOR, 1);
    }

    // final classifier: [200000,128] @ [128,64] + blin
    mma_gemm<64, 1, false, false><<<TP, 256, sm64>>>(
        XPA, Wlin, blin, (float*)d_out, nullptr, nullptr, nullptr, nullptr, NPAPER);
}

// round 5
// speedup vs baseline: 2.8725x; 1.6001x over previous
#include <cuda_runtime.h>
#include <cstdint>

// ---------------------------------------------------------------------------
// Problem constants
// ---------------------------------------------------------------------------
static constexpr int NPAPER  = 200000;
static constexpr int NAUTHOR = 100000;
static constexpr int HID     = 128;     // 4 heads x 32 channels
static constexpr int ECITES  = 1000000;
static constexpr int EWRITES = 500000;
static constexpr int EWB     = 500000;

static constexpr size_t SZ_P = (size_t)NPAPER * HID;
static constexpr size_t SZ_A = (size_t)NAUTHOR * HID;
static constexpr size_t V_P  = (size_t)NPAPER * 4;
static constexpr size_t V_A  = (size_t)NAUTHOR * 4;

// float scratch
static constexpr size_t O_XPA  = 0;
static constexpr size_t O_XAA  = O_XPA  + SZ_P;
static constexpr size_t O_XPB  = O_XAA  + SZ_A;
static constexpr size_t O_XAB  = O_XPB  + SZ_P;
static constexpr size_t O_HP0  = O_XAB  + SZ_A;
static constexpr size_t O_HP1  = O_HP0  + SZ_P;
static constexpr size_t O_HP2  = O_HP1  + SZ_P;
static constexpr size_t O_HA1  = O_HP2  + SZ_P;
static constexpr size_t O_HA2  = O_HA1  + SZ_A;
static constexpr size_t O_ASC  = O_HA2  + SZ_A;
static constexpr size_t O_ADC  = O_ASC  + V_P;
static constexpr size_t O_ASW  = O_ADC  + V_P;
static constexpr size_t O_ADW  = O_ASW  + V_A;
static constexpr size_t O_ASB  = O_ADW  + V_P;
static constexpr size_t O_ADB  = O_ASB  + V_P;
static constexpr size_t SCRATCH_FLOATS = O_ADB + V_A;

__device__ float g_scratch[SCRATCH_FLOATS];

// int scratch (CSR)
static constexpr size_t I_C_OFF = 0;                       // cites: dst=paper
static constexpr size_t I_C_DEG = I_C_OFF + NPAPER;
static constexpr size_t I_C_CUR = I_C_DEG + NPAPER;
static constexpr size_t I_C_SRC = I_C_CUR + NPAPER;
static constexpr size_t I_W_OFF = I_C_SRC + ECITES;        // writes: dst=paper
static constexpr size_t I_W_DEG = I_W_OFF + NPAPER;
static constexpr size_t I_W_CUR = I_W_DEG + NPAPER;
static constexpr size_t I_W_SRC = I_W_CUR + NPAPER;
static constexpr size_t I_B_OFF = I_W_SRC + EWRITES;       // wb: dst=author
static constexpr size_t I_B_DEG = I_B_OFF + NAUTHOR;
static constexpr size_t I_B_CUR = I_B_DEG + NAUTHOR;
static constexpr size_t I_B_SRC = I_B_CUR + NAUTHOR;
static constexpr size_t I_BS    = I_B_SRC + EWB;           // block sums (3 x 256)
static constexpr size_t SCRATCH_INTS = I_BS + 3 * 256;

__device__ int g_iscratch[SCRATCH_INTS];

// ---------------------------------------------------------------------------
// tf32 helpers (plain sm_80+ PTX — no 'a'-suffix features)
// ---------------------------------------------------------------------------
__device__ __forceinline__ float f2tf32(float f) {
    uint32_t u;
    asm("cvt.rna.tf32.f32 %0, %1;" : "=r"(u) : "f"(f));
    return __uint_as_float(u);
}

__device__ __forceinline__ void mma_tf32(float* c, uint32_t a0, uint32_t a1,
                                         uint32_t a2, uint32_t a3,
                                         uint32_t b0, uint32_t b1) {
    asm volatile(
        "mma.sync.aligned.m16n8k8.row.col.f32.tf32.tf32.f32 "
        "{%0,%1,%2,%3}, {%4,%5,%6,%7}, {%8,%9}, {%0,%1,%2,%3};"
        : "+f"(c[0]), "+f"(c[1]), "+f"(c[2]), "+f"(c[3])
        : "r"(a0), "r"(a1), "r"(a2), "r"(a3), "r"(b0), "r"(b1));
}

// ---------------------------------------------------------------------------
// tf32 mma.sync GEMM (unchanged from R4): C[M,N] = A[M,KCH*128] @ W (+bias),
// fused per-row attention logits out_s/out_d.
// ---------------------------------------------------------------------------
template <int N, int KCH, bool LOGS, bool LOGD>
__global__ void __launch_bounds__(256, 2)
mma_gemm(const float* __restrict__ A, const float* __restrict__ W,
         const float* __restrict__ bias, float* __restrict__ C,
         const float* __restrict__ att_s, const float* __restrict__ att_d,
         float* __restrict__ out_s, float* __restrict__ out_d, int M) {
    constexpr int LDA_S = 68;
    constexpr int LDB_S = N + 8;
    constexpr int NF    = N / 16;
    constexpr int KTOT  = KCH * 128;

    extern __shared__ float sm[];
    float* As = sm;
    float* Bs = sm + 128 * LDA_S;

    const int tid  = threadIdx.x;
    const int wid  = tid >> 5;
    const int lane = tid & 31;
    const int wm   = wid >> 1;
    const int wn   = wid & 1;
    const int g    = lane >> 2;
    const int tg   = lane & 3;
    const int row0 = blockIdx.x * 128;

    float acc[2][NF][4];
#pragma unroll
    for (int mf = 0; mf < 2; mf++)
#pragma unroll
        for (int nf = 0; nf < NF; nf++)
#pragma unroll
            for (int j = 0; j < 4; j++) acc[mf][nf][j] = 0.f;

    for (int kc = 0; kc < KCH * 2; kc++) {
        const int k0 = kc * 64;
#pragma unroll
        for (int i = tid; i < 128 * 16; i += 256) {
            int r = i >> 4, c4 = i & 15;
            int gr = row0 + r;
            float4 v = make_float4(0.f, 0.f, 0.f, 0.f);
            if (gr < M)
                v = *reinterpret_cast<const float4*>(A + (size_t)gr * KTOT + k0 + c4 * 4);
            float4 t = make_float4(f2tf32(v.x), f2tf32(v.y), f2tf32(v.z), f2tf32(v.w));
            *reinterpret_cast<float4*>(As + r * LDA_S + c4 * 4) = t;
        }
#pragma unroll
        for (int i = tid; i < 64 * (N / 4); i += 256) {
            int k = i / (N / 4), n4 = i % (N / 4);
            float4 v = *reinterpret_cast<const float4*>(W + (size_t)(k0 + k) * N + n4 * 4);
            float4 t = make_float4(f2tf32(v.x), f2tf32(v.y), f2tf32(v.z), f2tf32(v.w));
            *reinterpret_cast<float4*>(Bs + k * LDB_S + n4 * 4) = t;
        }
        __syncthreads();

#pragma unroll
        for (int s = 0; s < 8; s++) {
            const int kk = 8 * s;
            uint32_t b[NF][2];
#pragma unroll
            for (int nf = 0; nf < NF; nf++) {
                int col = wn * (N / 2) + nf * 8 + g;
                b[nf][0] = __float_as_uint(Bs[(kk + tg) * LDB_S + col]);
                b[nf][1] = __float_as_uint(Bs[(kk + tg + 4) * LDB_S + col]);
            }
#pragma unroll
            for (int mf = 0; mf < 2; mf++) {
                const int rb = wm * 32 + mf * 16;
                uint32_t a0 = __float_as_uint(As[(rb + g) * LDA_S + kk + tg]);
                uint32_t a1 = __float_as_uint(As[(rb + g + 8) * LDA_S + kk + tg]);
                uint32_t a2 = __float_as_uint(As[(rb + g) * LDA_S + kk + tg + 4]);
                uint32_t a3 = __float_as_uint(As[(rb + g + 8) * LDA_S + kk + tg + 4]);
#pragma unroll
                for (int nf = 0; nf < NF; nf++)
                    mma_tf32(acc[mf][nf], a0, a1, a2, a3, b[nf][0], b[nf][1]);
            }
        }
        __syncthreads();
    }

#pragma unroll
    for (int mf = 0; mf < 2; mf++) {
        const int r0 = row0 + wm * 32 + mf * 16 + g;
        const int r1 = r0 + 8;
        float sl[2][2] = {{0.f, 0.f}, {0.f, 0.f}};
        float dl[2][2] = {{0.f, 0.f}, {0.f, 0.f}};
#pragma unroll
        for (int nf = 0; nf < NF; nf++) {
            const int col = wn * (N / 2) + nf * 8 + tg * 2;
            float c0 = acc[mf][nf][0], c1 = acc[mf][nf][1];
            float c2 = acc[mf][nf][2], c3 = acc[mf][nf][3];
            if (LOGS) {
                int h = nf >> 2;
                float w0 = att_s[col], w1 = att_s[col + 1];
                sl[h][0] += c0 * w0 + c1 * w1;
                sl[h][1] += c2 * w0 + c3 * w1;
            }
            if (LOGD) {
                int h = nf >> 2;
                float w0 = att_d[col], w1 = att_d[col + 1];
                dl[h][0] += c0 * w0 + c1 * w1;
                dl[h][1] += c2 * w0 + c3 * w1;
            }
            float b0v = 0.f, b1v = 0.f;
            if (bias) { b0v = bias[col]; b1v = bias[col + 1]; }
            if (r0 < M) {
                float2 o = make_float2(c0 + b0v, c1 + b1v);
                *reinterpret_cast<float2*>(C + (size_t)r0 * N + col) = o;
            }
            if (r1 < M) {
                float2 o = make_float2(c2 + b0v, c3 + b1v);
                *reinterpret_cast<float2*>(C + (size_t)r1 * N + col) = o;
            }
        }
        if (LOGS || LOGD) {
#pragma unroll
            for (int h = 0; h < 2; h++)
#pragma unroll
                for (int rr = 0; rr < 2; rr++) {
                    if (LOGS) {
                        sl[h][rr] += __shfl_xor_sync(0xffffffffu, sl[h][rr], 1);
                        sl[h][rr] += __shfl_xor_sync(0xffffffffu, sl[h][rr], 2);
                    }
                    if (LOGD) {
                        dl[h][rr] += __shfl_xor_sync(0xffffffffu, dl[h][rr], 1);
                        dl[h][rr] += __shfl_xor_sync(0xffffffffu, dl[h][rr], 2);
                    }
                }
            if (tg == 0) {
#pragma unroll
                for (int h = 0; h < 2; h++)
#pragma unroll
                    for (int rr = 0; rr < 2; rr++) {
                        int row = rr ? r1 : r0;
                        if (row < M) {
                            int hg = wn * 2 + h;
                            if (LOGS) out_s[(size_t)row * 4 + hg] = sl[h][rr];
                            if (LOGD) out_d[(size_t)row * 4 + hg] = dl[h][rr];
                        }
                    }
            }
        }
    }
}

// ---------------------------------------------------------------------------
// CSR build: hist -> 3-phase exclusive scan -> scatter (src ids, dst-major)
// ---------------------------------------------------------------------------
__global__ void hist_k(const int* __restrict__ dst, int* __restrict__ deg, int E) {
    int e = blockIdx.x * blockDim.x + threadIdx.x;
    if (e < E) atomicAdd(&deg[dst[e]], 1);
}

// per-block (2048-elem chunk) exclusive scan; bsum[b] = chunk total
__global__ void scanA_k(const int* __restrict__ deg, int* __restrict__ off,
                        int* __restrict__ bsum, int n) {
    __shared__ int sh[256];
    const int t = threadIdx.x, b = blockIdx.x;
    const int base = b * 2048 + t * 8;
    int v[8], s = 0;
#pragma unroll
    for (int i = 0; i < 8; i++) {
        int idx = base + i;
        v[i] = (idx < n) ? deg[idx] : 0;
        s += v[i];
    }
    sh[t] = s;
    __syncthreads();
    for (int o = 1; o < 256; o <<= 1) {
        int y = (t >= o) ? sh[t - o] : 0;
        __syncthreads();
        sh[t] += y;
        __syncthreads();
    }
    int run = sh[t] - s;  // exclusive prefix of this thread's chunk
    if (t == 255) bsum[b] = sh[255];
#pragma unroll
    for (int i = 0; i < 8; i++) {
        int idx = base + i;
        if (idx < n) off[idx] = run;
        run += v[i];
    }
}

// single-block exclusive scan of block sums (nb <= 256)
__global__ void scanB_k(int* __restrict__ bsum, int nb) {
    __shared__ int sh[256];
    int t = threadIdx.x;
    int v = (t < nb) ? bsum[t] : 0;
    sh[t] = v;
    __syncthreads();
    for (int o = 1; o < 256; o <<= 1) {
        int y = (t >= o) ? sh[t - o] : 0;
        __syncthreads();
        sh[t] += y;
        __syncthreads();
    }
    if (t < nb) bsum[t] = sh[t] - v;
}

__global__ void scanC_k(int* __restrict__ off, int* __restrict__ cur,
                        const int* __restrict__ bsum, int n) {
    int i = blockIdx.x * blockDim.x + threadIdx.x;
    if (i >= n) return;
    int v = off[i] + bsum[i >> 11];
    off[i] = v;
    cur[i] = v;
}

__global__ void scatter_k(const int* __restrict__ src, const int* __restrict__ dst,
                          int* __restrict__ cur, int* __restrict__ csrc, int E) {
    int e = blockIdx.x * blockDim.x + threadIdx.x;
    if (e >= E) return;
    int pos = atomicAdd(&cur[dst[e]], 1);
    csrc[pos] = src[e];
}

// ---------------------------------------------------------------------------
// Dst-major GAT aggregation. One warp per dst node; lane owns 4 channels
// (float4), head = lane>>3. Fuses: softmax-normalize, 2-relation sum,
// bias, optional leaky(0.01). No atomics.
// ---------------------------------------------------------------------------
__device__ __forceinline__ float lrelu02(float v) { return v > 0.f ? v : 0.2f * v; }

__global__ void agg_paper_k(
    const int* __restrict__ c_src, const int* __restrict__ c_off, const int* __restrict__ c_deg,
    const int* __restrict__ w_src, const int* __restrict__ w_off, const int* __restrict__ w_deg,
    const float* __restrict__ asc, const float* __restrict__ adc, const float* __restrict__ h1,
    const float* __restrict__ asw, const float* __restrict__ adw, const float* __restrict__ h2,
    const float* __restrict__ bb, float* __restrict__ out, int act) {
    const int n    = (blockIdx.x * blockDim.x + threadIdx.x) >> 5;
    const int lane = threadIdx.x & 31;
    if (n >= NPAPER) return;
    const int h = lane >> 3;

    float4 a1 = make_float4(0.f, 0.f, 0.f, 0.f);
    float  s1 = 0.f;
    {
        float ad = adc[(size_t)n * 4 + h];
        int st = c_off[n], d = c_deg[n];
        for (int j = 0; j < d; j++) {
            int sidx = c_src[st + j];
            float x = __expf(lrelu02(asc[(size_t)sidx * 4 + h] + ad));
            float4 hv = reinterpret_cast<const float4*>(h1 + (size_t)sidx * HID)[lane];
            s1 += x;
            a1.x += x * hv.x; a1.y += x * hv.y; a1.z += x * hv.z; a1.w += x * hv.w;
        }
    }
    float4 a2 = make_float4(0.f, 0.f, 0.f, 0.f);
    float  s2 = 0.f;
    {
        float ad = adw[(size_t)n * 4 + h];
        int st = w_off[n], d = w_deg[n];
        for (int j = 0; j < d; j++) {
            int sidx = w_src[st + j];
            float x = __expf(lrelu02(asw[(size_t)sidx * 4 + h] + ad));
            float4 hv = reinterpret_cast<const float4*>(h2 + (size_t)sidx * HID)[lane];
            s2 += x;
            a2.x += x * hv.x; a2.y += x * hv.y; a2.z += x * hv.z; a2.w += x * hv.w;
        }
    }
    float i1 = 1.f / (s1 + 1e-16f);
    float i2 = 1.f / (s2 + 1e-16f);
    float4 bv1 = reinterpret_cast<const float4*>(bb)[lane];
    float4 bv2 = reinterpret_cast<const float4*>(bb + 128)[lane];
    float4 o;
    o.x = a1.x * i1 + a2.x * i2 + bv1.x + bv2.x;
    o.y = a1.y * i1 + a2.y * i2 + bv1.y + bv2.y;
    o.z = a1.z * i1 + a2.z * i2 + bv1.z + bv2.z;
    o.w = a1.w * i1 + a2.w * i2 + bv1.w + bv2.w;
    if (act) {
        o.x = o.x > 0.f ? o.x : 0.01f * o.x;
        o.y = o.y > 0.f ? o.y : 0.01f * o.y;
        o.z = o.z > 0.f ? o.z : 0.01f * o.z;
        o.w = o.w > 0.f ? o.w : 0.01f * o.w;
    }
    reinterpret_cast<float4*>(out + (size_t)n * HID)[lane] = o;
}

__global__ void agg_author_k(
    const int* __restrict__ b_src, const int* __restrict__ b_off, const int* __restrict__ b_deg,
    const float* __restrict__ asb, const float* __restrict__ adb, const float* __restrict__ h1,
    const float* __restrict__ bb, float* __restrict__ out) {
    const int n    = (blockIdx.x * blockDim.x + threadIdx.x) >> 5;
    const int lane = threadIdx.x & 31;
    if (n >= NAUTHOR) return;
    const int h = lane >> 3;

    float4 a1 = make_float4(0.f, 0.f, 0.f, 0.f);
    float  s1 = 0.f;
    float ad = adb[(size_t)n * 4 + h];
    int st = b_off[n], d = b_deg[n];
    for (int j = 0; j < d; j++) {
        int sidx = b_src[st + j];
        float x = __expf(lrelu02(asb[(size_t)sidx * 4 + h] + ad));
        float4 hv = reinterpret_cast<const float4*>(h1 + (size_t)sidx * HID)[lane];
        s1 += x;
        a1.x += x * hv.x; a1.y += x * hv.y; a1.z += x * hv.z; a1.w += x * hv.w;
    }
    float i1 = 1.f / (s1 + 1e-16f);
    float4 bv = reinterpret_cast<const float4*>(bb)[lane];
    float4 o;
    o.x = a1.x * i1 + bv.x;
    o.y = a1.y * i1 + bv.y;
    o.z = a1.z * i1 + bv.z;
    o.w = a1.w * i1 + bv.w;
    o.x = o.x > 0.f ? o.x : 0.01f * o.x;
    o.y = o.y > 0.f ? o.y : 0.01f * o.y;
    o.z = o.z > 0.f ? o.z : 0.01f * o.z;
    o.w = o.w > 0.f ? o.w : 0.01f * o.w;
    reinterpret_cast<float4*>(out + (size_t)n * HID)[lane] = o;
}

// ---------------------------------------------------------------------------
// Host orchestration
// ---------------------------------------------------------------------------
static inline int gemm_smem(int N) { return (128 * 68 + 64 * (N + 8)) * 4; }

static void build_csr(const int* src, const int* dst, int E, int Ndst,
                      int* off, int* deg, int* cur, int* csrc, int* bsum) {
    cudaMemsetAsync(deg, 0, (size_t)Ndst * sizeof(int));
    hist_k<<<(E + 255) / 256, 256>>>(dst, deg, E);
    int nb = (Ndst + 2047) / 2048;
    scanA_k<<<nb, 256>>>(deg, off, bsum, Ndst);
    scanB_k<<<1, 256>>>(bsum, nb);
    scanC_k<<<(Ndst + 255) / 256, 256>>>(off, cur, bsum, Ndst);
    scatter_k<<<(E + 255) / 256, 256>>>(src, dst, cur, csrc, E);
}

extern "C" void kernel_launch(void* const* d_in, const int* in_sizes, int n_in,
                              void* d_out, int out_size) {
    const float* x_paper  = (const float*)d_in[0];
    const float* x_author = (const float*)d_in[1];
    const float* Wp   = (const float*)d_in[2];
    const float* bp   = (const float*)d_in[3];
    const float* Wa   = (const float*)d_in[4];
    const float* ba   = (const float*)d_in[5];
    const float* W0   = (const float*)d_in[6];
    const float* as0  = (const float*)d_in[7];
    const float* ad0  = (const float*)d_in[8];
    const float* b0   = (const float*)d_in[9];
    const float* W1   = (const float*)d_in[10];
    const float* as1  = (const float*)d_in[11];
    const float* ad1  = (const float*)d_in[12];
    const float* b1   = (const float*)d_in[13];
    const float* Wlin = (const float*)d_in[14];
    const float* blin = (const float*)d_in[15];
    const int* src_c  = (const int*)d_in[16];
    const int* dst_c  = (const int*)d_in[17];
    const int* src_w  = (const int*)d_in[18];
    const int* dst_w  = (const int*)d_in[19];
    const int* src_b  = (const int*)d_in[20];
    const int* dst_b  = (const int*)d_in[21];

    float* S = nullptr;
    cudaGetSymbolAddress((void**)&S, g_scratch);
    int* I = nullptr;
    cudaGetSymbolAddress((void**)&I, g_iscratch);

    float* XPA  = S + O_XPA;
    float* XAA  = S + O_XAA;
    float* XPB  = S + O_XPB;
    float* XAB  = S + O_XAB;
    float* HP0  = S + O_HP0;
    float* HP1  = S + O_HP1;
    float* HP2  = S + O_HP2;
    float* HA1  = S + O_HA1;
    float* HA2  = S + O_HA2;
    float* ASC  = S + O_ASC;
    float* ADC  = S + O_ADC;
    float* ASW  = S + O_ASW;
    float* ADW  = S + O_ADW;
    float* ASB  = S + O_ASB;
    float* ADB  = S + O_ADB;

    int* C_OFF = I + I_C_OFF; int* C_DEG = I + I_C_DEG;
    int* C_CUR = I + I_C_CUR; int* C_SRC = I + I_C_SRC;
    int* W_OFF = I + I_W_OFF; int* W_DEG = I + I_W_DEG;
    int* W_CUR = I + I_W_CUR; int* W_SRC = I + I_W_SRC;
    int* B_OFF = I + I_B_OFF; int* B_DEG = I + I_B_DEG;
    int* B_CUR = I + I_B_CUR; int* B_SRC = I + I_B_SRC;
    int* BS    = I + I_BS;

    const int sm128 = gemm_smem(128);
    const int sm64  = gemm_smem(64);
    cudaFuncSetAttribute(mma_gemm<128, 2, false, false>, cudaFuncAttributeMaxDynamicSharedMemorySize, sm128);
    cudaFuncSetAttribute(mma_gemm<128, 1, false, false>, cudaFuncAttributeMaxDynamicSharedMemorySize, sm128);
    cudaFuncSetAttribute(mma_gemm<128, 1, true,  true >, cudaFuncAttributeMaxDynamicSharedMemorySize, sm128);
    cudaFuncSetAttribute(mma_gemm<128, 1, true,  false>, cudaFuncAttributeMaxDynamicSharedMemorySize, sm128);
    cudaFuncSetAttribute(mma_gemm<128, 1, false, true >, cudaFuncAttributeMaxDynamicSharedMemorySize, sm128);
    cudaFuncSetAttribute(mma_gemm<64,  1, false, false>, cudaFuncAttributeMaxDynamicSharedMemorySize, sm64);

    const int TP = (NPAPER + 127) / 128;
    const int TA = (NAUTHOR + 127) / 128;

    // ---- build CSRs once (edges shared across both layers) ----
    build_csr(src_c, dst_c, ECITES,  NPAPER,  C_OFF, C_DEG, C_CUR, C_SRC, BS);
    build_csr(src_w, dst_w, EWRITES, NPAPER,  W_OFF, W_DEG, W_CUR, W_SRC, BS + 256);
    build_csr(src_b, dst_b, EWB,     NAUTHOR, B_OFF, B_DEG, B_CUR, B_SRC, BS + 512);

    // ---- input projections ----
    mma_gemm<128, 2, false, false><<<TP, 256, sm128>>>(
        x_paper, Wp, bp, XPA, nullptr, nullptr, nullptr, nullptr, NPAPER);
    mma_gemm<128, 1, false, false><<<TA, 256, sm128>>>(
        x_author, Wa, ba, XAA, nullptr, nullptr, nullptr, nullptr, NAUTHOR);

    for (int l = 0; l < 2; l++) {
        const float* W   = l ? W1  : W0;
        const float* as_ = l ? as1 : as0;
        const float* ad_ = l ? ad1 : ad0;
        const float* bb  = l ? b1  : b0;
        const float* xp  = l ? XPB : XPA;
        const float* xa  = l ? XAB : XAA;

        // feature transforms + fused attention logits
        // (layer 1: wb relation output is dead -> skipped)
        mma_gemm<128, 1, true, true><<<TP, 256, sm128>>>(
            xp, W + 0 * HID * HID, nullptr, HP0, as_ + 0, ad_ + 0, ASC, ADC, NPAPER);
        mma_gemm<128, 1, false, true><<<TP, 256, sm128>>>(
            xp, W + 1 * HID * HID, nullptr, HP1, nullptr, ad_ + 128, nullptr, ADW, NPAPER);
        mma_gemm<128, 1, true, false><<<TA, 256, sm128>>>(
            xa, W + 1 * HID * HID, nullptr, HA1, as_ + 128, nullptr, ASW, nullptr, NAUTHOR);
        if (!l) {
            mma_gemm<128, 1, true, false><<<TP, 256, sm128>>>(
                xp, W + 2 * HID * HID, nullptr, HP2, as_ + 256, nullptr, ASB, nullptr, NPAPER);
            mma_gemm<128, 1, false, true><<<TA, 256, sm128>>>(
                xa, W + 2 * HID * HID, nullptr, HA2, nullptr, ad_ + 256, nullptr, ADB, NAUTHOR);
        }

        // dst-major aggregation: softmax + 2-relation sum + bias + activation,
        // no atomics, no memsets, no combine pass.
        agg_paper_k<<<(NPAPER * 32 + 255) / 256, 256>>>(
            C_SRC, C_OFF, C_DEG, W_SRC, W_OFF, W_DEG,
            ASC, ADC, HP0, ASW, ADW, HA1,
            bb, l ? XPA : XPB, l == 0);
        if (!l)
            agg_author_k<<<(NAUTHOR * 32 + 255) / 256, 256>>>(
                B_SRC, B_OFF, B_DEG, ASB, ADB, HP2, bb + 256, XAB);
    }

    // final classifier: [200000,128] @ [128,64] + blin
    mma_gemm<64, 1, false, false><<<TP, 256, sm64>>>(
        XPA, Wlin, blin, (float*)d_out, nullptr, nullptr, nullptr, nullptr, NPAPER);
}

// round 7
// speedup vs baseline: 3.0505x; 1.0620x over previous
#include <cuda_runtime.h>
#include <cstdint>

// ---------------------------------------------------------------------------
// Problem constants
// ---------------------------------------------------------------------------
static constexpr int NPAPER  = 200000;
static constexpr int NAUTHOR = 100000;
static constexpr int HID     = 128;     // 4 heads x 32 channels
static constexpr int ECITES  = 1000000;
static constexpr int EWRITES = 500000;
static constexpr int EWB     = 500000;

static constexpr size_t SZ_P = (size_t)NPAPER * HID;
static constexpr size_t SZ_A = (size_t)NAUTHOR * HID;

// float scratch
static constexpr size_t O_XPA  = 0;
static constexpr size_t O_XAA  = O_XPA  + SZ_P;
static constexpr size_t O_XPB  = O_XAA  + SZ_A;
static constexpr size_t O_XAB  = O_XPB  + SZ_P;
static constexpr size_t O_HP0  = O_XAB  + SZ_A;
static constexpr size_t O_HP2  = O_HP0  + SZ_P;
static constexpr size_t O_HA1  = O_HP2  + SZ_P;
static constexpr size_t O_LP1  = O_HA1  + SZ_A;              // paper logits GEMM1 [N,16]
static constexpr size_t O_LP2  = O_LP1  + (size_t)NPAPER * 16;
static constexpr size_t O_LA   = O_LP2  + (size_t)NPAPER * 16;
static constexpr size_t O_V    = O_LA   + (size_t)NAUTHOR * 16;  // 5 x [128][16]
static constexpr size_t SCRATCH_FLOATS = O_V + 5 * 2048;

__device__ float g_scratch[SCRATCH_FLOATS];

// int scratch (CSR)
static constexpr size_t I_C_OFF = 0;
static constexpr size_t I_C_DEG = I_C_OFF + NPAPER;
static constexpr size_t I_C_CUR = I_C_DEG + NPAPER;
static constexpr size_t I_C_SRC = I_C_CUR + NPAPER;
static constexpr size_t I_W_OFF = I_C_SRC + ECITES;
static constexpr size_t I_W_DEG = I_W_OFF + NPAPER;
static constexpr size_t I_W_CUR = I_W_DEG + NPAPER;
static constexpr size_t I_W_SRC = I_W_CUR + NPAPER;
static constexpr size_t I_B_OFF = I_W_SRC + EWRITES;
static constexpr size_t I_B_DEG = I_B_OFF + NAUTHOR;
static constexpr size_t I_B_CUR = I_B_DEG + NAUTHOR;
static constexpr size_t I_B_SRC = I_B_CUR + NAUTHOR;
static constexpr size_t I_BS    = I_B_SRC + EWB;
static constexpr size_t SCRATCH_INTS = I_BS + 3 * 256;

__device__ int g_iscratch[SCRATCH_INTS];

// ---------------------------------------------------------------------------
// tf32 helpers (plain sm_80+ PTX)
// ---------------------------------------------------------------------------
__device__ __forceinline__ float f2tf32(float f) {
    uint32_t u;
    asm("cvt.rna.tf32.f32 %0, %1;" : "=r"(u) : "f"(f));
    return __uint_as_float(u);
}

__device__ __forceinline__ void mma_tf32(float* c, uint32_t a0, uint32_t a1,
                                         uint32_t a2, uint32_t a3,
                                         uint32_t b0, uint32_t b1) {
    asm volatile(
        "mma.sync.aligned.m16n8k8.row.col.f32.tf32.tf32.f32 "
        "{%0,%1,%2,%3}, {%4,%5,%6,%7}, {%8,%9}, {%0,%1,%2,%3};"
        : "+f"(c[0]), "+f"(c[1]), "+f"(c[2]), "+f"(c[3])
        : "r"(a0), "r"(a1), "r"(a2), "r"(a3), "r"(b0), "r"(b1));
}

// ---------------------------------------------------------------------------
// Prep: V matrices = W @ att (per head). 5 matrices of [128][16]:
//  m0: layer0 paper  j0-3=W0[0]·as0[0]  j4-7=W0[0]·ad0[0]  j8-11=W0[1]·ad0[1]
//  m1: layer1 paper  (same with W1/as1/ad1)
//  m2: layer0 paper2 j0-3=W0[2]·as0[2]
//  m3: layer0 author j0-3=W0[1]·as0[1]  j4-7=W0[2]·ad0[2]
//  m4: layer1 author j0-3=W1[1]·as1[1]
// ---------------------------------------------------------------------------
__global__ void prep_v_k(const float* __restrict__ W0, const float* __restrict__ as0,
                         const float* __restrict__ ad0, const float* __restrict__ W1,
                         const float* __restrict__ as1, const float* __restrict__ ad1,
                         float* __restrict__ V) {
    int idx = blockIdx.x * blockDim.x + threadIdx.x;
    if (idx >= 5 * 2048) return;
    int m = idx >> 11;
    int r = idx & 2047;
    int k = r >> 4;
    int j = r & 15;
    int h = j & 3;
    int q = j >> 2;

    const float* Wm = nullptr;
    const float* at = nullptr;
    if (m == 0 || m == 1) {
        const float* W  = m ? W1 : W0;
        const float* as_ = m ? as1 : as0;
        const float* ad_ = m ? ad1 : ad0;
        if (q == 0)      { Wm = W;          at = as_; }
        else if (q == 1) { Wm = W;          at = ad_; }
        else if (q == 2) { Wm = W + 16384;  at = ad_ + 128; }
    } else if (m == 2) {
        if (q == 0) { Wm = W0 + 2 * 16384; at = as0 + 256; }
    } else if (m == 3) {
        if (q == 0)      { Wm = W0 + 16384;     at = as0 + 128; }
        else if (q == 1) { Wm = W0 + 2 * 16384; at = ad0 + 256; }
    } else {
        if (q == 0) { Wm = W1 + 16384; at = as1 + 128; }
    }
    float v = 0.f;
    if (Wm) {
#pragma unroll
        for (int c = 0; c < 32; c++)
            v += Wm[k * 128 + h * 32 + c] * at[h * 32 + c];
    }
    V[m * 2048 + k * 16 + j] = v;
}

// ---------------------------------------------------------------------------
// tf32 mma.sync GEMM: C[M,NC] = A[M,KCH*128] @ W[KCH*128, NC] (+bias);
// if VEXT, B gets 16 extra columns from Vx[128][16] whose outputs go to
// Lbuf[row*16 + (col-NC)]. W row stride is NC (FIX: was hardcoded 128).
// CTA tile 128 x N, 256 threads, 8 warps 4x2 (warp tile 32 x N/2).
// ---------------------------------------------------------------------------
template <int N, int KCH, bool VEXT>
__global__ void __launch_bounds__(256, 2)
mma_gemm(const float* __restrict__ A, const float* __restrict__ W,
         const float* __restrict__ Vx, const float* __restrict__ bias,
         float* __restrict__ C, float* __restrict__ Lbuf, int M) {
    constexpr int LDA_S = 68;
    constexpr int LDB_S = N + 8;
    constexpr int NF    = N / 16;
    constexpr int KTOT  = KCH * 128;
    constexpr int NC    = VEXT ? N - 16 : N;   // data columns == W width

    extern __shared__ float sm[];
    float* As = sm;
    float* Bs = sm + 128 * LDA_S;

    const int tid  = threadIdx.x;
    const int wid  = tid >> 5;
    const int lane = tid & 31;
    const int wm   = wid >> 1;
    const int wn   = wid & 1;
    const int g    = lane >> 2;
    const int tg   = lane & 3;
    const int row0 = blockIdx.x * 128;

    float acc[2][NF][4];
#pragma unroll
    for (int mf = 0; mf < 2; mf++)
#pragma unroll
        for (int nf = 0; nf < NF; nf++)
#pragma unroll
            for (int j = 0; j < 4; j++) acc[mf][nf][j] = 0.f;

    for (int kc = 0; kc < KCH * 2; kc++) {
        const int k0 = kc * 64;
#pragma unroll
        for (int i = tid; i < 128 * 16; i += 256) {
            int r = i >> 4, c4 = i & 15;
            int gr = row0 + r;
            float4 v = make_float4(0.f, 0.f, 0.f, 0.f);
            if (gr < M)
                v = *reinterpret_cast<const float4*>(A + (size_t)gr * KTOT + k0 + c4 * 4);
            float4 t = make_float4(f2tf32(v.x), f2tf32(v.y), f2tf32(v.z), f2tf32(v.w));
            *reinterpret_cast<float4*>(As + r * LDA_S + c4 * 4) = t;
        }
#pragma unroll
        for (int i = tid; i < 64 * (N / 4); i += 256) {
            int k = i / (N / 4), n4 = i % (N / 4);
            float4 v;
            if (!VEXT || n4 < NC / 4)
                v = *reinterpret_cast<const float4*>(W + (size_t)(k0 + k) * NC + n4 * 4);
            else
                v = reinterpret_cast<const float4*>(Vx)[(k0 + k) * 4 + (n4 - NC / 4)];
            float4 t = make_float4(f2tf32(v.x), f2tf32(v.y), f2tf32(v.z), f2tf32(v.w));
            *reinterpret_cast<float4*>(Bs + k * LDB_S + n4 * 4) = t;
        }
        __syncthreads();

#pragma unroll
        for (int s = 0; s < 8; s++) {
            const int kk = 8 * s;
            uint32_t b[NF][2];
#pragma unroll
            for (int nf = 0; nf < NF; nf++) {
                int col = wn * (N / 2) + nf * 8 + g;
                b[nf][0] = __float_as_uint(Bs[(kk + tg) * LDB_S + col]);
                b[nf][1] = __float_as_uint(Bs[(kk + tg + 4) * LDB_S + col]);
            }
#pragma unroll
            for (int mf = 0; mf < 2; mf++) {
                const int rb = wm * 32 + mf * 16;
                uint32_t a0 = __float_as_uint(As[(rb + g) * LDA_S + kk + tg]);
                uint32_t a1 = __float_as_uint(As[(rb + g + 8) * LDA_S + kk + tg]);
                uint32_t a2 = __float_as_uint(As[(rb + g) * LDA_S + kk + tg + 4]);
                uint32_t a3 = __float_as_uint(As[(rb + g + 8) * LDA_S + kk + tg + 4]);
#pragma unroll
                for (int nf = 0; nf < NF; nf++)
                    mma_tf32(acc[mf][nf], a0, a1, a2, a3, b[nf][0], b[nf][1]);
            }
        }
        __syncthreads();
    }

    // ---- epilogue ----
#pragma unroll
    for (int mf = 0; mf < 2; mf++) {
        const int r0 = row0 + wm * 32 + mf * 16 + g;
        const int r1 = r0 + 8;
#pragma unroll
        for (int nf = 0; nf < NF; nf++) {
            const int col = wn * (N / 2) + nf * 8 + tg * 2;
            float c0 = acc[mf][nf][0], c1 = acc[mf][nf][1];
            float c2 = acc[mf][nf][2], c3 = acc[mf][nf][3];
            if (!VEXT || col < NC) {
                if (bias) {
                    float b0v = bias[col], b1v = bias[col + 1];
                    c0 += b0v; c1 += b1v; c2 += b0v; c3 += b1v;
                }
                if (r0 < M)
                    *reinterpret_cast<float2*>(C + (size_t)r0 * NC + col) = make_float2(c0, c1);
                if (r1 < M)
                    *reinterpret_cast<float2*>(C + (size_t)r1 * NC + col) = make_float2(c2, c3);
            } else {
                const int lc = col - NC;
                if (r0 < M)
                    *reinterpret_cast<float2*>(Lbuf + (size_t)r0 * 16 + lc) = make_float2(c0, c1);
                if (r1 < M)
                    *reinterpret_cast<float2*>(Lbuf + (size_t)r1 * 16 + lc) = make_float2(c2, c3);
            }
        }
    }
}

// ---------------------------------------------------------------------------
// CSR build
// ---------------------------------------------------------------------------
__global__ void hist_k(const int* __restrict__ dst, int* __restrict__ deg, int E) {
    int e = blockIdx.x * blockDim.x + threadIdx.x;
    if (e < E) atomicAdd(&deg[dst[e]], 1);
}

__global__ void scanA_k(const int* __restrict__ deg, int* __restrict__ off,
                        int* __restrict__ bsum, int n) {
    __shared__ int sh[256];
    const int t = threadIdx.x, b = blockIdx.x;
    const int base = b * 2048 + t * 8;
    int v[8], s = 0;
#pragma unroll
    for (int i = 0; i < 8; i++) {
        int idx = base + i;
        v[i] = (idx < n) ? deg[idx] : 0;
        s += v[i];
    }
    sh[t] = s;
    __syncthreads();
    for (int o = 1; o < 256; o <<= 1) {
        int y = (t >= o) ? sh[t - o] : 0;
        __syncthreads();
        sh[t] += y;
        __syncthreads();
    }
    int run = sh[t] - s;
    if (t == 255) bsum[b] = sh[255];
#pragma unroll
    for (int i = 0; i < 8; i++) {
        int idx = base + i;
        if (idx < n) off[idx] = run;
        run += v[i];
    }
}

__global__ void scanB_k(int* __restrict__ bsum, int nb) {
    __shared__ int sh[256];
    int t = threadIdx.x;
    int v = (t < nb) ? bsum[t] : 0;
    sh[t] = v;
    __syncthreads();
    for (int o = 1; o < 256; o <<= 1) {
        int y = (t >= o) ? sh[t - o] : 0;
        __syncthreads();
        sh[t] += y;
        __syncthreads();
    }
    if (t < nb) bsum[t] = sh[t] - v;
}

__global__ void scanC_k(int* __restrict__ off, int* __restrict__ cur,
                        const int* __restrict__ bsum, int n) {
    int i = blockIdx.x * blockDim.x + threadIdx.x;
    if (i >= n) return;
    int v = off[i] + bsum[i >> 11];
    off[i] = v;
    cur[i] = v;
}

__global__ void scatter_k(const int* __restrict__ src, const int* __restrict__ dst,
                          int* __restrict__ cur, int* __restrict__ csrc, int E) {
    int e = blockIdx.x * blockDim.x + threadIdx.x;
    if (e >= E) return;
    int pos = atomicAdd(&cur[dst[e]], 1);
    csrc[pos] = src[e];
}

// ---------------------------------------------------------------------------
// Dst-major GAT aggregation (logits from 16-stride L buffers).
// ---------------------------------------------------------------------------
__device__ __forceinline__ float lrelu02(float v) { return v > 0.f ? v : 0.2f * v; }

__global__ void agg_paper_k(
    const int* __restrict__ c_src, const int* __restrict__ c_off, const int* __restrict__ c_deg,
    const int* __restrict__ w_src, const int* __restrict__ w_off, const int* __restrict__ w_deg,
    const float* __restrict__ LP1, const float* __restrict__ h1,
    const float* __restrict__ LA,  const float* __restrict__ h2,
    const float* __restrict__ bb, float* __restrict__ out, int act) {
    const int n    = (blockIdx.x * blockDim.x + threadIdx.x) >> 5;
    const int lane = threadIdx.x & 31;
    if (n >= NPAPER) return;
    const int h = lane >> 3;

    // relation 'cites': src logit LP1[:,0..3], dst logit LP1[:,4..7], feats h1
    float4 a1 = make_float4(0.f, 0.f, 0.f, 0.f);
    float  s1 = 0.f;
    {
        float ad = LP1[(size_t)n * 16 + 4 + h];
        int st = c_off[n], d = c_deg[n];
        for (int j = 0; j < d; j++) {
            int sidx = c_src[st + j];
            float x = __expf(lrelu02(LP1[(size_t)sidx * 16 + h] + ad));
            float4 hv = reinterpret_cast<const float4*>(h1 + (size_t)sidx * HID)[lane];
            s1 += x;
            a1.x += x * hv.x; a1.y += x * hv.y; a1.z += x * hv.z; a1.w += x * hv.w;
        }
    }
    // relation 'writes': src logit LA[:,0..3], dst logit LP1[:,8..11], feats h2
    float4 a2 = make_float4(0.f, 0.f, 0.f, 0.f);
    float  s2 = 0.f;
    {
        float ad = LP1[(size_t)n * 16 + 8 + h];
        int st = w_off[n], d = w_deg[n];
        for (int j = 0; j < d; j++) {
            int sidx = w_src[st + j];
            float x = __expf(lrelu02(LA[(size_t)sidx * 16 + h] + ad));
            float4 hv = reinterpret_cast<const float4*>(h2 + (size_t)sidx * HID)[lane];
            s2 += x;
            a2.x += x * hv.x; a2.y += x * hv.y; a2.z += x * hv.z; a2.w += x * hv.w;
        }
    }
    float i1 = 1.f / (s1 + 1e-16f);
    float i2 = 1.f / (s2 + 1e-16f);
    float4 bv1 = reinterpret_cast<const float4*>(bb)[lane];
    float4 bv2 = reinterpret_cast<const float4*>(bb + 128)[lane];
    float4 o;
    o.x = a1.x * i1 + a2.x * i2 + bv1.x + bv2.x;
    o.y = a1.y * i1 + a2.y * i2 + bv1.y + bv2.y;
    o.z = a1.z * i1 + a2.z * i2 + bv1.z + bv2.z;
    o.w = a1.w * i1 + a2.w * i2 + bv1.w + bv2.w;
    if (act) {
        o.x = o.x > 0.f ? o.x : 0.01f * o.x;
        o.y = o.y > 0.f ? o.y : 0.01f * o.y;
        o.z = o.z > 0.f ? o.z : 0.01f * o.z;
        o.w = o.w > 0.f ? o.w : 0.01f * o.w;
    }
    reinterpret_cast<float4*>(out + (size_t)n * HID)[lane] = o;
}

__global__ void agg_author_k(
    const int* __restrict__ b_src, const int* __restrict__ b_off, const int* __restrict__ b_deg,
    const float* __restrict__ LP2, const float* __restrict__ LA,
    const float* __restrict__ h1, const float* __restrict__ bb,
    float* __restrict__ out) {
    const int n    = (blockIdx.x * blockDim.x + threadIdx.x) >> 5;
    const int lane = threadIdx.x & 31;
    if (n >= NAUTHOR) return;
    const int h = lane >> 3;

    // relation 'written_by': src logit LP2[:,0..3], dst logit LA[:,4..7]
    float4 a1 = make_float4(0.f, 0.f, 0.f, 0.f);
    float  s1 = 0.f;
    float ad = LA[(size_t)n * 16 + 4 + h];
    int st = b_off[n], d = b_deg[n];
    for (int j = 0; j < d; j++) {
        int sidx = b_src[st + j];
        float x = __expf(lrelu02(LP2[(size_t)sidx * 16 + h] + ad));
        float4 hv = reinterpret_cast<const float4*>(h1 + (size_t)sidx * HID)[lane];
        s1 += x;
        a1.x += x * hv.x; a1.y += x * hv.y; a1.z += x * hv.z; a1.w += x * hv.w;
    }
    float i1 = 1.f / (s1 + 1e-16f);
    float4 bv = reinterpret_cast<const float4*>(bb)[lane];
    float4 o;
    o.x = a1.x * i1 + bv.x;
    o.y = a1.y * i1 + bv.y;
    o.z = a1.z * i1 + bv.z;
    o.w = a1.w * i1 + bv.w;
    o.x = o.x > 0.f ? o.x : 0.01f * o.x;
    o.y = o.y > 0.f ? o.y : 0.01f * o.y;
    o.z = o.z > 0.f ? o.z : 0.01f * o.z;
    o.w = o.w > 0.f ? o.w : 0.01f * o.w;
    reinterpret_cast<float4*>(out + (size_t)n * HID)[lane] = o;
}

// ---------------------------------------------------------------------------
// Host orchestration
// ---------------------------------------------------------------------------
static inline int gemm_smem(int N) { return (128 * 68 + 64 * (N + 8)) * 4; }

static void build_csr(const int* src, const int* dst, int E, int Ndst,
                      int* off, int* deg, int* cur, int* csrc, int* bsum) {
    cudaMemsetAsync(deg, 0, (size_t)Ndst * sizeof(int));
    hist_k<<<(E + 255) / 256, 256>>>(dst, deg, E);
    int nb = (Ndst + 2047) / 2048;
    scanA_k<<<nb, 256>>>(deg, off, bsum, Ndst);
    scanB_k<<<1, 256>>>(bsum, nb);
    scanC_k<<<(Ndst + 255) / 256, 256>>>(off, cur, bsum, Ndst);
    scatter_k<<<(E + 255) / 256, 256>>>(src, dst, cur, csrc, E);
}

extern "C" void kernel_launch(void* const* d_in, const int* in_sizes, int n_in,
                              void* d_out, int out_size) {
    const float* x_paper  = (const float*)d_in[0];
    const float* x_author = (const float*)d_in[1];
    const float* Wp   = (const float*)d_in[2];
    const float* bp   = (const float*)d_in[3];
    const float* Wa   = (const float*)d_in[4];
    const float* ba   = (const float*)d_in[5];
    const float* W0   = (const float*)d_in[6];
    const float* as0  = (const float*)d_in[7];
    const float* ad0  = (const float*)d_in[8];
    const float* b0   = (const float*)d_in[9];
    const float* W1   = (const float*)d_in[10];
    const float* as1  = (const float*)d_in[11];
    const float* ad1  = (const float*)d_in[12];
    const float* b1   = (const float*)d_in[13];
    const float* Wlin = (const float*)d_in[14];
    const float* blin = (const float*)d_in[15];
    const int* src_c  = (const int*)d_in[16];
    const int* dst_c  = (const int*)d_in[17];
    const int* src_w  = (const int*)d_in[18];
    const int* dst_w  = (const int*)d_in[19];
    const int* src_b  = (const int*)d_in[20];
    const int* dst_b  = (const int*)d_in[21];

    float* S = nullptr;
    cudaGetSymbolAddress((void**)&S, g_scratch);
    int* I = nullptr;
    cudaGetSymbolAddress((void**)&I, g_iscratch);

    float* XPA = S + O_XPA;
    float* XAA = S + O_XAA;
    float* XPB = S + O_XPB;
    float* XAB = S + O_XAB;
    float* HP0 = S + O_HP0;
    float* HP2 = S + O_HP2;
    float* HA1 = S + O_HA1;
    float* LP1 = S + O_LP1;
    float* LP2 = S + O_LP2;
    float* LA  = S + O_LA;
    float* V   = S + O_V;

    int* C_OFF = I + I_C_OFF; int* C_DEG = I + I_C_DEG;
    int* C_CUR = I + I_C_CUR; int* C_SRC = I + I_C_SRC;
    int* W_OFF = I + I_W_OFF; int* W_DEG = I + I_W_DEG;
    int* W_CUR = I + I_W_CUR; int* W_SRC = I + I_W_SRC;
    int* B_OFF = I + I_B_OFF; int* B_DEG = I + I_B_DEG;
    int* B_CUR = I + I_B_CUR; int* B_SRC = I + I_B_SRC;
    int* BS    = I + I_BS;

    const int sm144 = gemm_smem(144);
    const int sm128 = gemm_smem(128);
    const int sm64  = gemm_smem(64);
    cudaFuncSetAttribute(mma_gemm<128, 2, false>, cudaFuncAttributeMaxDynamicSharedMemorySize, sm128);
    cudaFuncSetAttribute(mma_gemm<128, 1, false>, cudaFuncAttributeMaxDynamicSharedMemorySize, sm128);
    cudaFuncSetAttribute(mma_gemm<144, 1, true >, cudaFuncAttributeMaxDynamicSharedMemorySize, sm144);
    cudaFuncSetAttribute(mma_gemm<64,  1, false>, cudaFuncAttributeMaxDynamicSharedMemorySize, sm64);

    const int TP = (NPAPER + 127) / 128;
    const int TA = (NAUTHOR + 127) / 128;

    // ---- prep V (skinny logit matrices) + CSRs (edges shared across layers) ----
    prep_v_k<<<40, 256>>>(W0, as0, ad0, W1, as1, ad1, V);
    build_csr(src_c, dst_c, ECITES,  NPAPER,  C_OFF, C_DEG, C_CUR, C_SRC, BS);
    build_csr(src_w, dst_w, EWRITES, NPAPER,  W_OFF, W_DEG, W_CUR, W_SRC, BS + 256);
    build_csr(src_b, dst_b, EWB,     NAUTHOR, B_OFF, B_DEG, B_CUR, B_SRC, BS + 512);

    // ---- input projections ----
    mma_gemm<128, 2, false><<<TP, 256, sm128>>>(x_paper, Wp, nullptr, bp, XPA, nullptr, NPAPER);
    mma_gemm<128, 1, false><<<TA, 256, sm128>>>(x_author, Wa, nullptr, ba, XAA, nullptr, NAUTHOR);

    for (int l = 0; l < 2; l++) {
        const float* W  = l ? W1 : W0;
        const float* bb = l ? b1 : b0;
        const float* xp = l ? XPB : XPA;
        const float* xa = l ? XAB : XAA;

        // paper main: HP0 = xp@W[0]; logits as·W[0] / ad·W[0] / ad·W[1] -> LP1
        mma_gemm<144, 1, true><<<TP, 256, sm144>>>(
            xp, W + 0 * HID * HID, V + (l ? 1 : 0) * 2048, nullptr, HP0, LP1, NPAPER);
        // author: HA1 = xa@W[1]; logits as·W[1] (+ ad·W[2] in layer0) -> LA
        mma_gemm<144, 1, true><<<TA, 256, sm144>>>(
            xa, W + 1 * HID * HID, V + (l ? 4 : 3) * 2048, nullptr, HA1, LA, NAUTHOR);
        if (!l) {
            // paper 2nd: HP2 = xp@W[2]; logit as·W[2] -> LP2
            mma_gemm<144, 1, true><<<TP, 256, sm144>>>(
                xp, W + 2 * HID * HID, V + 2 * 2048, nullptr, HP2, LP2, NPAPER);
        }

        agg_paper_k<<<(NPAPER * 32 + 255) / 256, 256>>>(
            C_SRC, C_OFF, C_DEG, W_SRC, W_OFF, W_DEG,
            LP1, HP0, LA, HA1, bb, l ? XPA : XPB, l == 0);
        if (!l)
            agg_author_k<<<(NAUTHOR * 32 + 255) / 256, 256>>>(
                B_SRC, B_OFF, B_DEG, LP2, LA, HP2, bb + 256, XAB);
    }

    // final classifier: [200000,128] @ [128,64] + blin
    mma_gemm<64, 1, false><<<TP, 256, sm64>>>(
        XPA, Wlin, nullptr, blin, (float*)d_out, nullptr, NPAPER);
}

// round 8
// speedup vs baseline: 3.3923x; 1.1120x over previous
#include <cuda_runtime.h>
#include <cuda_fp16.h>
#include <cstdint>

// ---------------------------------------------------------------------------
// Problem constants
// ---------------------------------------------------------------------------
static constexpr int NPAPER  = 200000;
static constexpr int NAUTHOR = 100000;
static constexpr int HID     = 128;     // 4 heads x 32 channels
static constexpr int ECITES  = 1000000;
static constexpr int EWRITES = 500000;
static constexpr int EWB     = 500000;
static constexpr int ETOT    = ECITES + EWRITES + EWB;   // 2,000,000
static constexpr int NTOT    = 2 * NPAPER + NAUTHOR;     // 500,000 (cites|writes|wb slots)

static constexpr size_t SZ_P = (size_t)NPAPER * HID;
static constexpr size_t SZ_A = (size_t)NAUTHOR * HID;

// float scratch
static constexpr size_t O_XPA  = 0;
static constexpr size_t O_XAA  = O_XPA  + SZ_P;
static constexpr size_t O_XPB  = O_XAA  + SZ_A;
static constexpr size_t O_XAB  = O_XPB  + SZ_P;
static constexpr size_t O_LP1  = O_XAB  + SZ_A;                  // paper logits [N,16]
static constexpr size_t O_LP2  = O_LP1  + (size_t)NPAPER * 16;
static constexpr size_t O_LA   = O_LP2  + (size_t)NPAPER * 16;
static constexpr size_t O_V    = O_LA   + (size_t)NAUTHOR * 16;  // 5 x [128][16]
static constexpr size_t SCRATCH_FLOATS = O_V + 5 * 2048;

__device__ float g_scratch[SCRATCH_FLOATS];

// half scratch (gathered feature buffers only)
static constexpr size_t H_HP0 = 0;
static constexpr size_t H_HP2 = H_HP0 + SZ_P;
static constexpr size_t H_HA1 = H_HP2 + SZ_P;
static constexpr size_t SCRATCH_HALF = H_HA1 + SZ_A;

__device__ __half g_hscratch[SCRATCH_HALF];

// int scratch: merged CSR over concatenated node slots
// slot = dst          (cites,  dst paper)   [0, NPAPER)
//      = NPAPER + dst (writes, dst paper)   [NPAPER, 2*NPAPER)
//      = 2*NPAPER+dst (wb,     dst author)  [2*NPAPER, NTOT)
static constexpr size_t I_DEGS = 0;
static constexpr size_t I_OFFS = I_DEGS + NTOT;
static constexpr size_t I_CURS = I_OFFS + NTOT;
static constexpr size_t I_SRCS = I_CURS + NTOT;
static constexpr size_t I_BS   = I_SRCS + ETOT;
static constexpr size_t SCRATCH_INTS = I_BS + 256;

__device__ int g_iscratch[SCRATCH_INTS];

// ---------------------------------------------------------------------------
// tf32 helpers (plain sm_80+ PTX)
// ---------------------------------------------------------------------------
__device__ __forceinline__ float f2tf32(float f) {
    uint32_t u;
    asm("cvt.rna.tf32.f32 %0, %1;" : "=r"(u) : "f"(f));
    return __uint_as_float(u);
}

__device__ __forceinline__ void mma_tf32(float* c, uint32_t a0, uint32_t a1,
                                         uint32_t a2, uint32_t a3,
                                         uint32_t b0, uint32_t b1) {
    asm volatile(
        "mma.sync.aligned.m16n8k8.row.col.f32.tf32.tf32.f32 "
        "{%0,%1,%2,%3}, {%4,%5,%6,%7}, {%8,%9}, {%0,%1,%2,%3};"
        : "+f"(c[0]), "+f"(c[1]), "+f"(c[2]), "+f"(c[3])
        : "r"(a0), "r"(a1), "r"(a2), "r"(a3), "r"(b0), "r"(b1));
}

// ---------------------------------------------------------------------------
// Prep: V matrices = W @ att (per head). 5 matrices of [128][16]:
//  m0: layer0 paper  j0-3=W0[0]·as0[0]  j4-7=W0[0]·ad0[0]  j8-11=W0[1]·ad0[1]
//  m1: layer1 paper  (same with W1/as1/ad1)
//  m2: layer0 paper2 j0-3=W0[2]·as0[2]
//  m3: layer0 author j0-3=W0[1]·as0[1]  j4-7=W0[2]·ad0[2]
//  m4: layer1 author j0-3=W1[1]·as1[1]
// ---------------------------------------------------------------------------
__global__ void prep_v_k(const float* __restrict__ W0, const float* __restrict__ as0,
                         const float* __restrict__ ad0, const float* __restrict__ W1,
                         const float* __restrict__ as1, const float* __restrict__ ad1,
                         float* __restrict__ V) {
    int idx = blockIdx.x * blockDim.x + threadIdx.x;
    if (idx >= 5 * 2048) return;
    int m = idx >> 11;
    int r = idx & 2047;
    int k = r >> 4;
    int j = r & 15;
    int h = j & 3;
    int q = j >> 2;

    const float* Wm = nullptr;
    const float* at = nullptr;
    if (m == 0 || m == 1) {
        const float* W  = m ? W1 : W0;
        const float* as_ = m ? as1 : as0;
        const float* ad_ = m ? ad1 : ad0;
        if (q == 0)      { Wm = W;          at = as_; }
        else if (q == 1) { Wm = W;          at = ad_; }
        else if (q == 2) { Wm = W + 16384;  at = ad_ + 128; }
    } else if (m == 2) {
        if (q == 0) { Wm = W0 + 2 * 16384; at = as0 + 256; }
    } else if (m == 3) {
        if (q == 0)      { Wm = W0 + 16384;     at = as0 + 128; }
        else if (q == 1) { Wm = W0 + 2 * 16384; at = ad0 + 256; }
    } else {
        if (q == 0) { Wm = W1 + 16384; at = as1 + 128; }
    }
    float v = 0.f;
    if (Wm) {
#pragma unroll
        for (int c = 0; c < 32; c++)
            v += Wm[k * 128 + h * 32 + c] * at[h * 32 + c];
    }
    V[m * 2048 + k * 16 + j] = v;
}

// ---------------------------------------------------------------------------
// tf32 mma.sync GEMM: C[M,NC] = A[M,KCH*128] @ W[KCH*128, NC] (+bias);
// if VEXT, B gets 16 extra columns from Vx[128][16] -> Lbuf[row*16 + (col-NC)].
// If HALF, C is __half (half2 stores). W row stride is NC.
// CTA tile 128 x N, 256 threads, 8 warps 4x2 (warp tile 32 x N/2).
// ---------------------------------------------------------------------------
template <int N, int KCH, bool VEXT, bool HALF>
__global__ void __launch_bounds__(256, 2)
mma_gemm(const float* __restrict__ A, const float* __restrict__ W,
         const float* __restrict__ Vx, const float* __restrict__ bias,
         void* __restrict__ Cv, float* __restrict__ Lbuf, int M) {
    constexpr int LDA_S = 68;
    constexpr int LDB_S = N + 8;
    constexpr int NF    = N / 16;
    constexpr int KTOT  = KCH * 128;
    constexpr int NC    = VEXT ? N - 16 : N;   // data columns == W width

    extern __shared__ float sm[];
    float* As = sm;
    float* Bs = sm + 128 * LDA_S;

    const int tid  = threadIdx.x;
    const int wid  = tid >> 5;
    const int lane = tid & 31;
    const int wm   = wid >> 1;
    const int wn   = wid & 1;
    const int g    = lane >> 2;
    const int tg   = lane & 3;
    const int row0 = blockIdx.x * 128;

    float acc[2][NF][4];
#pragma unroll
    for (int mf = 0; mf < 2; mf++)
#pragma unroll
        for (int nf = 0; nf < NF; nf++)
#pragma unroll
            for (int j = 0; j < 4; j++) acc[mf][nf][j] = 0.f;

    for (int kc = 0; kc < KCH * 2; kc++) {
        const int k0 = kc * 64;
#pragma unroll
        for (int i = tid; i < 128 * 16; i += 256) {
            int r = i >> 4, c4 = i & 15;
            int gr = row0 + r;
            float4 v = make_float4(0.f, 0.f, 0.f, 0.f);
            if (gr < M)
                v = *reinterpret_cast<const float4*>(A + (size_t)gr * KTOT + k0 + c4 * 4);
            float4 t = make_float4(f2tf32(v.x), f2tf32(v.y), f2tf32(v.z), f2tf32(v.w));
            *reinterpret_cast<float4*>(As + r * LDA_S + c4 * 4) = t;
        }
#pragma unroll
        for (int i = tid; i < 64 * (N / 4); i += 256) {
            int k = i / (N / 4), n4 = i % (N / 4);
            float4 v;
            if (!VEXT || n4 < NC / 4)
                v = *reinterpret_cast<const float4*>(W + (size_t)(k0 + k) * NC + n4 * 4);
            else
                v = reinterpret_cast<const float4*>(Vx)[(k0 + k) * 4 + (n4 - NC / 4)];
            float4 t = make_float4(f2tf32(v.x), f2tf32(v.y), f2tf32(v.z), f2tf32(v.w));
            *reinterpret_cast<float4*>(Bs + k * LDB_S + n4 * 4) = t;
        }
        __syncthreads();

#pragma unroll
        for (int s = 0; s < 8; s++) {
            const int kk = 8 * s;
            uint32_t b[NF][2];
#pragma unroll
            for (int nf = 0; nf < NF; nf++) {
                int col = wn * (N / 2) + nf * 8 + g;
                b[nf][0] = __float_as_uint(Bs[(kk + tg) * LDB_S + col]);
                b[nf][1] = __float_as_uint(Bs[(kk + tg + 4) * LDB_S + col]);
            }
#pragma unroll
            for (int mf = 0; mf < 2; mf++) {
                const int rb = wm * 32 + mf * 16;
                uint32_t a0 = __float_as_uint(As[(rb + g) * LDA_S + kk + tg]);
                uint32_t a1 = __float_as_uint(As[(rb + g + 8) * LDA_S + kk + tg]);
                uint32_t a2 = __float_as_uint(As[(rb + g) * LDA_S + kk + tg + 4]);
                uint32_t a3 = __float_as_uint(As[(rb + g + 8) * LDA_S + kk + tg + 4]);
#pragma unroll
                for (int nf = 0; nf < NF; nf++)
                    mma_tf32(acc[mf][nf], a0, a1, a2, a3, b[nf][0], b[nf][1]);
            }
        }
        __syncthreads();
    }

    // ---- epilogue ----
#pragma unroll
    for (int mf = 0; mf < 2; mf++) {
        const int r0 = row0 + wm * 32 + mf * 16 + g;
        const int r1 = r0 + 8;
#pragma unroll
        for (int nf = 0; nf < NF; nf++) {
            const int col = wn * (N / 2) + nf * 8 + tg * 2;
            float c0 = acc[mf][nf][0], c1 = acc[mf][nf][1];
            float c2 = acc[mf][nf][2], c3 = acc[mf][nf][3];
            if (!VEXT || col < NC) {
                if (bias) {
                    float b0v = bias[col], b1v = bias[col + 1];
                    c0 += b0v; c1 += b1v; c2 += b0v; c3 += b1v;
                }
                if (HALF) {
                    __half* C = (__half*)Cv;
                    if (r0 < M)
                        *reinterpret_cast<__half2*>(C + (size_t)r0 * NC + col) =
                            __floats2half2_rn(c0, c1);
                    if (r1 < M)
                        *reinterpret_cast<__half2*>(C + (size_t)r1 * NC + col) =
                            __floats2half2_rn(c2, c3);
                } else {
                    float* C = (float*)Cv;
                    if (r0 < M)
                        *reinterpret_cast<float2*>(C + (size_t)r0 * NC + col) = make_float2(c0, c1);
                    if (r1 < M)
                        *reinterpret_cast<float2*>(C + (size_t)r1 * NC + col) = make_float2(c2, c3);
                }
            } else {
                const int lc = col - NC;
                if (r0 < M)
                    *reinterpret_cast<float2*>(Lbuf + (size_t)r0 * 16 + lc) = make_float2(c0, c1);
                if (r1 < M)
                    *reinterpret_cast<float2*>(Lbuf + (size_t)r1 * 16 + lc) = make_float2(c2, c3);
            }
        }
    }
}

// ---------------------------------------------------------------------------
// Merged CSR build over concatenated slot space (3 relations, one scan)
// ---------------------------------------------------------------------------
__global__ void hist3_k(const int* __restrict__ dc, const int* __restrict__ dw,
                        const int* __restrict__ db, int* __restrict__ degs) {
    int e = blockIdx.x * blockDim.x + threadIdx.x;
    if (e >= ETOT) return;
    int slot;
    if (e < ECITES)                slot = dc[e];
    else if (e < ECITES + EWRITES) slot = NPAPER + dw[e - ECITES];
    else                           slot = 2 * NPAPER + db[e - ECITES - EWRITES];
    atomicAdd(&degs[slot], 1);
}

__global__ void scanA_k(const int* __restrict__ deg, int* __restrict__ off,
                        int* __restrict__ bsum, int n) {
    __shared__ int sh[256];
    const int t = threadIdx.x, b = blockIdx.x;
    const int base = b * 2048 + t * 8;
    int v[8], s = 0;
#pragma unroll
    for (int i = 0; i < 8; i++) {
        int idx = base + i;
        v[i] = (idx < n) ? deg[idx] : 0;
        s += v[i];
    }
    sh[t] = s;
    __syncthreads();
    for (int o = 1; o < 256; o <<= 1) {
        int y = (t >= o) ? sh[t - o] : 0;
        __syncthreads();
        sh[t] += y;
        __syncthreads();
    }
    int run = sh[t] - s;
    if (t == 255) bsum[b] = sh[255];
#pragma unroll
    for (int i = 0; i < 8; i++) {
        int idx = base + i;
        if (idx < n) off[idx] = run;
        run += v[i];
    }
}

__global__ void scanB_k(int* __restrict__ bsum, int nb) {
    __shared__ int sh[256];
    int t = threadIdx.x;
    int v = (t < nb) ? bsum[t] : 0;
    sh[t] = v;
    __syncthreads();
    for (int o = 1; o < 256; o <<= 1) {
        int y = (t >= o) ? sh[t - o] : 0;
        __syncthreads();
        sh[t] += y;
        __syncthreads();
    }
    if (t < nb) bsum[t] = sh[t] - v;
}

__global__ void scanC_k(int* __restrict__ off, int* __restrict__ cur,
                        const int* __restrict__ bsum, int n) {
    int i = blockIdx.x * blockDim.x + threadIdx.x;
    if (i >= n) return;
    int v = off[i] + bsum[i >> 11];
    off[i] = v;
    cur[i] = v;
}

__global__ void scatter3_k(const int* __restrict__ sc, const int* __restrict__ dc,
                           const int* __restrict__ sw, const int* __restrict__ dw,
                           const int* __restrict__ sb, const int* __restrict__ db,
                           int* __restrict__ curs, int* __restrict__ srcs) {
    int e = blockIdx.x * blockDim.x + threadIdx.x;
    if (e >= ETOT) return;
    int slot, sv;
    if (e < ECITES)                { slot = dc[e]; sv = sc[e]; }
    else if (e < ECITES + EWRITES) { int i = e - ECITES; slot = NPAPER + dw[i]; sv = sw[i]; }
    else                           { int i = e - ECITES - EWRITES; slot = 2 * NPAPER + db[i]; sv = sb[i]; }
    srcs[atomicAdd(&curs[slot], 1)] = sv;
}

// ---------------------------------------------------------------------------
// Dst-major GAT aggregation; gathered features are fp16 (half the traffic).
// ---------------------------------------------------------------------------
__device__ __forceinline__ float lrelu02(float v) { return v > 0.f ? v : 0.2f * v; }

__device__ __forceinline__ float4 gather_h16(const __half* __restrict__ hbuf,
                                             int sidx, int lane) {
    uint2 u = reinterpret_cast<const uint2*>(hbuf + (size_t)sidx * HID)[lane];
    __half2 p0 = *reinterpret_cast<__half2*>(&u.x);
    __half2 p1 = *reinterpret_cast<__half2*>(&u.y);
    float2 f0 = __half22float2(p0);
    float2 f1 = __half22float2(p1);
    return make_float4(f0.x, f0.y, f1.x, f1.y);
}

__global__ void agg_paper_k(
    const int* __restrict__ srcs, const int* __restrict__ offs, const int* __restrict__ degs,
    const float* __restrict__ LP1, const __half* __restrict__ h1,
    const float* __restrict__ LA,  const __half* __restrict__ h2,
    const float* __restrict__ bb, float* __restrict__ out, int act) {
    const int n    = (blockIdx.x * blockDim.x + threadIdx.x) >> 5;
    const int lane = threadIdx.x & 31;
    if (n >= NPAPER) return;
    const int h = lane >> 3;

    // relation 'cites' (slot n): src logit LP1[:,0..3], dst logit LP1[:,4..7]
    float4 a1 = make_float4(0.f, 0.f, 0.f, 0.f);
    float  s1 = 0.f;
    {
        float ad = LP1[(size_t)n * 16 + 4 + h];
        int st = offs[n], d = degs[n];
        for (int j = 0; j < d; j++) {
            int sidx = srcs[st + j];
            float x = __expf(lrelu02(LP1[(size_t)sidx * 16 + h] + ad));
            float4 hv = gather_h16(h1, sidx, lane);
            s1 += x;
            a1.x += x * hv.x; a1.y += x * hv.y; a1.z += x * hv.z; a1.w += x * hv.w;
        }
    }
    // relation 'writes' (slot NPAPER+n): src logit LA[:,0..3], dst logit LP1[:,8..11]
    float4 a2 = make_float4(0.f, 0.f, 0.f, 0.f);
    float  s2 = 0.f;
    {
        float ad = LP1[(size_t)n * 16 + 8 + h];
        int st = offs[NPAPER + n], d = degs[NPAPER + n];
        for (int j = 0; j < d; j++) {
            int sidx = srcs[st + j];
            float x = __expf(lrelu02(LA[(size_t)sidx * 16 + h] + ad));
            float4 hv = gather_h16(h2, sidx, lane);
            s2 += x;
            a2.x += x * hv.x; a2.y += x * hv.y; a2.z += x * hv.z; a2.w += x * hv.w;
        }
    }
    float i1 = 1.f / (s1 + 1e-16f);
    float i2 = 1.f / (s2 + 1e-16f);
    float4 bv1 = reinterpret_cast<const float4*>(bb)[lane];
    float4 bv2 = reinterpret_cast<const float4*>(bb + 128)[lane];
    float4 o;
    o.x = a1.x * i1 + a2.x * i2 + bv1.x + bv2.x;
    o.y = a1.y * i1 + a2.y * i2 + bv1.y + bv2.y;
    o.z = a1.z * i1 + a2.z * i2 + bv1.z + bv2.z;
    o.w = a1.w * i1 + a2.w * i2 + bv1.w + bv2.w;
    if (act) {
        o.x = o.x > 0.f ? o.x : 0.01f * o.x;
        o.y = o.y > 0.f ? o.y : 0.01f * o.y;
        o.z = o.z > 0.f ? o.z : 0.01f * o.z;
        o.w = o.w > 0.f ? o.w : 0.01f * o.w;
    }
    reinterpret_cast<float4*>(out + (size_t)n * HID)[lane] = o;
}

__global__ void agg_author_k(
    const int* __restrict__ srcs, const int* __restrict__ offs, const int* __restrict__ degs,
    const float* __restrict__ LP2, const float* __restrict__ LA,
    const __half* __restrict__ h1, const float* __restrict__ bb,
    float* __restrict__ out) {
    const int n    = (blockIdx.x * blockDim.x + threadIdx.x) >> 5;
    const int lane = threadIdx.x & 31;
    if (n >= NAUTHOR) return;
    const int h = lane >> 3;

    // relation 'written_by' (slot 2*NPAPER+n): src logit LP2[:,0..3], dst logit LA[:,4..7]
    float4 a1 = make_float4(0.f, 0.f, 0.f, 0.f);
    float  s1 = 0.f;
    float ad = LA[(size_t)n * 16 + 4 + h];
    int st = offs[2 * NPAPER + n], d = degs[2 * NPAPER + n];
    for (int j = 0; j < d; j++) {
        int sidx = srcs[st + j];
        float x = __expf(lrelu02(LP2[(size_t)sidx * 16 + h] + ad));
        float4 hv = gather_h16(h1, sidx, lane);
        s1 += x;
        a1.x += x * hv.x; a1.y += x * hv.y; a1.z += x * hv.z; a1.w += x * hv.w;
    }
    float i1 = 1.f / (s1 + 1e-16f);
    float4 bv = reinterpret_cast<const float4*>(bb)[lane];
    float4 o;
    o.x = a1.x * i1 + bv.x;
    o.y = a1.y * i1 + bv.y;
    o.z = a1.z * i1 + bv.z;
    o.w = a1.w * i1 + bv.w;
    o.x = o.x > 0.f ? o.x : 0.01f * o.x;
    o.y = o.y > 0.f ? o.y : 0.01f * o.y;
    o.z = o.z > 0.f ? o.z : 0.01f * o.z;
    o.w = o.w > 0.f ? o.w : 0.01f * o.w;
    reinterpret_cast<float4*>(out + (size_t)n * HID)[lane] = o;
}

// ---------------------------------------------------------------------------
// Host orchestration
// ---------------------------------------------------------------------------
static inline int gemm_smem(int N) { return (128 * 68 + 64 * (N + 8)) * 4; }

extern "C" void kernel_launch(void* const* d_in, const int* in_sizes, int n_in,
                              void* d_out, int out_size) {
    const float* x_paper  = (const float*)d_in[0];
    const float* x_author = (const float*)d_in[1];
    const float* Wp   = (const float*)d_in[2];
    const float* bp   = (const float*)d_in[3];
    const float* Wa   = (const float*)d_in[4];
    const float* ba   = (const float*)d_in[5];
    const float* W0   = (const float*)d_in[6];
    const float* as0  = (const float*)d_in[7];
    const float* ad0  = (const float*)d_in[8];
    const float* b0   = (const float*)d_in[9];
    const float* W1   = (const float*)d_in[10];
    const float* as1  = (const float*)d_in[11];
    const float* ad1  = (const float*)d_in[12];
    const float* b1   = (const float*)d_in[13];
    const float* Wlin = (const float*)d_in[14];
    const float* blin = (const float*)d_in[15];
    const int* src_c  = (const int*)d_in[16];
    const int* dst_c  = (const int*)d_in[17];
    const int* src_w  = (const int*)d_in[18];
    const int* dst_w  = (const int*)d_in[19];
    const int* src_b  = (const int*)d_in[20];
    const int* dst_b  = (const int*)d_in[21];

    float* S = nullptr;
    cudaGetSymbolAddress((void**)&S, g_scratch);
    __half* Hh = nullptr;
    cudaGetSymbolAddress((void**)&Hh, g_hscratch);
    int* I = nullptr;
    cudaGetSymbolAddress((void**)&I, g_iscratch);

    float*  XPA = S + O_XPA;
    float*  XAA = S + O_XAA;
    float*  XPB = S + O_XPB;
    float*  XAB = S + O_XAB;
    float*  LP1 = S + O_LP1;
    float*  LP2 = S + O_LP2;
    float*  LA  = S + O_LA;
    float*  V   = S + O_V;
    __half* HP0 = Hh + H_HP0;
    __half* HP2 = Hh + H_HP2;
    __half* HA1 = Hh + H_HA1;

    int* DEGS = I + I_DEGS;
    int* OFFS = I + I_OFFS;
    int* CURS = I + I_CURS;
    int* SRCS = I + I_SRCS;
    int* BS   = I + I_BS;

    const int sm144 = gemm_smem(144);
    const int sm128 = gemm_smem(128);
    const int sm64  = gemm_smem(64);
    cudaFuncSetAttribute(mma_gemm<128, 2, false, false>, cudaFuncAttributeMaxDynamicSharedMemorySize, sm128);
    cudaFuncSetAttribute(mma_gemm<128, 1, false, false>, cudaFuncAttributeMaxDynamicSharedMemorySize, sm128);
    cudaFuncSetAttribute(mma_gemm<144, 1, true,  true >, cudaFuncAttributeMaxDynamicSharedMemorySize, sm144);
    cudaFuncSetAttribute(mma_gemm<64,  1, false, false>, cudaFuncAttributeMaxDynamicSharedMemorySize, sm64);

    const int TP = (NPAPER + 127) / 128;
    const int TA = (NAUTHOR + 127) / 128;

    // ---- prep V + merged CSR build (edges shared across both layers) ----
    prep_v_k<<<40, 256>>>(W0, as0, ad0, W1, as1, ad1, V);
    cudaMemsetAsync(DEGS, 0, (size_t)NTOT * sizeof(int));
    hist3_k<<<(ETOT + 255) / 256, 256>>>(dst_c, dst_w, dst_b, DEGS);
    const int NB = (NTOT + 2047) / 2048;  // 245 <= 256
    scanA_k<<<NB, 256>>>(DEGS, OFFS, BS, NTOT);
    scanB_k<<<1, 256>>>(BS, NB);
    scanC_k<<<(NTOT + 255) / 256, 256>>>(OFFS, CURS, BS, NTOT);
    scatter3_k<<<(ETOT + 255) / 256, 256>>>(src_c, dst_c, src_w, dst_w, src_b, dst_b,
                                            CURS, SRCS);

    // ---- input projections ----
    mma_gemm<128, 2, false, false><<<TP, 256, sm128>>>(
        x_paper, Wp, nullptr, bp, XPA, nullptr, NPAPER);
    mma_gemm<128, 1, false, false><<<TA, 256, sm128>>>(
        x_author, Wa, nullptr, ba, XAA, nullptr, NAUTHOR);

    for (int l = 0; l < 2; l++) {
        const float* W  = l ? W1 : W0;
        const float* bb = l ? b1 : b0;
        const float* xp = l ? XPB : XPA;
        const float* xa = l ? XAB : XAA;

        // paper main: HP0 = xp@W[0] (fp16); logits as·W[0]/ad·W[0]/ad·W[1] -> LP1
        mma_gemm<144, 1, true, true><<<TP, 256, sm144>>>(
            xp, W + 0 * HID * HID, V + (l ? 1 : 0) * 2048, nullptr, HP0, LP1, NPAPER);
        // author: HA1 = xa@W[1] (fp16); logits as·W[1] (+ ad·W[2] layer0) -> LA
        mma_gemm<144, 1, true, true><<<TA, 256, sm144>>>(
            xa, W + 1 * HID * HID, V + (l ? 4 : 3) * 2048, nullptr, HA1, LA, NAUTHOR);
        if (!l) {
            // paper 2nd: HP2 = xp@W[2] (fp16); logit as·W[2] -> LP2
            mma_gemm<144, 1, true, true><<<TP, 256, sm144>>>(
                xp, W + 2 * HID * HID, V + 2 * 2048, nullptr, HP2, LP2, NPAPER);
        }

        agg_paper_k<<<(NPAPER * 32 + 255) / 256, 256>>>(
            SRCS, OFFS, DEGS, LP1, HP0, LA, HA1, bb, l ? XPA : XPB, l == 0);
        if (!l)
            agg_author_k<<<(NAUTHOR * 32 + 255) / 256, 256>>>(
                SRCS, OFFS, DEGS, LP2, LA, HP2, bb + 256, XAB);
    }

    // final classifier: [200000,128] @ [128,64] + blin
    mma_gemm<64, 1, false, false><<<TP, 256, sm64>>>(
        XPA, Wlin, nullptr, blin, d_out, nullptr, NPAPER);
}

// round 9
// speedup vs baseline: 4.3264x; 1.2754x over previous
#include <cuda_runtime.h>
#include <cuda_fp16.h>
#include <cstdint>

// ---------------------------------------------------------------------------
// Problem constants
// ---------------------------------------------------------------------------
static constexpr int NPAPER  = 200000;
static constexpr int NAUTHOR = 100000;
static constexpr int HID     = 128;     // 4 heads x 32 channels
static constexpr int ECITES  = 1000000;
static constexpr int EWRITES = 500000;
static constexpr int EWB     = 500000;
static constexpr int ETOT    = ECITES + EWRITES + EWB;   // 2,000,000
static constexpr int NTOT    = 2 * NPAPER + NAUTHOR;     // 500,000

static constexpr size_t SZ_P = (size_t)NPAPER * HID;
static constexpr size_t SZ_A = (size_t)NAUTHOR * HID;

// float scratch
static constexpr size_t O_XPA  = 0;
static constexpr size_t O_XAA  = O_XPA  + SZ_P;
static constexpr size_t O_XPB  = O_XAA  + SZ_A;
static constexpr size_t O_XAB  = O_XPB  + SZ_P;
static constexpr size_t O_LP1  = O_XAB  + SZ_A;                  // paper logits [N,16]
static constexpr size_t O_LP2  = O_LP1  + (size_t)NPAPER * 16;
static constexpr size_t O_LA   = O_LP2  + (size_t)NPAPER * 16;
static constexpr size_t O_V    = O_LA   + (size_t)NAUTHOR * 16;  // 5 x [128][16]
static constexpr size_t SCRATCH_FLOATS = O_V + 5 * 2048;

__device__ float g_scratch[SCRATCH_FLOATS];

// half scratch (gathered feature buffers only)
static constexpr size_t H_HP0 = 0;
static constexpr size_t H_HP2 = H_HP0 + SZ_P;
static constexpr size_t H_HA1 = H_HP2 + SZ_P;
static constexpr size_t SCRATCH_HALF = H_HA1 + SZ_A;

__device__ __half g_hscratch[SCRATCH_HALF];

// int scratch: merged CSR over concatenated node slots
static constexpr size_t I_DEGS = 0;
static constexpr size_t I_OFFS = I_DEGS + NTOT;
static constexpr size_t I_CURS = I_OFFS + NTOT;
static constexpr size_t I_SRCS = I_CURS + NTOT;
static constexpr size_t I_BS   = I_SRCS + ETOT;
static constexpr size_t SCRATCH_INTS = I_BS + 256;

__device__ int g_iscratch[SCRATCH_INTS];

// ---------------------------------------------------------------------------
// fp16 mma + ldmatrix helpers (plain sm_75+/sm_80+ PTX)
// ---------------------------------------------------------------------------
__device__ __forceinline__ void mma_f16(float* c, uint32_t a0, uint32_t a1,
                                        uint32_t a2, uint32_t a3,
                                        uint32_t b0, uint32_t b1) {
    asm volatile(
        "mma.sync.aligned.m16n8k16.row.col.f32.f16.f16.f32 "
        "{%0,%1,%2,%3}, {%4,%5,%6,%7}, {%8,%9}, {%0,%1,%2,%3};"
        : "+f"(c[0]), "+f"(c[1]), "+f"(c[2]), "+f"(c[3])
        : "r"(a0), "r"(a1), "r"(a2), "r"(a3), "r"(b0), "r"(b1));
}

__device__ __forceinline__ void ldm_x4(uint32_t* r, uint32_t addr) {
    asm volatile("ldmatrix.sync.aligned.m8n8.x4.shared.b16 {%0,%1,%2,%3}, [%4];"
                 : "=r"(r[0]), "=r"(r[1]), "=r"(r[2]), "=r"(r[3]) : "r"(addr));
}
__device__ __forceinline__ void ldm_x4t(uint32_t* r, uint32_t addr) {
    asm volatile("ldmatrix.sync.aligned.m8n8.x4.trans.shared.b16 {%0,%1,%2,%3}, [%4];"
                 : "=r"(r[0]), "=r"(r[1]), "=r"(r[2]), "=r"(r[3]) : "r"(addr));
}
__device__ __forceinline__ void ldm_x2t(uint32_t* r, uint32_t addr) {
    asm volatile("ldmatrix.sync.aligned.m8n8.x2.trans.shared.b16 {%0,%1}, [%2];"
                 : "=r"(r[0]), "=r"(r[1]) : "r"(addr));
}

// ---------------------------------------------------------------------------
// Prep: V matrices = W @ att (per head). 5 matrices of [128][16] (see R7).
// ---------------------------------------------------------------------------
__global__ void prep_v_k(const float* __restrict__ W0, const float* __restrict__ as0,
                         const float* __restrict__ ad0, const float* __restrict__ W1,
                         const float* __restrict__ as1, const float* __restrict__ ad1,
                         float* __restrict__ V) {
    int idx = blockIdx.x * blockDim.x + threadIdx.x;
    if (idx >= 5 * 2048) return;
    int m = idx >> 11;
    int r = idx & 2047;
    int k = r >> 4;
    int j = r & 15;
    int h = j & 3;
    int q = j >> 2;

    const float* Wm = nullptr;
    const float* at = nullptr;
    if (m == 0 || m == 1) {
        const float* W  = m ? W1 : W0;
        const float* as_ = m ? as1 : as0;
        const float* ad_ = m ? ad1 : ad0;
        if (q == 0)      { Wm = W;          at = as_; }
        else if (q == 1) { Wm = W;          at = ad_; }
        else if (q == 2) { Wm = W + 16384;  at = ad_ + 128; }
    } else if (m == 2) {
        if (q == 0) { Wm = W0 + 2 * 16384; at = as0 + 256; }
    } else if (m == 3) {
        if (q == 0)      { Wm = W0 + 16384;     at = as0 + 128; }
        else if (q == 1) { Wm = W0 + 2 * 16384; at = ad0 + 256; }
    } else {
        if (q == 0) { Wm = W1 + 16384; at = as1 + 128; }
    }
    float v = 0.f;
    if (Wm) {
#pragma unroll
        for (int c = 0; c < 32; c++)
            v += Wm[k * 128 + h * 32 + c] * at[h * 32 + c];
    }
    V[m * 2048 + k * 16 + j] = v;
}

// ---------------------------------------------------------------------------
// fp16 mma.sync GEMM (m16n8k16 + ldmatrix):
//   C[M,NC] = A[M,KCH*128] @ W[KCH*128, NC] (+bias)
// VEXT: 16 extra B columns from Vx -> Lbuf[row*16 + (col-NC)].
// HALF: C stored as __half. Operands converted fp32->fp16 during staging
// (same 10-bit mantissa as tf32). CTA 128 x N, 8 warps 4x2.
// As[128][136] halves (272B stride: ldmatrix conflict-free),
// Bs[128][N+8] halves.
// ---------------------------------------------------------------------------
template <int N, int KCH, bool VEXT, bool HALF>
__global__ void __launch_bounds__(256, 2)
mma_gemm(const float* __restrict__ A, const float* __restrict__ W,
         const float* __restrict__ Vx, const float* __restrict__ bias,
         void* __restrict__ Cv, float* __restrict__ Lbuf, int M) {
    constexpr int LDA_S = 136;         // halves
    constexpr int LDB_S = N + 8;       // halves
    constexpr int NF    = N / 16;      // 8-col frags per warp
    constexpr int KTOT  = KCH * 128;
    constexpr int NC    = VEXT ? N - 16 : N;

    extern __shared__ __half smh[];
    __half* As = smh;
    __half* Bs = smh + 128 * LDA_S;

    const int tid  = threadIdx.x;
    const int wid  = tid >> 5;
    const int lane = tid & 31;
    const int wm   = wid >> 1;
    const int wn   = wid & 1;
    const int g    = lane >> 2;
    const int tg   = lane & 3;
    const int row0 = blockIdx.x * 128;

    const uint32_t asBase = (uint32_t)__cvta_generic_to_shared(As);
    const uint32_t bsBase = (uint32_t)__cvta_generic_to_shared(Bs);
    // ldmatrix lane-address components
    const int lrow = (lane & 7) + ((lane >> 3) & 1) * 8;  // row within 16
    const int lcol = (lane >> 4) * 8;                     // col block (0/8)

    float acc[2][NF][4];
#pragma unroll
    for (int mf = 0; mf < 2; mf++)
#pragma unroll
        for (int nf = 0; nf < NF; nf++)
#pragma unroll
            for (int j = 0; j < 4; j++) acc[mf][nf][j] = 0.f;

    for (int kc = 0; kc < KCH; kc++) {
        const int k0g = kc * 128;
        // ---- stage A chunk [128 x 128] fp32 -> fp16 ----
#pragma unroll
        for (int i = tid; i < 128 * 32; i += 256) {
            int r = i >> 5, c4 = i & 31;
            int gr = row0 + r;
            float4 v = make_float4(0.f, 0.f, 0.f, 0.f);
            if (gr < M)
                v = *reinterpret_cast<const float4*>(A + (size_t)gr * KTOT + k0g + c4 * 4);
            __half2* dst = reinterpret_cast<__half2*>(As + r * LDA_S + c4 * 4);
            dst[0] = __floats2half2_rn(v.x, v.y);
            dst[1] = __floats2half2_rn(v.z, v.w);
        }
        // ---- stage B chunk [128 x N] ----
#pragma unroll
        for (int i = tid; i < 128 * (N / 4); i += 256) {
            int k = i / (N / 4), n4 = i % (N / 4);
            float4 v;
            if (!VEXT || n4 < NC / 4)
                v = *reinterpret_cast<const float4*>(W + (size_t)(k0g + k) * NC + n4 * 4);
            else
                v = reinterpret_cast<const float4*>(Vx)[k * 4 + (n4 - NC / 4)];
            __half2* dst = reinterpret_cast<__half2*>(Bs + k * LDB_S + n4 * 4);
            dst[0] = __floats2half2_rn(v.x, v.y);
            dst[1] = __floats2half2_rn(v.z, v.w);
        }
        __syncthreads();

        // ---- 8 k-steps of m16n8k16 ----
#pragma unroll
        for (int s = 0; s < 8; s++) {
            const int kk = s * 16;
            // A fragments: 2 x ldmatrix.x4
            uint32_t a[2][4];
#pragma unroll
            for (int mf = 0; mf < 2; mf++) {
                int row = wm * 32 + mf * 16 + lrow;
                ldm_x4(a[mf], asBase + (uint32_t)(row * LDA_S + kk + lcol) * 2);
            }
            // B fragments: x4.trans pairs (+ x2 tail when NF odd)
            uint32_t b[NF][2];
#pragma unroll
            for (int nf2 = 0; nf2 < NF / 2; nf2++) {
                int n0 = wn * (N / 2) + nf2 * 16;
                uint32_t r4[4];
                ldm_x4t(r4, bsBase + (uint32_t)((kk + lrow) * LDB_S + n0 + lcol) * 2);
                b[nf2 * 2][0] = r4[0]; b[nf2 * 2][1] = r4[1];
                b[nf2 * 2 + 1][0] = r4[2]; b[nf2 * 2 + 1][1] = r4[3];
            }
            if (NF & 1) {
                int n0 = wn * (N / 2) + (NF - 1) * 8;
                ldm_x2t(b[NF - 1], bsBase + (uint32_t)((kk + lrow) * LDB_S + n0) * 2);
            }
#pragma unroll
            for (int mf = 0; mf < 2; mf++)
#pragma unroll
                for (int nf = 0; nf < NF; nf++)
                    mma_f16(acc[mf][nf], a[mf][0], a[mf][1], a[mf][2], a[mf][3],
                            b[nf][0], b[nf][1]);
        }
        __syncthreads();
    }

    // ---- epilogue (fragment layout identical to tf32 m16n8k8 D) ----
#pragma unroll
    for (int mf = 0; mf < 2; mf++) {
        const int r0 = row0 + wm * 32 + mf * 16 + g;
        const int r1 = r0 + 8;
#pragma unroll
        for (int nf = 0; nf < NF; nf++) {
            const int col = wn * (N / 2) + nf * 8 + tg * 2;
            float c0 = acc[mf][nf][0], c1 = acc[mf][nf][1];
            float c2 = acc[mf][nf][2], c3 = acc[mf][nf][3];
            if (!VEXT || col < NC) {
                if (bias) {
                    float b0v = bias[col], b1v = bias[col + 1];
                    c0 += b0v; c1 += b1v; c2 += b0v; c3 += b1v;
                }
                if (HALF) {
                    __half* C = (__half*)Cv;
                    if (r0 < M)
                        *reinterpret_cast<__half2*>(C + (size_t)r0 * NC + col) =
                            __floats2half2_rn(c0, c1);
                    if (r1 < M)
                        *reinterpret_cast<__half2*>(C + (size_t)r1 * NC + col) =
                            __floats2half2_rn(c2, c3);
                } else {
                    float* C = (float*)Cv;
                    if (r0 < M)
                        *reinterpret_cast<float2*>(C + (size_t)r0 * NC + col) = make_float2(c0, c1);
                    if (r1 < M)
                        *reinterpret_cast<float2*>(C + (size_t)r1 * NC + col) = make_float2(c2, c3);
                }
            } else {
                const int lc = col - NC;
                if (r0 < M)
                    *reinterpret_cast<float2*>(Lbuf + (size_t)r0 * 16 + lc) = make_float2(c0, c1);
                if (r1 < M)
                    *reinterpret_cast<float2*>(Lbuf + (size_t)r1 * 16 + lc) = make_float2(c2, c3);
            }
        }
    }
}

// ---------------------------------------------------------------------------
// Merged CSR build (one scan over concatenated slot space)
// ---------------------------------------------------------------------------
__global__ void hist3_k(const int* __restrict__ dc, const int* __restrict__ dw,
                        const int* __restrict__ db, int* __restrict__ degs) {
    int e = blockIdx.x * blockDim.x + threadIdx.x;
    if (e >= ETOT) return;
    int slot;
    if (e < ECITES)                slot = dc[e];
    else if (e < ECITES + EWRITES) slot = NPAPER + dw[e - ECITES];
    else                           slot = 2 * NPAPER + db[e - ECITES - EWRITES];
    atomicAdd(&degs[slot], 1);
}

__global__ void scanA_k(const int* __restrict__ deg, int* __restrict__ off,
                        int* __restrict__ bsum, int n) {
    __shared__ int sh[256];
    const int t = threadIdx.x, b = blockIdx.x;
    const int base = b * 2048 + t * 8;
    int v[8], s = 0;
#pragma unroll
    for (int i = 0; i < 8; i++) {
        int idx = base + i;
        v[i] = (idx < n) ? deg[idx] : 0;
        s += v[i];
    }
    sh[t] = s;
    __syncthreads();
    for (int o = 1; o < 256; o <<= 1) {
        int y = (t >= o) ? sh[t - o] : 0;
        __syncthreads();
        sh[t] += y;
        __syncthreads();
    }
    int run = sh[t] - s;
    if (t == 255) bsum[b] = sh[255];
#pragma unroll
    for (int i = 0; i < 8; i++) {
        int idx = base + i;
        if (idx < n) off[idx] = run;
        run += v[i];
    }
}

__global__ void scanB_k(int* __restrict__ bsum, int nb) {
    __shared__ int sh[256];
    int t = threadIdx.x;
    int v = (t < nb) ? bsum[t] : 0;
    sh[t] = v;
    __syncthreads();
    for (int o = 1; o < 256; o <<= 1) {
        int y = (t >= o) ? sh[t - o] : 0;
        __syncthreads();
        sh[t] += y;
        __syncthreads();
    }
    if (t < nb) bsum[t] = sh[t] - v;
}

__global__ void scanC_k(int* __restrict__ off, int* __restrict__ cur,
                        const int* __restrict__ bsum, int n) {
    int i = blockIdx.x * blockDim.x + threadIdx.x;
    if (i >= n) return;
    int v = off[i] + bsum[i >> 11];
    off[i] = v;
    cur[i] = v;
}

__global__ void scatter3_k(const int* __restrict__ sc, const int* __restrict__ dc,
                           const int* __restrict__ sw, const int* __restrict__ dw,
                           const int* __restrict__ sb, const int* __restrict__ db,
                           int* __restrict__ curs, int* __restrict__ srcs) {
    int e = blockIdx.x * blockDim.x + threadIdx.x;
    if (e >= ETOT) return;
    int slot, sv;
    if (e < ECITES)                { slot = dc[e]; sv = sc[e]; }
    else if (e < ECITES + EWRITES) { int i = e - ECITES; slot = NPAPER + dw[i]; sv = sw[i]; }
    else                           { int i = e - ECITES - EWRITES; slot = 2 * NPAPER + db[i]; sv = sb[i]; }
    srcs[atomicAdd(&curs[slot], 1)] = sv;
}

// ---------------------------------------------------------------------------
// Dst-major GAT aggregation; gathered features are fp16.
// ---------------------------------------------------------------------------
__device__ __forceinline__ float lrelu02(float v) { return v > 0.f ? v : 0.2f * v; }

__device__ __forceinline__ float4 gather_h16(const __half* __restrict__ hbuf,
                                             int sidx, int lane) {
    uint2 u = reinterpret_cast<const uint2*>(hbuf + (size_t)sidx * HID)[lane];
    __half2 p0 = *reinterpret_cast<__half2*>(&u.x);
    __half2 p1 = *reinterpret_cast<__half2*>(&u.y);
    float2 f0 = __half22float2(p0);
    float2 f1 = __half22float2(p1);
    return make_float4(f0.x, f0.y, f1.x, f1.y);
}

__global__ void agg_paper_k(
    const int* __restrict__ srcs, const int* __restrict__ offs, const int* __restrict__ degs,
    const float* __restrict__ LP1, const __half* __restrict__ h1,
    const float* __restrict__ LA,  const __half* __restrict__ h2,
    const float* __restrict__ bb, float* __restrict__ out, int act) {
    const int n    = (blockIdx.x * blockDim.x + threadIdx.x) >> 5;
    const int lane = threadIdx.x & 31;
    if (n >= NPAPER) return;
    const int h = lane >> 3;

    float4 a1 = make_float4(0.f, 0.f, 0.f, 0.f);
    float  s1 = 0.f;
    {
        float ad = LP1[(size_t)n * 16 + 4 + h];
        int st = offs[n], d = degs[n];
        for (int j = 0; j < d; j++) {
            int sidx = srcs[st + j];
            float x = __expf(lrelu02(LP1[(size_t)sidx * 16 + h] + ad));
            float4 hv = gather_h16(h1, sidx, lane);
            s1 += x;
            a1.x += x * hv.x; a1.y += x * hv.y; a1.z += x * hv.z; a1.w += x * hv.w;
        }
    }
    float4 a2 = make_float4(0.f, 0.f, 0.f, 0.f);
    float  s2 = 0.f;
    {
        float ad = LP1[(size_t)n * 16 + 8 + h];
        int st = offs[NPAPER + n], d = degs[NPAPER + n];
        for (int j = 0; j < d; j++) {
            int sidx = srcs[st + j];
            float x = __expf(lrelu02(LA[(size_t)sidx * 16 + h] + ad));
            float4 hv = gather_h16(h2, sidx, lane);
            s2 += x;
            a2.x += x * hv.x; a2.y += x * hv.y; a2.z += x * hv.z; a2.w += x * hv.w;
        }
    }
    float i1 = 1.f / (s1 + 1e-16f);
    float i2 = 1.f / (s2 + 1e-16f);
    float4 bv1 = reinterpret_cast<const float4*>(bb)[lane];
    float4 bv2 = reinterpret_cast<const float4*>(bb + 128)[lane];
    float4 o;
    o.x = a1.x * i1 + a2.x * i2 + bv1.x + bv2.x;
    o.y = a1.y * i1 + a2.y * i2 + bv1.y + bv2.y;
    o.z = a1.z * i1 + a2.z * i2 + bv1.z + bv2.z;
    o.w = a1.w * i1 + a2.w * i2 + bv1.w + bv2.w;
    if (act) {
        o.x = o.x > 0.f ? o.x : 0.01f * o.x;
        o.y = o.y > 0.f ? o.y : 0.01f * o.y;
        o.z = o.z > 0.f ? o.z : 0.01f * o.z;
        o.w = o.w > 0.f ? o.w : 0.01f * o.w;
    }
    reinterpret_cast<float4*>(out + (size_t)n * HID)[lane] = o;
}

__global__ void agg_author_k(
    const int* __restrict__ srcs, const int* __restrict__ offs, const int* __restrict__ degs,
    const float* __restrict__ LP2, const float* __restrict__ LA,
    const __half* __restrict__ h1, const float* __restrict__ bb,
    float* __restrict__ out) {
    const int n    = (blockIdx.x * blockDim.x + threadIdx.x) >> 5;
    const int lane = threadIdx.x & 31;
    if (n >= NAUTHOR) return;
    const int h = lane >> 3;

    float4 a1 = make_float4(0.f, 0.f, 0.f, 0.f);
    float  s1 = 0.f;
    float ad = LA[(size_t)n * 16 + 4 + h];
    int st = offs[2 * NPAPER + n], d = degs[2 * NPAPER + n];
    for (int j = 0; j < d; j++) {
        int sidx = srcs[st + j];
        float x = __expf(lrelu02(LP2[(size_t)sidx * 16 + h] + ad));
        float4 hv = gather_h16(h1, sidx, lane);
        s1 += x;
        a1.x += x * hv.x; a1.y += x * hv.y; a1.z += x * hv.z; a1.w += x * hv.w;
    }
    float i1 = 1.f / (s1 + 1e-16f);
    float4 bv = reinterpret_cast<const float4*>(bb)[lane];
    float4 o;
    o.x = a1.x * i1 + bv.x;
    o.y = a1.y * i1 + bv.y;
    o.z = a1.z * i1 + bv.z;
    o.w = a1.w * i1 + bv.w;
    o.x = o.x > 0.f ? o.x : 0.01f * o.x;
    o.y = o.y > 0.f ? o.y : 0.01f * o.y;
    o.z = o.z > 0.f ? o.z : 0.01f * o.z;
    o.w = o.w > 0.f ? o.w : 0.01f * o.w;
    reinterpret_cast<float4*>(out + (size_t)n * HID)[lane] = o;
}

// ---------------------------------------------------------------------------
// Host orchestration
// ---------------------------------------------------------------------------
static inline int gemm_smem(int N) { return (128 * 136 + 128 * (N + 8)) * 2; }

extern "C" void kernel_launch(void* const* d_in, const int* in_sizes, int n_in,
                              void* d_out, int out_size) {
    const float* x_paper  = (const float*)d_in[0];
    const float* x_author = (const float*)d_in[1];
    const float* Wp   = (const float*)d_in[2];
    const float* bp   = (const float*)d_in[3];
    const float* Wa   = (const float*)d_in[4];
    const float* ba   = (const float*)d_in[5];
    const float* W0   = (const float*)d_in[6];
    const float* as0  = (const float*)d_in[7];
    const float* ad0  = (const float*)d_in[8];
    const float* b0   = (const float*)d_in[9];
    const float* W1   = (const float*)d_in[10];
    const float* as1  = (const float*)d_in[11];
    const float* ad1  = (const float*)d_in[12];
    const float* b1   = (const float*)d_in[13];
    const float* Wlin = (const float*)d_in[14];
    const float* blin = (const float*)d_in[15];
    const int* src_c  = (const int*)d_in[16];
    const int* dst_c  = (const int*)d_in[17];
    const int* src_w  = (const int*)d_in[18];
    const int* dst_w  = (const int*)d_in[19];
    const int* src_b  = (const int*)d_in[20];
    const int* dst_b  = (const int*)d_in[21];

    float* S = nullptr;
    cudaGetSymbolAddress((void**)&S, g_scratch);
    __half* Hh = nullptr;
    cudaGetSymbolAddress((void**)&Hh, g_hscratch);
    int* I = nullptr;
    cudaGetSymbolAddress((void**)&I, g_iscratch);

    float*  XPA = S + O_XPA;
    float*  XAA = S + O_XAA;
    float*  XPB = S + O_XPB;
    float*  XAB = S + O_XAB;
    float*  LP1 = S + O_LP1;
    float*  LP2 = S + O_LP2;
    float*  LA  = S + O_LA;
    float*  V   = S + O_V;
    __half* HP0 = Hh + H_HP0;
    __half* HP2 = Hh + H_HP2;
    __half* HA1 = Hh + H_HA1;

    int* DEGS = I + I_DEGS;
    int* OFFS = I + I_OFFS;
    int* CURS = I + I_CURS;
    int* SRCS = I + I_SRCS;
    int* BS   = I + I_BS;

    const int sm144 = gemm_smem(144);
    const int sm128 = gemm_smem(128);
    const int sm64  = gemm_smem(64);
    cudaFuncSetAttribute(mma_gemm<128, 2, false, false>, cudaFuncAttributeMaxDynamicSharedMemorySize, sm128);
    cudaFuncSetAttribute(mma_gemm<128, 1, false, false>, cudaFuncAttributeMaxDynamicSharedMemorySize, sm128);
    cudaFuncSetAttribute(mma_gemm<144, 1, true,  true >, cudaFuncAttributeMaxDynamicSharedMemorySize, sm144);
    cudaFuncSetAttribute(mma_gemm<64,  1, false, false>, cudaFuncAttributeMaxDynamicSharedMemorySize, sm64);

    const int TP = (NPAPER + 127) / 128;
    const int TA = (NAUTHOR + 127) / 128;

    // ---- prep V + merged CSR build ----
    prep_v_k<<<40, 256>>>(W0, as0, ad0, W1, as1, ad1, V);
    cudaMemsetAsync(DEGS, 0, (size_t)NTOT * sizeof(int));
    hist3_k<<<(ETOT + 255) / 256, 256>>>(dst_c, dst_w, dst_b, DEGS);
    const int NB = (NTOT + 2047) / 2048;  // 245 <= 256
    scanA_k<<<NB, 256>>>(DEGS, OFFS, BS, NTOT);
    scanB_k<<<1, 256>>>(BS, NB);
    scanC_k<<<(NTOT + 255) / 256, 256>>>(OFFS, CURS, BS, NTOT);
    scatter3_k<<<(ETOT + 255) / 256, 256>>>(src_c, dst_c, src_w, dst_w, src_b, dst_b,
                                            CURS, SRCS);

    // ---- input projections ----
    mma_gemm<128, 2, false, false><<<TP, 256, sm128>>>(
        x_paper, Wp, nullptr, bp, XPA, nullptr, NPAPER);
    mma_gemm<128, 1, false, false><<<TA, 256, sm128>>>(
        x_author, Wa, nullptr, ba, XAA, nullptr, NAUTHOR);

    for (int l = 0; l < 2; l++) {
        const float* W  = l ? W1 : W0;
        const float* bb = l ? b1 : b0;
        const float* xp = l ? XPB : XPA;
        const float* xa = l ? XAB : XAA;

        mma_gemm<144, 1, true, true><<<TP, 256, sm144>>>(
            xp, W + 0 * HID * HID, V + (l ? 1 : 0) * 2048, nullptr, HP0, LP1, NPAPER);
        mma_gemm<144, 1, true, true><<<TA, 256, sm144>>>(
            xa, W + 1 * HID * HID, V + (l ? 4 : 3) * 2048, nullptr, HA1, LA, NAUTHOR);
        if (!l) {
            mma_gemm<144, 1, true, true><<<TP, 256, sm144>>>(
                xp, W + 2 * HID * HID, V + 2 * 2048, nullptr, HP2, LP2, NPAPER);
        }

        agg_paper_k<<<(NPAPER * 32 + 255) / 256, 256>>>(
            SRCS, OFFS, DEGS, LP1, HP0, LA, HA1, bb, l ? XPA : XPB, l == 0);
        if (!l)
            agg_author_k<<<(NAUTHOR * 32 + 255) / 256, 256>>>(
                SRCS, OFFS, DEGS, LP2, LA, HP2, bb + 256, XAB);
    }

    // final classifier: [200000,128] @ [128,64] + blin
    mma_gemm<64, 1, false, false><<<TP, 256, sm64>>>(
        XPA, Wlin, nullptr, blin, d_out, nullptr, NPAPER);
}

// round 10
// speedup vs baseline: 4.6262x; 1.0693x over previous
#include <cuda_runtime.h>
#include <cuda_fp16.h>
#include <cstdint>

// ---------------------------------------------------------------------------
// Problem constants
// ---------------------------------------------------------------------------
static constexpr int NPAPER  = 200000;
static constexpr int NAUTHOR = 100000;
static constexpr int HID     = 128;     // 4 heads x 32 channels
static constexpr int ECITES  = 1000000;
static constexpr int EWRITES = 500000;
static constexpr int EWB     = 500000;
static constexpr int ETOT    = ECITES + EWRITES + EWB;   // 2,000,000
static constexpr int NTOT    = 2 * NPAPER + NAUTHOR;     // 500,000

static constexpr size_t SZ_P = (size_t)NPAPER * HID;
static constexpr size_t SZ_A = (size_t)NAUTHOR * HID;

// float scratch (logits + V only)
static constexpr size_t O_LP1  = 0;                              // paper logits [N,16]
static constexpr size_t O_LP2  = O_LP1 + (size_t)NPAPER * 16;
static constexpr size_t O_LA   = O_LP2 + (size_t)NPAPER * 16;
static constexpr size_t O_V    = O_LA  + (size_t)NAUTHOR * 16;   // 5 x [128][16]
static constexpr size_t SCRATCH_FLOATS = O_V + 5 * 2048;

__device__ float g_scratch[SCRATCH_FLOATS];

// half scratch: activations + gathered feature buffers
static constexpr size_t H_XPA = 0;
static constexpr size_t H_XAA = H_XPA + SZ_P;
static constexpr size_t H_XPB = H_XAA + SZ_A;
static constexpr size_t H_XAB = H_XPB + SZ_P;
static constexpr size_t H_HP0 = H_XAB + SZ_A;
static constexpr size_t H_HP2 = H_HP0 + SZ_P;
static constexpr size_t H_HA1 = H_HP2 + SZ_P;
static constexpr size_t SCRATCH_HALF = H_HA1 + SZ_A;

__device__ __half g_hscratch[SCRATCH_HALF];

// int scratch: merged CSR over concatenated node slots
static constexpr size_t I_DEGS = 0;
static constexpr size_t I_OFFS = I_DEGS + NTOT;
static constexpr size_t I_CURS = I_OFFS + NTOT;
static constexpr size_t I_SRCS = I_CURS + NTOT;
static constexpr size_t I_BS   = I_SRCS + ETOT;
static constexpr size_t SCRATCH_INTS = I_BS + 256;

__device__ int g_iscratch[SCRATCH_INTS];

// ---------------------------------------------------------------------------
// fp16 mma + ldmatrix helpers (plain sm_75+/sm_80+ PTX)
// ---------------------------------------------------------------------------
__device__ __forceinline__ void mma_f16(float* c, uint32_t a0, uint32_t a1,
                                        uint32_t a2, uint32_t a3,
                                        uint32_t b0, uint32_t b1) {
    asm volatile(
        "mma.sync.aligned.m16n8k16.row.col.f32.f16.f16.f32 "
        "{%0,%1,%2,%3}, {%4,%5,%6,%7}, {%8,%9}, {%0,%1,%2,%3};"
        : "+f"(c[0]), "+f"(c[1]), "+f"(c[2]), "+f"(c[3])
        : "r"(a0), "r"(a1), "r"(a2), "r"(a3), "r"(b0), "r"(b1));
}

__device__ __forceinline__ void ldm_x4(uint32_t* r, uint32_t addr) {
    asm volatile("ldmatrix.sync.aligned.m8n8.x4.shared.b16 {%0,%1,%2,%3}, [%4];"
                 : "=r"(r[0]), "=r"(r[1]), "=r"(r[2]), "=r"(r[3]) : "r"(addr));
}
__device__ __forceinline__ void ldm_x4t(uint32_t* r, uint32_t addr) {
    asm volatile("ldmatrix.sync.aligned.m8n8.x4.trans.shared.b16 {%0,%1,%2,%3}, [%4];"
                 : "=r"(r[0]), "=r"(r[1]), "=r"(r[2]), "=r"(r[3]) : "r"(addr));
}
__device__ __forceinline__ void ldm_x2t(uint32_t* r, uint32_t addr) {
    asm volatile("ldmatrix.sync.aligned.m8n8.x2.trans.shared.b16 {%0,%1}, [%2];"
                 : "=r"(r[0]), "=r"(r[1]) : "r"(addr));
}

// ---------------------------------------------------------------------------
// Prep: V matrices = W @ att (per head). 5 matrices of [128][16] (see R7).
// ---------------------------------------------------------------------------
__global__ void prep_v_k(const float* __restrict__ W0, const float* __restrict__ as0,
                         const float* __restrict__ ad0, const float* __restrict__ W1,
                         const float* __restrict__ as1, const float* __restrict__ ad1,
                         float* __restrict__ V) {
    int idx = blockIdx.x * blockDim.x + threadIdx.x;
    if (idx >= 5 * 2048) return;
    int m = idx >> 11;
    int r = idx & 2047;
    int k = r >> 4;
    int j = r & 15;
    int h = j & 3;
    int q = j >> 2;

    const float* Wm = nullptr;
    const float* at = nullptr;
    if (m == 0 || m == 1) {
        const float* W  = m ? W1 : W0;
        const float* as_ = m ? as1 : as0;
        const float* ad_ = m ? ad1 : ad0;
        if (q == 0)      { Wm = W;          at = as_; }
        else if (q == 1) { Wm = W;          at = ad_; }
        else if (q == 2) { Wm = W + 16384;  at = ad_ + 128; }
    } else if (m == 2) {
        if (q == 0) { Wm = W0 + 2 * 16384; at = as0 + 256; }
    } else if (m == 3) {
        if (q == 0)      { Wm = W0 + 16384;     at = as0 + 128; }
        else if (q == 1) { Wm = W0 + 2 * 16384; at = ad0 + 256; }
    } else {
        if (q == 0) { Wm = W1 + 16384; at = as1 + 128; }
    }
    float v = 0.f;
    if (Wm) {
#pragma unroll
        for (int c = 0; c < 32; c++)
            v += Wm[k * 128 + h * 32 + c] * at[h * 32 + c];
    }
    V[m * 2048 + k * 16 + j] = v;
}

// ---------------------------------------------------------------------------
// fp16 mma.sync GEMM (m16n8k16 + ldmatrix):
//   C[M,NC] = A[M,KCH*128] @ W[KCH*128, NC] (+bias)
// AHALF: A is __half (direct 16B staging, no cvt). Else fp32 -> fp16 staging.
// VEXT: 16 extra B columns from Vx -> Lbuf[row*16 + (col-NC)].
// HALF: C stored as __half. CTA 128 x N, 8 warps 4x2.
// ---------------------------------------------------------------------------
template <int N, int KCH, bool VEXT, bool HALF, bool AHALF>
__global__ void __launch_bounds__(256, 2)
mma_gemm(const void* __restrict__ Av, const float* __restrict__ W,
         const float* __restrict__ Vx, const float* __restrict__ bias,
         void* __restrict__ Cv, float* __restrict__ Lbuf, int M) {
    constexpr int LDA_S = 136;         // halves
    constexpr int LDB_S = N + 8;       // halves
    constexpr int NF    = N / 16;
    constexpr int KTOT  = KCH * 128;
    constexpr int NC    = VEXT ? N - 16 : N;

    extern __shared__ __half smh[];
    __half* As = smh;
    __half* Bs = smh + 128 * LDA_S;

    const int tid  = threadIdx.x;
    const int wid  = tid >> 5;
    const int lane = tid & 31;
    const int wm   = wid >> 1;
    const int wn   = wid & 1;
    const int g    = lane >> 2;
    const int tg   = lane & 3;
    const int row0 = blockIdx.x * 128;

    const uint32_t asBase = (uint32_t)__cvta_generic_to_shared(As);
    const uint32_t bsBase = (uint32_t)__cvta_generic_to_shared(Bs);
    const int lrow = (lane & 7) + ((lane >> 3) & 1) * 8;
    const int lcol = (lane >> 4) * 8;

    float acc[2][NF][4];
#pragma unroll
    for (int mf = 0; mf < 2; mf++)
#pragma unroll
        for (int nf = 0; nf < NF; nf++)
#pragma unroll
            for (int j = 0; j < 4; j++) acc[mf][nf][j] = 0.f;

    for (int kc = 0; kc < KCH; kc++) {
        const int k0g = kc * 128;
        // ---- stage A chunk [128 x 128] ----
        if (AHALF) {
            const __half* A = (const __half*)Av;
#pragma unroll
            for (int i = tid; i < 128 * 16; i += 256) {
                int r = i >> 4, c8 = i & 15;
                int gr = row0 + r;
                uint4 v = make_uint4(0u, 0u, 0u, 0u);
                if (gr < M)
                    v = *reinterpret_cast<const uint4*>(A + (size_t)gr * KTOT + k0g + c8 * 8);
                *reinterpret_cast<uint4*>(As + r * LDA_S + c8 * 8) = v;
            }
        } else {
            const float* A = (const float*)Av;
#pragma unroll
            for (int i = tid; i < 128 * 32; i += 256) {
                int r = i >> 5, c4 = i & 31;
                int gr = row0 + r;
                float4 v = make_float4(0.f, 0.f, 0.f, 0.f);
                if (gr < M)
                    v = *reinterpret_cast<const float4*>(A + (size_t)gr * KTOT + k0g + c4 * 4);
                __half2* dst = reinterpret_cast<__half2*>(As + r * LDA_S + c4 * 4);
                dst[0] = __floats2half2_rn(v.x, v.y);
                dst[1] = __floats2half2_rn(v.z, v.w);
            }
        }
        // ---- stage B chunk [128 x N] fp32 -> fp16 ----
#pragma unroll
        for (int i = tid; i < 128 * (N / 4); i += 256) {
            int k = i / (N / 4), n4 = i % (N / 4);
            float4 v;
            if (!VEXT || n4 < NC / 4)
                v = *reinterpret_cast<const float4*>(W + (size_t)(k0g + k) * NC + n4 * 4);
            else
                v = reinterpret_cast<const float4*>(Vx)[k * 4 + (n4 - NC / 4)];
            __half2* dst = reinterpret_cast<__half2*>(Bs + k * LDB_S + n4 * 4);
            dst[0] = __floats2half2_rn(v.x, v.y);
            dst[1] = __floats2half2_rn(v.z, v.w);
        }
        __syncthreads();

        // ---- 8 k-steps of m16n8k16 ----
#pragma unroll
        for (int s = 0; s < 8; s++) {
            const int kk = s * 16;
            uint32_t a[2][4];
#pragma unroll
            for (int mf = 0; mf < 2; mf++) {
                int row = wm * 32 + mf * 16 + lrow;
                ldm_x4(a[mf], asBase + (uint32_t)(row * LDA_S + kk + lcol) * 2);
            }
            uint32_t b[NF][2];
#pragma unroll
            for (int nf2 = 0; nf2 < NF / 2; nf2++) {
                int n0 = wn * (N / 2) + nf2 * 16;
                uint32_t r4[4];
                ldm_x4t(r4, bsBase + (uint32_t)((kk + lrow) * LDB_S + n0 + lcol) * 2);
                b[nf2 * 2][0] = r4[0]; b[nf2 * 2][1] = r4[1];
                b[nf2 * 2 + 1][0] = r4[2]; b[nf2 * 2 + 1][1] = r4[3];
            }
            if (NF & 1) {
                int n0 = wn * (N / 2) + (NF - 1) * 8;
                ldm_x2t(b[NF - 1], bsBase + (uint32_t)((kk + lrow) * LDB_S + n0) * 2);
            }
#pragma unroll
            for (int mf = 0; mf < 2; mf++)
#pragma unroll
                for (int nf = 0; nf < NF; nf++)
                    mma_f16(acc[mf][nf], a[mf][0], a[mf][1], a[mf][2], a[mf][3],
                            b[nf][0], b[nf][1]);
        }
        __syncthreads();
    }

    // ---- epilogue ----
#pragma unroll
    for (int mf = 0; mf < 2; mf++) {
        const int r0 = row0 + wm * 32 + mf * 16 + g;
        const int r1 = r0 + 8;
#pragma unroll
        for (int nf = 0; nf < NF; nf++) {
            const int col = wn * (N / 2) + nf * 8 + tg * 2;
            float c0 = acc[mf][nf][0], c1 = acc[mf][nf][1];
            float c2 = acc[mf][nf][2], c3 = acc[mf][nf][3];
            if (!VEXT || col < NC) {
                if (bias) {
                    float b0v = bias[col], b1v = bias[col + 1];
                    c0 += b0v; c1 += b1v; c2 += b0v; c3 += b1v;
                }
                if (HALF) {
                    __half* C = (__half*)Cv;
                    if (r0 < M)
                        *reinterpret_cast<__half2*>(C + (size_t)r0 * NC + col) =
                            __floats2half2_rn(c0, c1);
                    if (r1 < M)
                        *reinterpret_cast<__half2*>(C + (size_t)r1 * NC + col) =
                            __floats2half2_rn(c2, c3);
                } else {
                    float* C = (float*)Cv;
                    if (r0 < M)
                        *reinterpret_cast<float2*>(C + (size_t)r0 * NC + col) = make_float2(c0, c1);
                    if (r1 < M)
                        *reinterpret_cast<float2*>(C + (size_t)r1 * NC + col) = make_float2(c2, c3);
                }
            } else {
                const int lc = col - NC;
                if (r0 < M)
                    *reinterpret_cast<float2*>(Lbuf + (size_t)r0 * 16 + lc) = make_float2(c0, c1);
                if (r1 < M)
                    *reinterpret_cast<float2*>(Lbuf + (size_t)r1 * 16 + lc) = make_float2(c2, c3);
            }
        }
    }
}

// ---------------------------------------------------------------------------
// Merged CSR build (one scan over concatenated slot space)
// ---------------------------------------------------------------------------
__global__ void hist3_k(const int* __restrict__ dc, const int* __restrict__ dw,
                        const int* __restrict__ db, int* __restrict__ degs) {
    int e = blockIdx.x * blockDim.x + threadIdx.x;
    if (e >= ETOT) return;
    int slot;
    if (e < ECITES)                slot = dc[e];
    else if (e < ECITES + EWRITES) slot = NPAPER + dw[e - ECITES];
    else                           slot = 2 * NPAPER + db[e - ECITES - EWRITES];
    atomicAdd(&degs[slot], 1);
}

__global__ void scanA_k(const int* __restrict__ deg, int* __restrict__ off,
                        int* __restrict__ bsum, int n) {
    __shared__ int sh[256];
    const int t = threadIdx.x, b = blockIdx.x;
    const int base = b * 2048 + t * 8;
    int v[8], s = 0;
#pragma unroll
    for (int i = 0; i < 8; i++) {
        int idx = base + i;
        v[i] = (idx < n) ? deg[idx] : 0;
        s += v[i];
    }
    sh[t] = s;
    __syncthreads();
    for (int o = 1; o < 256; o <<= 1) {
        int y = (t >= o) ? sh[t - o] : 0;
        __syncthreads();
        sh[t] += y;
        __syncthreads();
    }
    int run = sh[t] - s;
    if (t == 255) bsum[b] = sh[255];
#pragma unroll
    for (int i = 0; i < 8; i++) {
        int idx = base + i;
        if (idx < n) off[idx] = run;
        run += v[i];
    }
}

__global__ void scanB_k(int* __restrict__ bsum, int nb) {
    __shared__ int sh[256];
    int t = threadIdx.x;
    int v = (t < nb) ? bsum[t] : 0;
    sh[t] = v;
    __syncthreads();
    for (int o = 1; o < 256; o <<= 1) {
        int y = (t >= o) ? sh[t - o] : 0;
        __syncthreads();
        sh[t] += y;
        __syncthreads();
    }
    if (t < nb) bsum[t] = sh[t] - v;
}

__global__ void scanC_k(int* __restrict__ off, int* __restrict__ cur,
                        const int* __restrict__ bsum, int n) {
    int i = blockIdx.x * blockDim.x + threadIdx.x;
    if (i >= n) return;
    int v = off[i] + bsum[i >> 11];
    off[i] = v;
    cur[i] = v;
}

__global__ void scatter3_k(const int* __restrict__ sc, const int* __restrict__ dc,
                           const int* __restrict__ sw, const int* __restrict__ dw,
                           const int* __restrict__ sb, const int* __restrict__ db,
                           int* __restrict__ curs, int* __restrict__ srcs) {
    int e = blockIdx.x * blockDim.x + threadIdx.x;
    if (e >= ETOT) return;
    int slot, sv;
    if (e < ECITES)                { slot = dc[e]; sv = sc[e]; }
    else if (e < ECITES + EWRITES) { int i = e - ECITES; slot = NPAPER + dw[i]; sv = sw[i]; }
    else                           { int i = e - ECITES - EWRITES; slot = 2 * NPAPER + db[i]; sv = sb[i]; }
    srcs[atomicAdd(&curs[slot], 1)] = sv;
}

// ---------------------------------------------------------------------------
// Dst-major GAT aggregation; fp16 gathered features, fp16 output.
// ---------------------------------------------------------------------------
__device__ __forceinline__ float lrelu02(float v) { return v > 0.f ? v : 0.2f * v; }

__device__ __forceinline__ float4 gather_h16(const __half* __restrict__ hbuf,
                                             int sidx, int lane) {
    uint2 u = reinterpret_cast<const uint2*>(hbuf + (size_t)sidx * HID)[lane];
    __half2 p0 = *reinterpret_cast<__half2*>(&u.x);
    __half2 p1 = *reinterpret_cast<__half2*>(&u.y);
    float2 f0 = __half22float2(p0);
    float2 f1 = __half22float2(p1);
    return make_float4(f0.x, f0.y, f1.x, f1.y);
}

__device__ __forceinline__ void store_h16(__half* __restrict__ out, int n, int lane,
                                          float4 o) {
    uint2 u;
    __half2 p0 = __floats2half2_rn(o.x, o.y);
    __half2 p1 = __floats2half2_rn(o.z, o.w);
    u.x = *reinterpret_cast<uint32_t*>(&p0);
    u.y = *reinterpret_cast<uint32_t*>(&p1);
    reinterpret_cast<uint2*>(out + (size_t)n * HID)[lane] = u;
}

__global__ void agg_paper_k(
    const int* __restrict__ srcs, const int* __restrict__ offs, const int* __restrict__ degs,
    const float* __restrict__ LP1, const __half* __restrict__ h1,
    const float* __restrict__ LA,  const __half* __restrict__ h2,
    const float* __restrict__ bb, __half* __restrict__ out, int act) {
    const int n    = (blockIdx.x * blockDim.x + threadIdx.x) >> 5;
    const int lane = threadIdx.x & 31;
    if (n >= NPAPER) return;
    const int h = lane >> 3;

    float4 a1 = make_float4(0.f, 0.f, 0.f, 0.f);
    float  s1 = 0.f;
    {
        float ad = LP1[(size_t)n * 16 + 4 + h];
        int st = offs[n], d = degs[n];
        for (int j = 0; j < d; j++) {
            int sidx = srcs[st + j];
            float x = __expf(lrelu02(LP1[(size_t)sidx * 16 + h] + ad));
            float4 hv = gather_h16(h1, sidx, lane);
            s1 += x;
            a1.x += x * hv.x; a1.y += x * hv.y; a1.z += x * hv.z; a1.w += x * hv.w;
        }
    }
    float4 a2 = make_float4(0.f, 0.f, 0.f, 0.f);
    float  s2 = 0.f;
    {
        float ad = LP1[(size_t)n * 16 + 8 + h];
        int st = offs[NPAPER + n], d = degs[NPAPER + n];
        for (int j = 0; j < d; j++) {
            int sidx = srcs[st + j];
            float x = __expf(lrelu02(LA[(size_t)sidx * 16 + h] + ad));
            float4 hv = gather_h16(h2, sidx, lane);
            s2 += x;
            a2.x += x * hv.x; a2.y += x * hv.y; a2.z += x * hv.z; a2.w += x * hv.w;
        }
    }
    float i1 = 1.f / (s1 + 1e-16f);
    float i2 = 1.f / (s2 + 1e-16f);
    float4 bv1 = reinterpret_cast<const float4*>(bb)[lane];
    float4 bv2 = reinterpret_cast<const float4*>(bb + 128)[lane];
    float4 o;
    o.x = a1.x * i1 + a2.x * i2 + bv1.x + bv2.x;
    o.y = a1.y * i1 + a2.y * i2 + bv1.y + bv2.y;
    o.z = a1.z * i1 + a2.z * i2 + bv1.z + bv2.z;
    o.w = a1.w * i1 + a2.w * i2 + bv1.w + bv2.w;
    if (act) {
        o.x = o.x > 0.f ? o.x : 0.01f * o.x;
        o.y = o.y > 0.f ? o.y : 0.01f * o.y;
        o.z = o.z > 0.f ? o.z : 0.01f * o.z;
        o.w = o.w > 0.f ? o.w : 0.01f * o.w;
    }
    store_h16(out, n, lane, o);
}

__global__ void agg_author_k(
    const int* __restrict__ srcs, const int* __restrict__ offs, const int* __restrict__ degs,
    const float* __restrict__ LP2, const float* __restrict__ LA,
    const __half* __restrict__ h1, const float* __restrict__ bb,
    __half* __restrict__ out) {
    const int n    = (blockIdx.x * blockDim.x + threadIdx.x) >> 5;
    const int lane = threadIdx.x & 31;
    if (n >= NAUTHOR) return;
    const int h = lane >> 3;

    float4 a1 = make_float4(0.f, 0.f, 0.f, 0.f);
    float  s1 = 0.f;
    float ad = LA[(size_t)n * 16 + 4 + h];
    int st = offs[2 * NPAPER + n], d = degs[2 * NPAPER + n];
    for (int j = 0; j < d; j++) {
        int sidx = srcs[st + j];
        float x = __expf(lrelu02(LP2[(size_t)sidx * 16 + h] + ad));
        float4 hv = gather_h16(h1, sidx, lane);
        s1 += x;
        a1.x += x * hv.x; a1.y += x * hv.y; a1.z += x * hv.z; a1.w += x * hv.w;
    }
    float i1 = 1.f / (s1 + 1e-16f);
    float4 bv = reinterpret_cast<const float4*>(bb)[lane];
    float4 o;
    o.x = a1.x * i1 + bv.x;
    o.y = a1.y * i1 + bv.y;
    o.z = a1.z * i1 + bv.z;
    o.w = a1.w * i1 + bv.w;
    o.x = o.x > 0.f ? o.x : 0.01f * o.x;
    o.y = o.y > 0.f ? o.y : 0.01f * o.y;
    o.z = o.z > 0.f ? o.z : 0.01f * o.z;
    o.w = o.w > 0.f ? o.w : 0.01f * o.w;
    store_h16(out, n, lane, o);
}

// ---------------------------------------------------------------------------
// Host orchestration
// ---------------------------------------------------------------------------
static inline int gemm_smem(int N) { return (128 * 136 + 128 * (N + 8)) * 2; }

extern "C" void kernel_launch(void* const* d_in, const int* in_sizes, int n_in,
                              void* d_out, int out_size) {
    const float* x_paper  = (const float*)d_in[0];
    const float* x_author = (const float*)d_in[1];
    const float* Wp   = (const float*)d_in[2];
    const float* bp   = (const float*)d_in[3];
    const float* Wa   = (const float*)d_in[4];
    const float* ba   = (const float*)d_in[5];
    const float* W0   = (const float*)d_in[6];
    const float* as0  = (const float*)d_in[7];
    const float* ad0  = (const float*)d_in[8];
    const float* b0   = (const float*)d_in[9];
    const float* W1   = (const float*)d_in[10];
    const float* as1  = (const float*)d_in[11];
    const float* ad1  = (const float*)d_in[12];
    const float* b1   = (const float*)d_in[13];
    const float* Wlin = (const float*)d_in[14];
    const float* blin = (const float*)d_in[15];
    const int* src_c  = (const int*)d_in[16];
    const int* dst_c  = (const int*)d_in[17];
    const int* src_w  = (const int*)d_in[18];
    const int* dst_w  = (const int*)d_in[19];
    const int* src_b  = (const int*)d_in[20];
    const int* dst_b  = (const int*)d_in[21];

    float* S = nullptr;
    cudaGetSymbolAddress((void**)&S, g_scratch);
    __half* Hh = nullptr;
    cudaGetSymbolAddress((void**)&Hh, g_hscratch);
    int* I = nullptr;
    cudaGetSymbolAddress((void**)&I, g_iscratch);

    float*  LP1 = S + O_LP1;
    float*  LP2 = S + O_LP2;
    float*  LA  = S + O_LA;
    float*  V   = S + O_V;
    __half* XPA = Hh + H_XPA;
    __half* XAA = Hh + H_XAA;
    __half* XPB = Hh + H_XPB;
    __half* XAB = Hh + H_XAB;
    __half* HP0 = Hh + H_HP0;
    __half* HP2 = Hh + H_HP2;
    __half* HA1 = Hh + H_HA1;

    int* DEGS = I + I_DEGS;
    int* OFFS = I + I_OFFS;
    int* CURS = I + I_CURS;
    int* SRCS = I + I_SRCS;
    int* BS   = I + I_BS;

    const int sm144 = gemm_smem(144);
    const int sm128 = gemm_smem(128);
    const int sm64  = gemm_smem(64);
    cudaFuncSetAttribute(mma_gemm<128, 2, false, true,  false>, cudaFuncAttributeMaxDynamicSharedMemorySize, sm128);
    cudaFuncSetAttribute(mma_gemm<128, 1, false, true,  false>, cudaFuncAttributeMaxDynamicSharedMemorySize, sm128);
    cudaFuncSetAttribute(mma_gemm<144, 1, true,  true,  true >, cudaFuncAttributeMaxDynamicSharedMemorySize, sm144);
    cudaFuncSetAttribute(mma_gemm<64,  1, false, false, true >, cudaFuncAttributeMaxDynamicSharedMemorySize, sm64);

    const int TP = (NPAPER + 127) / 128;
    const int TA = (NAUTHOR + 127) / 128;

    // ---- prep V + merged CSR build ----
    prep_v_k<<<40, 256>>>(W0, as0, ad0, W1, as1, ad1, V);
    cudaMemsetAsync(DEGS, 0, (size_t)NTOT * sizeof(int));
    hist3_k<<<(ETOT + 255) / 256, 256>>>(dst_c, dst_w, dst_b, DEGS);
    const int NB = (NTOT + 2047) / 2048;  // 245 <= 256
    scanA_k<<<NB, 256>>>(DEGS, OFFS, BS, NTOT);
    scanB_k<<<1, 256>>>(BS, NB);
    scanC_k<<<(NTOT + 255) / 256, 256>>>(OFFS, CURS, BS, NTOT);
    scatter3_k<<<(ETOT + 255) / 256, 256>>>(src_c, dst_c, src_w, dst_w, src_b, dst_b,
                                            CURS, SRCS);

    // ---- input projections (fp32 A in, fp16 X out) ----
    mma_gemm<128, 2, false, true, false><<<TP, 256, sm128>>>(
        x_paper, Wp, nullptr, bp, XPA, nullptr, NPAPER);
    mma_gemm<128, 1, false, true, false><<<TA, 256, sm128>>>(
        x_author, Wa, nullptr, ba, XAA, nullptr, NAUTHOR);

    for (int l = 0; l < 2; l++) {
        const float* W  = l ? W1 : W0;
        const float* bb = l ? b1 : b0;
        const __half* xp = l ? XPB : XPA;
        const __half* xa = l ? XAB : XAA;

        mma_gemm<144, 1, true, true, true><<<TP, 256, sm144>>>(
            xp, W + 0 * HID * HID, V + (l ? 1 : 0) * 2048, nullptr, HP0, LP1, NPAPER);
        mma_gemm<144, 1, true, true, true><<<TA, 256, sm144>>>(
            xa, W + 1 * HID * HID, V + (l ? 4 : 3) * 2048, nullptr, HA1, LA, NAUTHOR);
        if (!l) {
            mma_gemm<144, 1, true, true, true><<<TP, 256, sm144>>>(
                xp, W + 2 * HID * HID, V + 2 * 2048, nullptr, HP2, LP2, NPAPER);
        }

        agg_paper_k<<<(NPAPER * 32 + 255) / 256, 256>>>(
            SRCS, OFFS, DEGS, LP1, HP0, LA, HA1, bb, l ? XPA : XPB, l == 0);
        if (!l)
            agg_author_k<<<(NAUTHOR * 32 + 255) / 256, 256>>>(
                SRCS, OFFS, DEGS, LP2, LA, HP2, bb + 256, XAB);
    }

    // final classifier: [200000,128] fp16 @ [128,64] + blin -> fp32 out
    mma_gemm<64, 1, false, false, true><<<TP, 256, sm64>>>(
        XPA, Wlin, nullptr, blin, d_out, nullptr, NPAPER);
}

// round 12
// speedup vs baseline: 4.8043x; 1.0385x over previous
#include <cuda_runtime.h>
#include <cuda_fp16.h>
#include <cstdint>

// ---------------------------------------------------------------------------
// Problem constants
// ---------------------------------------------------------------------------
static constexpr int NPAPER  = 200000;
static constexpr int NAUTHOR = 100000;
static constexpr int HID     = 128;     // 4 heads x 32 channels
static constexpr int ECITES  = 1000000;
static constexpr int EWRITES = 500000;
static constexpr int EWB     = 500000;
static constexpr int ETOT    = ECITES + EWRITES + EWB;   // 2,000,000
static constexpr int NTOT    = 2 * NPAPER + NAUTHOR;     // 500,000

static constexpr size_t SZ_P = (size_t)NPAPER * HID;
static constexpr size_t SZ_A = (size_t)NAUTHOR * HID;

// float scratch (logits only)
static constexpr size_t O_LP1  = 0;                              // paper logits [N,16]
static constexpr size_t O_LP2  = O_LP1 + (size_t)NPAPER * 16;
static constexpr size_t O_LA   = O_LP2 + (size_t)NPAPER * 16;
static constexpr size_t SCRATCH_FLOATS = O_LA + (size_t)NAUTHOR * 16;

__device__ float g_scratch[SCRATCH_FLOATS];

// half scratch: activations + gathered features + fp16 weights + V
static constexpr size_t H_XPA  = 0;
static constexpr size_t H_XAA  = H_XPA + SZ_P;
static constexpr size_t H_XPB  = H_XAA + SZ_A;
static constexpr size_t H_XAB  = H_XPB + SZ_P;
static constexpr size_t H_HP0  = H_XAB + SZ_A;
static constexpr size_t H_HP2  = H_HP0 + SZ_P;
static constexpr size_t H_HA1  = H_HP2 + SZ_P;
static constexpr size_t H_WP   = H_HA1 + SZ_A;      // [256,128]
static constexpr size_t H_WA   = H_WP + 32768;      // [128,128]
static constexpr size_t H_W0   = H_WA + 16384;      // 3 x [128,128]
static constexpr size_t H_W1   = H_W0 + 49152;      // 3 x [128,128]
static constexpr size_t H_WLIN = H_W1 + 49152;      // [128,64]
static constexpr size_t H_V    = H_WLIN + 8192;     // 5 x [128][16]
static constexpr size_t SCRATCH_HALF = H_V + 5 * 2048;

__device__ __half g_hscratch[SCRATCH_HALF];

// int scratch: merged CSR over concatenated node slots
static constexpr size_t I_DEGS = 0;
static constexpr size_t I_OFFS = I_DEGS + NTOT;
static constexpr size_t I_CURS = I_OFFS + NTOT;
static constexpr size_t I_SRCS = I_CURS + NTOT;
static constexpr size_t I_BS   = I_SRCS + ETOT;
static constexpr size_t SCRATCH_INTS = I_BS + 256;

__device__ int g_iscratch[SCRATCH_INTS];

// ---------------------------------------------------------------------------
// fp16 mma + ldmatrix helpers (plain sm_75+/sm_80+ PTX)
// ---------------------------------------------------------------------------
__device__ __forceinline__ void mma_f16(float* c, uint32_t a0, uint32_t a1,
                                        uint32_t a2, uint32_t a3,
                                        uint32_t b0, uint32_t b1) {
    asm volatile(
        "mma.sync.aligned.m16n8k16.row.col.f32.f16.f16.f32 "
        "{%0,%1,%2,%3}, {%4,%5,%6,%7}, {%8,%9}, {%0,%1,%2,%3};"
        : "+f"(c[0]), "+f"(c[1]), "+f"(c[2]), "+f"(c[3])
        : "r"(a0), "r"(a1), "r"(a2), "r"(a3), "r"(b0), "r"(b1));
}

__device__ __forceinline__ void ldm_x4(uint32_t* r, uint32_t addr) {
    asm volatile("ldmatrix.sync.aligned.m8n8.x4.shared.b16 {%0,%1,%2,%3}, [%4];"
                 : "=r"(r[0]), "=r"(r[1]), "=r"(r[2]), "=r"(r[3]) : "r"(addr));
}
__device__ __forceinline__ void ldm_x4t(uint32_t* r, uint32_t addr) {
    asm volatile("ldmatrix.sync.aligned.m8n8.x4.trans.shared.b16 {%0,%1,%2,%3}, [%4];"
                 : "=r"(r[0]), "=r"(r[1]), "=r"(r[2]), "=r"(r[3]) : "r"(addr));
}
__device__ __forceinline__ void ldm_x2t(uint32_t* r, uint32_t addr) {
    asm volatile("ldmatrix.sync.aligned.m8n8.x2.trans.shared.b16 {%0,%1}, [%2];"
                 : "=r"(r[0]), "=r"(r[1]) : "r"(addr));
}

// ---------------------------------------------------------------------------
// Prep 1: convert all weight matrices to fp16 (one elementwise pass).
// Ranges: Wp 32768 | Wa 16384 | W0 49152 | W1 49152 | Wlin 8192 = 155648.
// ---------------------------------------------------------------------------
__global__ void prep_w_k(const float* __restrict__ Wp, const float* __restrict__ Wa,
                         const float* __restrict__ W0, const float* __restrict__ W1,
                         const float* __restrict__ Wlin, __half* __restrict__ out) {
    int idx = blockIdx.x * blockDim.x + threadIdx.x;
    if (idx >= 155648) return;
    float v;
    if (idx < 32768)       v = Wp[idx];
    else if (idx < 49152)  v = Wa[idx - 32768];
    else if (idx < 98304)  v = W0[idx - 49152];
    else if (idx < 147456) v = W1[idx - 98304];
    else                   v = Wlin[idx - 147456];
    out[idx] = __float2half_rn(v);
}

// ---------------------------------------------------------------------------
// Prep 2: V matrices = W @ att (per head), fp16 output. 5 x [128][16] (see R7).
// ---------------------------------------------------------------------------
__global__ void prep_v_k(const float* __restrict__ W0, const float* __restrict__ as0,
                         const float* __restrict__ ad0, const float* __restrict__ W1,
                         const float* __restrict__ as1, const float* __restrict__ ad1,
                         __half* __restrict__ V) {
    int idx = blockIdx.x * blockDim.x + threadIdx.x;
    if (idx >= 5 * 2048) return;
    int m = idx >> 11;
    int r = idx & 2047;
    int k = r >> 4;
    int j = r & 15;
    int h = j & 3;
    int q = j >> 2;

    const float* Wm = nullptr;
    const float* at = nullptr;
    if (m == 0 || m == 1) {
        const float* W  = m ? W1 : W0;
        const float* as_ = m ? as1 : as0;
        const float* ad_ = m ? ad1 : ad0;
        if (q == 0)      { Wm = W;          at = as_; }
        else if (q == 1) { Wm = W;          at = ad_; }
        else if (q == 2) { Wm = W + 16384;  at = ad_ + 128; }
    } else if (m == 2) {
        if (q == 0) { Wm = W0 + 2 * 16384; at = as0 + 256; }
    } else if (m == 3) {
        if (q == 0)      { Wm = W0 + 16384;     at = as0 + 128; }
        else if (q == 1) { Wm = W0 + 2 * 16384; at = ad0 + 256; }
    } else {
        if (q == 0) { Wm = W1 + 16384; at = as1 + 128; }
    }
    float v = 0.f;
    if (Wm) {
#pragma unroll
        for (int c = 0; c < 32; c++)
            v += Wm[k * 128 + h * 32 + c] * at[h * 32 + c];
    }
    V[m * 2048 + k * 16 + j] = __float2half_rn(v);
}

// ---------------------------------------------------------------------------
// fp16 mma.sync GEMM (m16n8k16 + ldmatrix):
//   C[M,NC] = A[M,KCH*128] @ W[KCH*128, NC] (+bias), W/Vx are fp16 (pure copies).
// AHALF: A is __half. VEXT: 16 extra B cols from Vx -> Lbuf. HALF: C is __half.
// ---------------------------------------------------------------------------
template <int N, int KCH, bool VEXT, bool HALF, bool AHALF>
__global__ void __launch_bounds__(256, 2)
mma_gemm(const void* __restrict__ Av, const __half* __restrict__ W,
         const __half* __restrict__ Vx, const float* __restrict__ bias,
         void* __restrict__ Cv, float* __restrict__ Lbuf, int M) {
    constexpr int LDA_S = 136;         // halves
    constexpr int LDB_S = N + 8;       // halves
    constexpr int NF    = N / 16;
    constexpr int KTOT  = KCH * 128;
    constexpr int NC    = VEXT ? N - 16 : N;

    extern __shared__ __half smh[];
    __half* As = smh;
    __half* Bs = smh + 128 * LDA_S;

    const int tid  = threadIdx.x;
    const int wid  = tid >> 5;
    const int lane = tid & 31;
    const int wm   = wid >> 1;
    const int wn   = wid & 1;
    const int g    = lane >> 2;
    const int tg   = lane & 3;
    const int row0 = blockIdx.x * 128;

    const uint32_t asBase = (uint32_t)__cvta_generic_to_shared(As);
    const uint32_t bsBase = (uint32_t)__cvta_generic_to_shared(Bs);
    const int lrow = (lane & 7) + ((lane >> 3) & 1) * 8;
    const int lcol = (lane >> 4) * 8;

    float acc[2][NF][4];
#pragma unroll
    for (int mf = 0; mf < 2; mf++)
#pragma unroll
        for (int nf = 0; nf < NF; nf++)
#pragma unroll
            for (int j = 0; j < 4; j++) acc[mf][nf][j] = 0.f;

    for (int kc = 0; kc < KCH; kc++) {
        const int k0g = kc * 128;
        // ---- stage A chunk [128 x 128] ----
        if (AHALF) {
            const __half* A = (const __half*)Av;
#pragma unroll
            for (int i = tid; i < 128 * 16; i += 256) {
                int r = i >> 4, c8 = i & 15;
                int gr = row0 + r;
                uint4 v = make_uint4(0u, 0u, 0u, 0u);
                if (gr < M)
                    v = *reinterpret_cast<const uint4*>(A + (size_t)gr * KTOT + k0g + c8 * 8);
                *reinterpret_cast<uint4*>(As + r * LDA_S + c8 * 8) = v;
            }
        } else {
            const float* A = (const float*)Av;
#pragma unroll
            for (int i = tid; i < 128 * 32; i += 256) {
                int r = i >> 5, c4 = i & 31;
                int gr = row0 + r;
                float4 v = make_float4(0.f, 0.f, 0.f, 0.f);
                if (gr < M)
                    v = *reinterpret_cast<const float4*>(A + (size_t)gr * KTOT + k0g + c4 * 4);
                __half2* dst = reinterpret_cast<__half2*>(As + r * LDA_S + c4 * 4);
                dst[0] = __floats2half2_rn(v.x, v.y);
                dst[1] = __floats2half2_rn(v.z, v.w);
            }
        }
        // ---- stage B chunk [128 x N] (pure fp16 copies) ----
#pragma unroll
        for (int i = tid; i < 128 * (N / 8); i += 256) {
            int k = i / (N / 8), n8 = i % (N / 8);
            uint4 v;
            if (!VEXT || n8 < NC / 8)
                v = *reinterpret_cast<const uint4*>(W + (size_t)(k0g + k) * NC + n8 * 8);
            else
                v = reinterpret_cast<const uint4*>(Vx)[k * 2 + (n8 - NC / 8)];
            *reinterpret_cast<uint4*>(Bs + k * LDB_S + n8 * 8) = v;
        }
        __syncthreads();

        // ---- 8 k-steps of m16n8k16 ----
#pragma unroll
        for (int s = 0; s < 8; s++) {
            const int kk = s * 16;
            uint32_t a[2][4];
#pragma unroll
            for (int mf = 0; mf < 2; mf++) {
                int row = wm * 32 + mf * 16 + lrow;
                ldm_x4(a[mf], asBase + (uint32_t)(row * LDA_S + kk + lcol) * 2);
            }
            uint32_t b[NF][2];
#pragma unroll
            for (int nf2 = 0; nf2 < NF / 2; nf2++) {
                int n0 = wn * (N / 2) + nf2 * 16;
                uint32_t r4[4];
                ldm_x4t(r4, bsBase + (uint32_t)((kk + lrow) * LDB_S + n0 + lcol) * 2);
                b[nf2 * 2][0] = r4[0]; b[nf2 * 2][1] = r4[1];
                b[nf2 * 2 + 1][0] = r4[2]; b[nf2 * 2 + 1][1] = r4[3];
            }
            if (NF & 1) {
                int n0 = wn * (N / 2) + (NF - 1) * 8;
                ldm_x2t(b[NF - 1], bsBase + (uint32_t)((kk + lrow) * LDB_S + n0) * 2);
            }
#pragma unroll
            for (int mf = 0; mf < 2; mf++)
#pragma unroll
                for (int nf = 0; nf < NF; nf++)
                    mma_f16(acc[mf][nf], a[mf][0], a[mf][1], a[mf][2], a[mf][3],
                            b[nf][0], b[nf][1]);
        }
        __syncthreads();
    }

    // ---- epilogue ----
#pragma unroll
    for (int mf = 0; mf < 2; mf++) {
        const int r0 = row0 + wm * 32 + mf * 16 + g;
        const int r1 = r0 + 8;
#pragma unroll
        for (int nf = 0; nf < NF; nf++) {
            const int col = wn * (N / 2) + nf * 8 + tg * 2;
            float c0 = acc[mf][nf][0], c1 = acc[mf][nf][1];
            float c2 = acc[mf][nf][2], c3 = acc[mf][nf][3];
            if (!VEXT || col < NC) {
                if (bias) {
                    float b0v = bias[col], b1v = bias[col + 1];
                    c0 += b0v; c1 += b1v; c2 += b0v; c3 += b1v;
                }
                if (HALF) {
                    __half* C = (__half*)Cv;
                    if (r0 < M)
                        *reinterpret_cast<__half2*>(C + (size_t)r0 * NC + col) =
                            __floats2half2_rn(c0, c1);
                    if (r1 < M)
                        *reinterpret_cast<__half2*>(C + (size_t)r1 * NC + col) =
                            __floats2half2_rn(c2, c3);
                } else {
                    float* C = (float*)Cv;
                    if (r0 < M)
                        *reinterpret_cast<float2*>(C + (size_t)r0 * NC + col) = make_float2(c0, c1);
                    if (r1 < M)
                        *reinterpret_cast<float2*>(C + (size_t)r1 * NC + col) = make_float2(c2, c3);
                }
            } else {
                const int lc = col - NC;
                if (r0 < M)
                    *reinterpret_cast<float2*>(Lbuf + (size_t)r0 * 16 + lc) = make_float2(c0, c1);
                if (r1 < M)
                    *reinterpret_cast<float2*>(Lbuf + (size_t)r1 * 16 + lc) = make_float2(c2, c3);
            }
        }
    }
}

// ---------------------------------------------------------------------------
// Merged CSR build (one scan over concatenated slot space)
// ---------------------------------------------------------------------------
__global__ void hist3_k(const int* __restrict__ dc, const int* __restrict__ dw,
                        const int* __restrict__ db, int* __restrict__ degs) {
    int e = blockIdx.x * blockDim.x + threadIdx.x;
    if (e >= ETOT) return;
    int slot;
    if (e < ECITES)                slot = dc[e];
    else if (e < ECITES + EWRITES) slot = NPAPER + dw[e - ECITES];
    else                           slot = 2 * NPAPER + db[e - ECITES - EWRITES];
    atomicAdd(&degs[slot], 1);
}

__global__ void scanA_k(const int* __restrict__ deg, int* __restrict__ off,
                        int* __restrict__ bsum, int n) {
    __shared__ int sh[256];
    const int t = threadIdx.x, b = blockIdx.x;
    const int base = b * 2048 + t * 8;
    int v[8], s = 0;
#pragma unroll
    for (int i = 0; i < 8; i++) {
        int idx = base + i;
        v[i] = (idx < n) ? deg[idx] : 0;
        s += v[i];
    }
    sh[t] = s;
    __syncthreads();
    for (int o = 1; o < 256; o <<= 1) {
        int y = (t >= o) ? sh[t - o] : 0;
        __syncthreads();
        sh[t] += y;
        __syncthreads();
    }
    int run = sh[t] - s;
    if (t == 255) bsum[b] = sh[255];
#pragma unroll
    for (int i = 0; i < 8; i++) {
        int idx = base + i;
        if (idx < n) off[idx] = run;
        run += v[i];
    }
}

__global__ void scanB_k(int* __restrict__ bsum, int nb) {
    __shared__ int sh[256];
    int t = threadIdx.x;
    int v = (t < nb) ? bsum[t] : 0;
    sh[t] = v;
    __syncthreads();
    for (int o = 1; o < 256; o <<= 1) {
        int y = (t >= o) ? sh[t - o] : 0;
        __syncthreads();
        sh[t] += y;
        __syncthreads();
    }
    if (t < nb) bsum[t] = sh[t] - v;
}

__global__ void scanC_k(int* __restrict__ off, int* __restrict__ cur,
                        const int* __restrict__ bsum, int n) {
    int i = blockIdx.x * blockDim.x + threadIdx.x;
    if (i >= n) return;
    int v = off[i] + bsum[i >> 11];
    off[i] = v;
    cur[i] = v;
}

__global__ void scatter3_k(const int* __restrict__ sc, const int* __restrict__ dc,
                           const int* __restrict__ sw, const int* __restrict__ dw,
                           const int* __restrict__ sb, const int* __restrict__ db,
                           int* __restrict__ curs, int* __restrict__ srcs) {
    int e = blockIdx.x * blockDim.x + threadIdx.x;
    if (e >= ETOT) return;
    int slot, sv;
    if (e < ECITES)                { slot = dc[e]; sv = sc[e]; }
    else if (e < ECITES + EWRITES) { int i = e - ECITES; slot = NPAPER + dw[i]; sv = sw[i]; }
    else                           { int i = e - ECITES - EWRITES; slot = 2 * NPAPER + db[i]; sv = sb[i]; }
    srcs[atomicAdd(&curs[slot], 1)] = sv;
}

// ---------------------------------------------------------------------------
// Dst-major GAT aggregation; fp16 features, 2x-unrolled edge loops for MLP.
// ---------------------------------------------------------------------------
__device__ __forceinline__ float lrelu02(float v) { return v > 0.f ? v : 0.2f * v; }

__device__ __forceinline__ float4 gather_h16(const __half* __restrict__ hbuf,
                                             int sidx, int lane) {
    uint2 u = reinterpret_cast<const uint2*>(hbuf + (size_t)sidx * HID)[lane];
    __half2 p0 = *reinterpret_cast<__half2*>(&u.x);
    __half2 p1 = *reinterpret_cast<__half2*>(&u.y);
    float2 f0 = __half22float2(p0);
    float2 f1 = __half22float2(p1);
    return make_float4(f0.x, f0.y, f1.x, f1.y);
}

__device__ __forceinline__ void store_h16(__half* __restrict__ out, int n, int lane,
                                          float4 o) {
    uint2 u;
    __half2 p0 = __floats2half2_rn(o.x, o.y);
    __half2 p1 = __floats2half2_rn(o.z, o.w);
    u.x = *reinterpret_cast<uint32_t*>(&p0);
    u.y = *reinterpret_cast<uint32_t*>(&p1);
    reinterpret_cast<uint2*>(out + (size_t)n * HID)[lane] = u;
}

// One relation segment: softmax-weighted sum over in-edges (2x unrolled).
__device__ __forceinline__ void agg_rel(const int* __restrict__ srcs, int st, int d,
                                        const float* __restrict__ Lsrc, float ad,
                                        const __half* __restrict__ hbuf,
                                        int lane, int h, float4& a, float& s) {
    int j = 0;
    for (; j + 2 <= d; j += 2) {
        int s0 = srcs[st + j];
        int s1 = srcs[st + j + 1];
        float l0 = Lsrc[(size_t)s0 * 16 + h];
        float l1 = Lsrc[(size_t)s1 * 16 + h];
        float4 h0 = gather_h16(hbuf, s0, lane);
        float4 h1 = gather_h16(hbuf, s1, lane);
        float x0 = __expf(lrelu02(l0 + ad));
        float x1 = __expf(lrelu02(l1 + ad));
        s += x0 + x1;
        a.x += x0 * h0.x + x1 * h1.x;
        a.y += x0 * h0.y + x1 * h1.y;
        a.z += x0 * h0.z + x1 * h1.z;
        a.w += x0 * h0.w + x1 * h1.w;
    }
    if (j < d) {
        int s0 = srcs[st + j];
        float x0 = __expf(lrelu02(Lsrc[(size_t)s0 * 16 + h] + ad));
        float4 h0 = gather_h16(hbuf, s0, lane);
        s += x0;
        a.x += x0 * h0.x; a.y += x0 * h0.y; a.z += x0 * h0.z; a.w += x0 * h0.w;
    }
}

__global__ void agg_paper_k(
    const int* __restrict__ srcs, const int* __restrict__ offs, const int* __restrict__ degs,
    const float* __restrict__ LP1, const __half* __restrict__ h1,
    const float* __restrict__ LA,  const __half* __restrict__ h2,
    const float* __restrict__ bb, __half* __restrict__ out, int act) {
    const int n    = (blockIdx.x * blockDim.x + threadIdx.x) >> 5;
    const int lane = threadIdx.x & 31;
    if (n >= NPAPER) return;
    const int h = lane >> 3;

    float4 a1 = make_float4(0.f, 0.f, 0.f, 0.f);
    float  s1 = 0.f;
    agg_rel(srcs, offs[n], degs[n], LP1, LP1[(size_t)n * 16 + 4 + h], h1, lane, h, a1, s1);

    float4 a2 = make_float4(0.f, 0.f, 0.f, 0.f);
    float  s2 = 0.f;
    agg_rel(srcs, offs[NPAPER + n], degs[NPAPER + n], LA, LP1[(size_t)n * 16 + 8 + h],
            h2, lane, h, a2, s2);

    float i1 = 1.f / (s1 + 1e-16f);
    float i2 = 1.f / (s2 + 1e-16f);
    float4 bv1 = reinterpret_cast<const float4*>(bb)[lane];
    float4 bv2 = reinterpret_cast<const float4*>(bb + 128)[lane];
    float4 o;
    o.x = a1.x * i1 + a2.x * i2 + bv1.x + bv2.x;
    o.y = a1.y * i1 + a2.y * i2 + bv1.y + bv2.y;
    o.z = a1.z * i1 + a2.z * i2 + bv1.z + bv2.z;
    o.w = a1.w * i1 + a2.w * i2 + bv1.w + bv2.w;
    if (act) {
        o.x = o.x > 0.f ? o.x : 0.01f * o.x;
        o.y = o.y > 0.f ? o.y : 0.01f * o.y;
        o.z = o.z > 0.f ? o.z : 0.01f * o.z;
        o.w = o.w > 0.f ? o.w : 0.01f * o.w;
    }
    store_h16(out, n, lane, o);
}

__global__ void agg_author_k(
    const int* __restrict__ srcs, const int* __restrict__ offs, const int* __restrict__ degs,
    const float* __restrict__ LP2, const float* __restrict__ LA,
    const __half* __restrict__ h1, const float* __restrict__ bb,
    __half* __restrict__ out) {
    const int n    = (blockIdx.x * blockDim.x + threadIdx.x) >> 5;
    const int lane = threadIdx.x & 31;
    if (n >= NAUTHOR) return;
    const int h = lane >> 3;

    float4 a1 = make_float4(0.f, 0.f, 0.f, 0.f);
    float  s1 = 0.f;
    agg_rel(srcs, offs[2 * NPAPER + n], degs[2 * NPAPER + n], LP2,
            LA[(size_t)n * 16 + 4 + h], h1, lane, h, a1, s1);

    float i1 = 1.f / (s1 + 1e-16f);
    float4 bv = reinterpret_cast<const float4*>(bb)[lane];
    float4 o;
    o.x = a1.x * i1 + bv.x;
    o.y = a1.y * i1 + bv.y;
    o.z = a1.z * i1 + bv.z;
    o.w = a1.w * i1 + bv.w;
    o.x = o.x > 0.f ? o.x : 0.01f * o.x;
    o.y = o.y > 0.f ? o.y : 0.01f * o.y;
    o.z = o.z > 0.f ? o.z : 0.01f * o.z;
    o.w = o.w > 0.f ? o.w : 0.01f * o.w;
    store_h16(out, n, lane, o);
}

// ---------------------------------------------------------------------------
// Host orchestration
// ---------------------------------------------------------------------------
static inline int gemm_smem(int N) { return (128 * 136 + 128 * (N + 8)) * 2; }

extern "C" void kernel_launch(void* const* d_in, const int* in_sizes, int n_in,
                              void* d_out, int out_size) {
    const float* x_paper  = (const float*)d_in[0];
    const float* x_author = (const float*)d_in[1];
    const float* Wp   = (const float*)d_in[2];
    const float* bp   = (const float*)d_in[3];
    const float* Wa   = (const float*)d_in[4];
    const float* ba   = (const float*)d_in[5];
    const float* W0   = (const float*)d_in[6];
    const float* as0  = (const float*)d_in[7];
    const float* ad0  = (const float*)d_in[8];
    const float* b0   = (const float*)d_in[9];
    const float* W1   = (const float*)d_in[10];
    const float* as1  = (const float*)d_in[11];
    const float* ad1  = (const float*)d_in[12];
    const float* b1   = (const float*)d_in[13];
    const float* Wlin = (const float*)d_in[14];
    const float* blin = (const float*)d_in[15];
    const int* src_c  = (const int*)d_in[16];
    const int* dst_c  = (const int*)d_in[17];
    const int* src_w  = (const int*)d_in[18];
    const int* dst_w  = (const int*)d_in[19];
    const int* src_b  = (const int*)d_in[20];
    const int* dst_b  = (const int*)d_in[21];

    float* S = nullptr;
    cudaGetSymbolAddress((void**)&S, g_scratch);
    __half* Hh = nullptr;
    cudaGetSymbolAddress((void**)&Hh, g_hscratch);
    int* I = nullptr;
    cudaGetSymbolAddress((void**)&I, g_iscratch);

    float*  LP1 = S + O_LP1;
    float*  LP2 = S + O_LP2;
    float*  LA  = S + O_LA;
    __half* XPA = Hh + H_XPA;
    __half* XAA = Hh + H_XAA;
    __half* XPB = Hh + H_XPB;
    __half* XAB = Hh + H_XAB;
    __half* HP0 = Hh + H_HP0;
    __half* HP2 = Hh + H_HP2;
    __half* HA1 = Hh + H_HA1;
    __half* HWP = Hh + H_WP;
    __half* HWA = Hh + H_WA;
    __half* HW0 = Hh + H_W0;
    __half* HW1 = Hh + H_W1;
    __half* HWL = Hh + H_WLIN;
    __half* HV  = Hh + H_V;

    int* DEGS = I + I_DEGS;
    int* OFFS = I + I_OFFS;
    int* CURS = I + I_CURS;
    int* SRCS = I + I_SRCS;
    int* BS   = I + I_BS;

    const int sm144 = gemm_smem(144);
    const int sm128 = gemm_smem(128);
    const int sm64  = gemm_smem(64);
    cudaFuncSetAttribute(mma_gemm<128, 2, false, true,  false>, cudaFuncAttributeMaxDynamicSharedMemorySize, sm128);
    cudaFuncSetAttribute(mma_gemm<128, 1, false, true,  false>, cudaFuncAttributeMaxDynamicSharedMemorySize, sm128);
    cudaFuncSetAttribute(mma_gemm<144, 1, true,  true,  true >, cudaFuncAttributeMaxDynamicSharedMemorySize, sm144);
    cudaFuncSetAttribute(mma_gemm<64,  1, false, false, true >, cudaFuncAttributeMaxDynamicSharedMemorySize, sm64);

    const int TP = (NPAPER + 127) / 128;
    const int TA = (NAUTHOR + 127) / 128;

    // ---- prep fp16 weights + V + merged CSR build ----
    prep_w_k<<<608, 256>>>(Wp, Wa, W0, W1, Wlin, Hh + H_WP);
    prep_v_k<<<40, 256>>>(W0, as0, ad0, W1, as1, ad1, HV);
    cudaMemsetAsync(DEGS, 0, (size_t)NTOT * sizeof(int));
    hist3_k<<<(ETOT + 255) / 256, 256>>>(dst_c, dst_w, dst_b, DEGS);
    const int NB = (NTOT + 2047) / 2048;  // 245 <= 256
    scanA_k<<<NB, 256>>>(DEGS, OFFS, BS, NTOT);
    scanB_k<<<1, 256>>>(BS, NB);
    scanC_k<<<(NTOT + 255) / 256, 256>>>(OFFS, CURS, BS, NTOT);
    scatter3_k<<<(ETOT + 255) / 256, 256>>>(src_c, dst_c, src_w, dst_w, src_b, dst_b,
                                            CURS, SRCS);

    // ---- input projections (fp32 A in, fp16 W, fp16 X out) ----
    mma_gemm<128, 2, false, true, false><<<TP, 256, sm128>>>(
        x_paper, HWP, nullptr, bp, XPA, nullptr, NPAPER);
    mma_gemm<128, 1, false, true, false><<<TA, 256, sm128>>>(
        x_author, HWA, nullptr, ba, XAA, nullptr, NAUTHOR);

    for (int l = 0; l < 2; l++) {
        const __half* W  = l ? HW1 : HW0;
        const float*  bb = l ? b1 : b0;
        const __half* xp = l ? XPB : XPA;
        const __half* xa = l ? XAB : XAA;

        mma_gemm<144, 1, true, true, true><<<TP, 256, sm144>>>(
            xp, W + 0 * HID * HID, HV + (l ? 1 : 0) * 2048, nullptr, HP0, LP1, NPAPER);
        mma_gemm<144, 1, true, true, true><<<TA, 256, sm144>>>(
            xa, W + 1 * HID * HID, HV + (l ? 4 : 3) * 2048, nullptr, HA1, LA, NAUTHOR);
        if (!l) {
            mma_gemm<144, 1, true, true, true><<<TP, 256, sm144>>>(
                xp, W + 2 * HID * HID, HV + 2 * 2048, nullptr, HP2, LP2, NPAPER);
        }

        agg_paper_k<<<(NPAPER * 32 + 255) / 256, 256>>>(
            SRCS, OFFS, DEGS, LP1, HP0, LA, HA1, bb, l ? XPA : XPB, l == 0);
        if (!l)
            agg_author_k<<<(NAUTHOR * 32 + 255) / 256, 256>>>(
                SRCS, OFFS, DEGS, LP2, LA, HP2, bb + 256, XAB);
    }

    // final classifier: [200000,128] fp16 @ [128,64] fp16 + blin -> fp32 out
    mma_gemm<64, 1, false, false, true><<<TP, 256, sm64>>>(
        XPA, HWL, nullptr, blin, d_out, nullptr, NPAPER);
}

// round 13
// speedup vs baseline: 5.1555x; 1.0731x over previous
#include <cuda_runtime.h>
#include <cuda_fp16.h>
#include <cstdint>

// ---------------------------------------------------------------------------
// Problem constants
// ---------------------------------------------------------------------------
static constexpr int NPAPER  = 200000;
static constexpr int NAUTHOR = 100000;
static constexpr int HID     = 128;     // 4 heads x 32 channels
static constexpr int ECITES  = 1000000;
static constexpr int EWRITES = 500000;
static constexpr int EWB     = 500000;
static constexpr int ETOT    = ECITES + EWRITES + EWB;   // 2,000,000
static constexpr int NTOT    = 2 * NPAPER + NAUTHOR;     // 500,000

static constexpr size_t SZ_P = (size_t)NPAPER * HID;
static constexpr size_t SZ_A = (size_t)NAUTHOR * HID;

// float scratch (logits only)
static constexpr size_t O_LP1  = 0;                              // paper logits [N,16]
static constexpr size_t O_LP2  = O_LP1 + (size_t)NPAPER * 16;
static constexpr size_t O_LA   = O_LP2 + (size_t)NPAPER * 16;
static constexpr size_t SCRATCH_FLOATS = O_LA + (size_t)NAUTHOR * 16;

__device__ float g_scratch[SCRATCH_FLOATS];

// half scratch: activations + gathered features + fp16 weights + V
static constexpr size_t H_XPA  = 0;
static constexpr size_t H_XAA  = H_XPA + SZ_P;
static constexpr size_t H_XPB  = H_XAA + SZ_A;
static constexpr size_t H_XAB  = H_XPB + SZ_P;
static constexpr size_t H_HP0  = H_XAB + SZ_A;
static constexpr size_t H_HP2  = H_HP0 + SZ_P;
static constexpr size_t H_HA1  = H_HP2 + SZ_P;
static constexpr size_t H_WP   = H_HA1 + SZ_A;      // [256,128]
static constexpr size_t H_WA   = H_WP + 32768;      // [128,128]
static constexpr size_t H_W0   = H_WA + 16384;      // 3 x [128,128]
static constexpr size_t H_W1   = H_W0 + 49152;      // 3 x [128,128]
static constexpr size_t H_WLIN = H_W1 + 49152;      // [128,64]
static constexpr size_t H_V    = H_WLIN + 8192;     // 5 x [128][16]
static constexpr size_t SCRATCH_HALF = H_V + 5 * 2048;

__device__ __half g_hscratch[SCRATCH_HALF];

// int scratch: merged CSR over concatenated node slots
static constexpr size_t I_DEGS = 0;
static constexpr size_t I_OFFS = I_DEGS + NTOT;
static constexpr size_t I_CURS = I_OFFS + NTOT;
static constexpr size_t I_SRCS = I_CURS + NTOT;
static constexpr size_t I_BS   = I_SRCS + ETOT;
static constexpr size_t SCRATCH_INTS = I_BS + 256;

__device__ int g_iscratch[SCRATCH_INTS];

// ---------------------------------------------------------------------------
// fp16 mma + ldmatrix helpers (plain sm_75+/sm_80+ PTX)
// ---------------------------------------------------------------------------
__device__ __forceinline__ void mma_f16(float* c, uint32_t a0, uint32_t a1,
                                        uint32_t a2, uint32_t a3,
                                        uint32_t b0, uint32_t b1) {
    asm volatile(
        "mma.sync.aligned.m16n8k16.row.col.f32.f16.f16.f32 "
        "{%0,%1,%2,%3}, {%4,%5,%6,%7}, {%8,%9}, {%0,%1,%2,%3};"
        : "+f"(c[0]), "+f"(c[1]), "+f"(c[2]), "+f"(c[3])
        : "r"(a0), "r"(a1), "r"(a2), "r"(a3), "r"(b0), "r"(b1));
}

__device__ __forceinline__ void ldm_x4(uint32_t* r, uint32_t addr) {
    asm volatile("ldmatrix.sync.aligned.m8n8.x4.shared.b16 {%0,%1,%2,%3}, [%4];"
                 : "=r"(r[0]), "=r"(r[1]), "=r"(r[2]), "=r"(r[3]) : "r"(addr));
}
__device__ __forceinline__ void ldm_x4t(uint32_t* r, uint32_t addr) {
    asm volatile("ldmatrix.sync.aligned.m8n8.x4.trans.shared.b16 {%0,%1,%2,%3}, [%4];"
                 : "=r"(r[0]), "=r"(r[1]), "=r"(r[2]), "=r"(r[3]) : "r"(addr));
}
__device__ __forceinline__ void ldm_x2t(uint32_t* r, uint32_t addr) {
    asm volatile("ldmatrix.sync.aligned.m8n8.x2.trans.shared.b16 {%0,%1}, [%2];"
                 : "=r"(r[0]), "=r"(r[1]) : "r"(addr));
}

// ---------------------------------------------------------------------------
// Prep 1: convert all weight matrices to fp16 (one elementwise pass).
// ---------------------------------------------------------------------------
__global__ void prep_w_k(const float* __restrict__ Wp, const float* __restrict__ Wa,
                         const float* __restrict__ W0, const float* __restrict__ W1,
                         const float* __restrict__ Wlin, __half* __restrict__ out) {
    int idx = blockIdx.x * blockDim.x + threadIdx.x;
    if (idx >= 155648) return;
    float v;
    if (idx < 32768)       v = Wp[idx];
    else if (idx < 49152)  v = Wa[idx - 32768];
    else if (idx < 98304)  v = W0[idx - 49152];
    else if (idx < 147456) v = W1[idx - 98304];
    else                   v = Wlin[idx - 147456];
    out[idx] = __float2half_rn(v);
}

// ---------------------------------------------------------------------------
// Prep 2: V matrices = W @ att (per head), fp16 output. 5 x [128][16] (see R7).
// ---------------------------------------------------------------------------
__global__ void prep_v_k(const float* __restrict__ W0, const float* __restrict__ as0,
                         const float* __restrict__ ad0, const float* __restrict__ W1,
                         const float* __restrict__ as1, const float* __restrict__ ad1,
                         __half* __restrict__ V) {
    int idx = blockIdx.x * blockDim.x + threadIdx.x;
    if (idx >= 5 * 2048) return;
    int m = idx >> 11;
    int r = idx & 2047;
    int k = r >> 4;
    int j = r & 15;
    int h = j & 3;
    int q = j >> 2;

    const float* Wm = nullptr;
    const float* at = nullptr;
    if (m == 0 || m == 1) {
        const float* W  = m ? W1 : W0;
        const float* as_ = m ? as1 : as0;
        const float* ad_ = m ? ad1 : ad0;
        if (q == 0)      { Wm = W;          at = as_; }
        else if (q == 1) { Wm = W;          at = ad_; }
        else if (q == 2) { Wm = W + 16384;  at = ad_ + 128; }
    } else if (m == 2) {
        if (q == 0) { Wm = W0 + 2 * 16384; at = as0 + 256; }
    } else if (m == 3) {
        if (q == 0)      { Wm = W0 + 16384;     at = as0 + 128; }
        else if (q == 1) { Wm = W0 + 2 * 16384; at = ad0 + 256; }
    } else {
        if (q == 0) { Wm = W1 + 16384; at = as1 + 128; }
    }
    float v = 0.f;
    if (Wm) {
#pragma unroll
        for (int c = 0; c < 32; c++)
            v += Wm[k * 128 + h * 32 + c] * at[h * 32 + c];
    }
    V[m * 2048 + k * 16 + j] = __float2half_rn(v);
}

// ---------------------------------------------------------------------------
// fp16 mma.sync GEMM (m16n8k16 + ldmatrix), optionally DUAL (two B/C pairs
// sharing one staged A). W/Vx are fp16. AHALF: A is __half. VEXT: extra 16
// B cols from Vx -> Lbuf. HALF: C stored as __half.
// ---------------------------------------------------------------------------
template <int N, int KCH, bool VEXT, bool HALF, bool AHALF, bool DUAL>
__global__ void __launch_bounds__(256, 2)
mma_gemm(const void* __restrict__ Av,
         const __half* __restrict__ W1p, const __half* __restrict__ V1,
         void* __restrict__ C1, float* __restrict__ L1,
         const __half* __restrict__ W2p, const __half* __restrict__ V2,
         void* __restrict__ C2, float* __restrict__ L2,
         const float* __restrict__ bias, int M) {
    constexpr int LDA_S = 136;         // halves
    constexpr int LDB_S = N + 8;       // halves
    constexpr int NF    = N / 16;
    constexpr int KTOT  = KCH * 128;
    constexpr int NC    = VEXT ? N - 16 : N;

    extern __shared__ __half smh[];
    __half* As = smh;
    __half* Bs = smh + 128 * LDA_S;

    const int tid  = threadIdx.x;
    const int wid  = tid >> 5;
    const int lane = tid & 31;
    const int wm   = wid >> 1;
    const int wn   = wid & 1;
    const int g    = lane >> 2;
    const int tg   = lane & 3;
    const int row0 = blockIdx.x * 128;

    const uint32_t asBase = (uint32_t)__cvta_generic_to_shared(As);
    const uint32_t bsBase = (uint32_t)__cvta_generic_to_shared(Bs);
    const int lrow = (lane & 7) + ((lane >> 3) & 1) * 8;
    const int lcol = (lane >> 4) * 8;

    float acc[2][NF][4];

    // ---- stage A once (KCH==1 when DUAL; loop kept for generality) ----
    for (int pass = 0; pass < (DUAL ? 2 : 1); pass++) {
        const __half* W  = pass ? W2p : W1p;
        const __half* Vx = pass ? V2 : V1;
        void* Cv  = pass ? C2 : C1;
        float* Lb = pass ? L2 : L1;

#pragma unroll
        for (int mf = 0; mf < 2; mf++)
#pragma unroll
            for (int nf = 0; nf < NF; nf++)
#pragma unroll
                for (int j = 0; j < 4; j++) acc[mf][nf][j] = 0.f;

        for (int kc = 0; kc < KCH; kc++) {
            const int k0g = kc * 128;
            if (pass == 0) {
                if (AHALF) {
                    const __half* A = (const __half*)Av;
#pragma unroll
                    for (int i = tid; i < 128 * 16; i += 256) {
                        int r = i >> 4, c8 = i & 15;
                        int gr = row0 + r;
                        uint4 v = make_uint4(0u, 0u, 0u, 0u);
                        if (gr < M)
                            v = *reinterpret_cast<const uint4*>(A + (size_t)gr * KTOT + k0g + c8 * 8);
                        *reinterpret_cast<uint4*>(As + r * LDA_S + c8 * 8) = v;
                    }
                } else {
                    const float* A = (const float*)Av;
#pragma unroll
                    for (int i = tid; i < 128 * 32; i += 256) {
                        int r = i >> 5, c4 = i & 31;
                        int gr = row0 + r;
                        float4 v = make_float4(0.f, 0.f, 0.f, 0.f);
                        if (gr < M)
                            v = *reinterpret_cast<const float4*>(A + (size_t)gr * KTOT + k0g + c4 * 4);
                        __half2* dst = reinterpret_cast<__half2*>(As + r * LDA_S + c4 * 4);
                        dst[0] = __floats2half2_rn(v.x, v.y);
                        dst[1] = __floats2half2_rn(v.z, v.w);
                    }
                }
            }
            // ---- stage B chunk [128 x N] (pure fp16 copies) ----
#pragma unroll
            for (int i = tid; i < 128 * (N / 8); i += 256) {
                int k = i / (N / 8), n8 = i % (N / 8);
                uint4 v;
                if (!VEXT || n8 < NC / 8)
                    v = *reinterpret_cast<const uint4*>(W + (size_t)(k0g + k) * NC + n8 * 8);
                else
                    v = reinterpret_cast<const uint4*>(Vx)[k * 2 + (n8 - NC / 8)];
                *reinterpret_cast<uint4*>(Bs + k * LDB_S + n8 * 8) = v;
            }
            __syncthreads();

            // ---- 8 k-steps of m16n8k16 ----
#pragma unroll
            for (int s = 0; s < 8; s++) {
                const int kk = s * 16;
                uint32_t a[2][4];
#pragma unroll
                for (int mf = 0; mf < 2; mf++) {
                    int row = wm * 32 + mf * 16 + lrow;
                    ldm_x4(a[mf], asBase + (uint32_t)(row * LDA_S + kk + lcol) * 2);
                }
                uint32_t b[NF][2];
#pragma unroll
                for (int nf2 = 0; nf2 < NF / 2; nf2++) {
                    int n0 = wn * (N / 2) + nf2 * 16;
                    uint32_t r4[4];
                    ldm_x4t(r4, bsBase + (uint32_t)((kk + lrow) * LDB_S + n0 + lcol) * 2);
                    b[nf2 * 2][0] = r4[0]; b[nf2 * 2][1] = r4[1];
                    b[nf2 * 2 + 1][0] = r4[2]; b[nf2 * 2 + 1][1] = r4[3];
                }
                if (NF & 1) {
                    int n0 = wn * (N / 2) + (NF - 1) * 8;
                    ldm_x2t(b[NF - 1], bsBase + (uint32_t)((kk + lrow) * LDB_S + n0) * 2);
                }
#pragma unroll
                for (int mf = 0; mf < 2; mf++)
#pragma unroll
                    for (int nf = 0; nf < NF; nf++)
                        mma_f16(acc[mf][nf], a[mf][0], a[mf][1], a[mf][2], a[mf][3],
                                b[nf][0], b[nf][1]);
            }
            __syncthreads();
        }

        // ---- epilogue ----
#pragma unroll
        for (int mf = 0; mf < 2; mf++) {
            const int r0 = row0 + wm * 32 + mf * 16 + g;
            const int r1 = r0 + 8;
#pragma unroll
            for (int nf = 0; nf < NF; nf++) {
                const int col = wn * (N / 2) + nf * 8 + tg * 2;
                float c0 = acc[mf][nf][0], c1 = acc[mf][nf][1];
                float c2 = acc[mf][nf][2], c3 = acc[mf][nf][3];
                if (!VEXT || col < NC) {
                    if (bias) {
                        float b0v = bias[col], b1v = bias[col + 1];
                        c0 += b0v; c1 += b1v; c2 += b0v; c3 += b1v;
                    }
                    if (HALF) {
                        __half* C = (__half*)Cv;
                        if (r0 < M)
                            *reinterpret_cast<__half2*>(C + (size_t)r0 * NC + col) =
                                __floats2half2_rn(c0, c1);
                        if (r1 < M)
                            *reinterpret_cast<__half2*>(C + (size_t)r1 * NC + col) =
                                __floats2half2_rn(c2, c3);
                    } else {
                        float* C = (float*)Cv;
                        if (r0 < M)
                            *reinterpret_cast<float2*>(C + (size_t)r0 * NC + col) = make_float2(c0, c1);
                        if (r1 < M)
                            *reinterpret_cast<float2*>(C + (size_t)r1 * NC + col) = make_float2(c2, c3);
                    }
                } else {
                    const int lc = col - NC;
                    if (r0 < M)
                        *reinterpret_cast<float2*>(Lb + (size_t)r0 * 16 + lc) = make_float2(c0, c1);
                    if (r1 < M)
                        *reinterpret_cast<float2*>(Lb + (size_t)r1 * 16 + lc) = make_float2(c2, c3);
                }
            }
        }
        if (DUAL && pass == 0) __syncthreads();   // all reads of Bs done before restage
    }
}

// ---------------------------------------------------------------------------
// Merged CSR build (one scan over concatenated slot space)
// ---------------------------------------------------------------------------
__global__ void hist3_k(const int* __restrict__ dc, const int* __restrict__ dw,
                        const int* __restrict__ db, int* __restrict__ degs) {
    int e = blockIdx.x * blockDim.x + threadIdx.x;
    if (e >= ETOT) return;
    int slot;
    if (e < ECITES)                slot = dc[e];
    else if (e < ECITES + EWRITES) slot = NPAPER + dw[e - ECITES];
    else                           slot = 2 * NPAPER + db[e - ECITES - EWRITES];
    atomicAdd(&degs[slot], 1);
}

__global__ void scanA_k(const int* __restrict__ deg, int* __restrict__ off,
                        int* __restrict__ bsum, int n) {
    __shared__ int sh[256];
    const int t = threadIdx.x, b = blockIdx.x;
    const int base = b * 2048 + t * 8;
    int v[8], s = 0;
#pragma unroll
    for (int i = 0; i < 8; i++) {
        int idx = base + i;
        v[i] = (idx < n) ? deg[idx] : 0;
        s += v[i];
    }
    sh[t] = s;
    __syncthreads();
    for (int o = 1; o < 256; o <<= 1) {
        int y = (t >= o) ? sh[t - o] : 0;
        __syncthreads();
        sh[t] += y;
        __syncthreads();
    }
    int run = sh[t] - s;
    if (t == 255) bsum[b] = sh[255];
#pragma unroll
    for (int i = 0; i < 8; i++) {
        int idx = base + i;
        if (idx < n) off[idx] = run;
        run += v[i];
    }
}

__global__ void scanB_k(int* __restrict__ bsum, int nb) {
    __shared__ int sh[256];
    int t = threadIdx.x;
    int v = (t < nb) ? bsum[t] : 0;
    sh[t] = v;
    __syncthreads();
    for (int o = 1; o < 256; o <<= 1) {
        int y = (t >= o) ? sh[t - o] : 0;
        __syncthreads();
        sh[t] += y;
        __syncthreads();
    }
    if (t < nb) bsum[t] = sh[t] - v;
}

__global__ void scanC_k(int* __restrict__ off, int* __restrict__ cur,
                        const int* __restrict__ bsum, int n) {
    int i = blockIdx.x * blockDim.x + threadIdx.x;
    if (i >= n) return;
    int v = off[i] + bsum[i >> 11];
    off[i] = v;
    cur[i] = v;
}

__global__ void scatter3_k(const int* __restrict__ sc, const int* __restrict__ dc,
                           const int* __restrict__ sw, const int* __restrict__ dw,
                           const int* __restrict__ sb, const int* __restrict__ db,
                           int* __restrict__ curs, int* __restrict__ srcs) {
    int e = blockIdx.x * blockDim.x + threadIdx.x;
    if (e >= ETOT) return;
    int slot, sv;
    if (e < ECITES)                { slot = dc[e]; sv = sc[e]; }
    else if (e < ECITES + EWRITES) { int i = e - ECITES; slot = NPAPER + dw[i]; sv = sw[i]; }
    else                           { int i = e - ECITES - EWRITES; slot = 2 * NPAPER + db[i]; sv = sb[i]; }
    srcs[atomicAdd(&curs[slot], 1)] = sv;
}

// ---------------------------------------------------------------------------
// Dst-major GAT aggregation: 2 nodes per warp (16-lane halves), each lane
// owns 8 channels (one uint4 = 16B gather). 2x unroll -> 4 gathers in
// flight per warp. fp16 features in/out; math identical to before.
// ---------------------------------------------------------------------------
__device__ __forceinline__ float lrelu02(float v) { return v > 0.f ? v : 0.2f * v; }

struct F8 { float v[8]; };

__device__ __forceinline__ F8 gather_h8(const __half* __restrict__ hbuf,
                                        int sidx, int l16) {
    uint4 u = reinterpret_cast<const uint4*>(hbuf + (size_t)sidx * HID)[l16];
    F8 r;
    const uint32_t* p = &u.x;
#pragma unroll
    for (int i = 0; i < 4; i++) {
        __half2 h2 = *reinterpret_cast<const __half2*>(&p[i]);
        float2 f = __half22float2(h2);
        r.v[2 * i] = f.x;
        r.v[2 * i + 1] = f.y;
    }
    return r;
}

// One relation segment (2x unrolled); accumulates into a[8] and s.
__device__ __forceinline__ void agg_rel(const int* __restrict__ srcs, int st, int d,
                                        const float* __restrict__ Lsrc, float ad,
                                        const __half* __restrict__ hbuf,
                                        int l16, int h, float* a, float& s) {
    int j = 0;
    for (; j + 2 <= d; j += 2) {
        int s0 = srcs[st + j];
        int s1 = srcs[st + j + 1];
        float l0 = Lsrc[(size_t)s0 * 16 + h];
        float l1 = Lsrc[(size_t)s1 * 16 + h];
        F8 h0 = gather_h8(hbuf, s0, l16);
        F8 h1 = gather_h8(hbuf, s1, l16);
        float x0 = __expf(lrelu02(l0 + ad));
        float x1 = __expf(lrelu02(l1 + ad));
        s += x0 + x1;
#pragma unroll
        for (int i = 0; i < 8; i++) a[i] += x0 * h0.v[i] + x1 * h1.v[i];
    }
    if (j < d) {
        int s0 = srcs[st + j];
        float x0 = __expf(lrelu02(Lsrc[(size_t)s0 * 16 + h] + ad));
        F8 h0 = gather_h8(hbuf, s0, l16);
        s += x0;
#pragma unroll
        for (int i = 0; i < 8; i++) a[i] += x0 * h0.v[i];
    }
}

__device__ __forceinline__ void store_h8(__half* __restrict__ out, int n, int l16,
                                         const float* o) {
    uint4 u;
    uint32_t* p = &u.x;
#pragma unroll
    for (int i = 0; i < 4; i++) {
        __half2 h2 = __floats2half2_rn(o[2 * i], o[2 * i + 1]);
        p[i] = *reinterpret_cast<uint32_t*>(&h2);
    }
    reinterpret_cast<uint4*>(out + (size_t)n * HID)[l16] = u;
}

__global__ void agg_paper_k(
    const int* __restrict__ srcs, const int* __restrict__ offs, const int* __restrict__ degs,
    const float* __restrict__ LP1, const __half* __restrict__ h1,
    const float* __restrict__ LA,  const __half* __restrict__ h2,
    const float* __restrict__ bb, __half* __restrict__ out, int act) {
    const int gid  = blockIdx.x * blockDim.x + threadIdx.x;
    const int lane = threadIdx.x & 31;
    const int l16  = lane & 15;
    const int n    = ((gid >> 5) << 1) + (lane >> 4);   // 2 nodes per warp
    if (n >= NPAPER) return;
    const int h = l16 >> 2;

    float a1[8] = {0, 0, 0, 0, 0, 0, 0, 0};
    float s1 = 0.f;
    agg_rel(srcs, offs[n], degs[n], LP1, LP1[(size_t)n * 16 + 4 + h], h1, l16, h, a1, s1);

    float a2[8] = {0, 0, 0, 0, 0, 0, 0, 0};
    float s2 = 0.f;
    agg_rel(srcs, offs[NPAPER + n], degs[NPAPER + n], LA, LP1[(size_t)n * 16 + 8 + h],
            h2, l16, h, a2, s2);

    float i1 = 1.f / (s1 + 1e-16f);
    float i2 = 1.f / (s2 + 1e-16f);
    float4 bv1a = reinterpret_cast<const float4*>(bb)[l16 * 2];
    float4 bv1b = reinterpret_cast<const float4*>(bb)[l16 * 2 + 1];
    float4 bv2a = reinterpret_cast<const float4*>(bb + 128)[l16 * 2];
    float4 bv2b = reinterpret_cast<const float4*>(bb + 128)[l16 * 2 + 1];
    float bsum[8] = {bv1a.x + bv2a.x, bv1a.y + bv2a.y, bv1a.z + bv2a.z, bv1a.w + bv2a.w,
                     bv1b.x + bv2b.x, bv1b.y + bv2b.y, bv1b.z + bv2b.z, bv1b.w + bv2b.w};
    float o[8];
#pragma unroll
    for (int i = 0; i < 8; i++) {
        float v = a1[i] * i1 + a2[i] * i2 + bsum[i];
        o[i] = (act && v < 0.f) ? 0.01f * v : v;
    }
    store_h8(out, n, l16, o);
}

__global__ void agg_author_k(
    const int* __restrict__ srcs, const int* __restrict__ offs, const int* __restrict__ degs,
    const float* __restrict__ LP2, const float* __restrict__ LA,
    const __half* __restrict__ h1, const float* __restrict__ bb,
    __half* __restrict__ out) {
    const int gid  = blockIdx.x * blockDim.x + threadIdx.x;
    const int lane = threadIdx.x & 31;
    const int l16  = lane & 15;
    const int n    = ((gid >> 5) << 1) + (lane >> 4);
    if (n >= NAUTHOR) return;
    const int h = l16 >> 2;

    float a1[8] = {0, 0, 0, 0, 0, 0, 0, 0};
    float s1 = 0.f;
    agg_rel(srcs, offs[2 * NPAPER + n], degs[2 * NPAPER + n], LP2,
            LA[(size_t)n * 16 + 4 + h], h1, l16, h, a1, s1);

    float i1 = 1.f / (s1 + 1e-16f);
    float4 bva = reinterpret_cast<const float4*>(bb)[l16 * 2];
    float4 bvb = reinterpret_cast<const float4*>(bb)[l16 * 2 + 1];
    float bs[8] = {bva.x, bva.y, bva.z, bva.w, bvb.x, bvb.y, bvb.z, bvb.w};
    float o[8];
#pragma unroll
    for (int i = 0; i < 8; i++) {
        float v = a1[i] * i1 + bs[i];
        o[i] = (v < 0.f) ? 0.01f * v : v;
    }
    store_h8(out, n, l16, o);
}

// ---------------------------------------------------------------------------
// Host orchestration
// ---------------------------------------------------------------------------
static inline int gemm_smem(int N) { return (128 * 136 + 128 * (N + 8)) * 2; }

extern "C" void kernel_launch(void* const* d_in, const int* in_sizes, int n_in,
                              void* d_out, int out_size) {
    const float* x_paper  = (const float*)d_in[0];
    const float* x_author = (const float*)d_in[1];
    const float* Wp   = (const float*)d_in[2];
    const float* bp   = (const float*)d_in[3];
    const float* Wa   = (const float*)d_in[4];
    const float* ba   = (const float*)d_in[5];
    const float* W0   = (const float*)d_in[6];
    const float* as0  = (const float*)d_in[7];
    const float* ad0  = (const float*)d_in[8];
    const float* b0   = (const float*)d_in[9];
    const float* W1   = (const float*)d_in[10];
    const float* as1  = (const float*)d_in[11];
    const float* ad1  = (const float*)d_in[12];
    const float* b1   = (const float*)d_in[13];
    const float* Wlin = (const float*)d_in[14];
    const float* blin = (const float*)d_in[15];
    const int* src_c  = (const int*)d_in[16];
    const int* dst_c  = (const int*)d_in[17];
    const int* src_w  = (const int*)d_in[18];
    const int* dst_w  = (const int*)d_in[19];
    const int* src_b  = (const int*)d_in[20];
    const int* dst_b  = (const int*)d_in[21];

    float* S = nullptr;
    cudaGetSymbolAddress((void**)&S, g_scratch);
    __half* Hh = nullptr;
    cudaGetSymbolAddress((void**)&Hh, g_hscratch);
    int* I = nullptr;
    cudaGetSymbolAddress((void**)&I, g_iscratch);

    float*  LP1 = S + O_LP1;
    float*  LP2 = S + O_LP2;
    float*  LA  = S + O_LA;
    __half* XPA = Hh + H_XPA;
    __half* XAA = Hh + H_XAA;
    __half* XPB = Hh + H_XPB;
    __half* XAB = Hh + H_XAB;
    __half* HP0 = Hh + H_HP0;
    __half* HP2 = Hh + H_HP2;
    __half* HA1 = Hh + H_HA1;
    __half* HWP = Hh + H_WP;
    __half* HWA = Hh + H_WA;
    __half* HW0 = Hh + H_W0;
    __half* HW1 = Hh + H_W1;
    __half* HWL = Hh + H_WLIN;
    __half* HV  = Hh + H_V;

    int* DEGS = I + I_DEGS;
    int* OFFS = I + I_OFFS;
    int* CURS = I + I_CURS;
    int* SRCS = I + I_SRCS;
    int* BS   = I + I_BS;

    const int sm144 = gemm_smem(144);
    const int sm128 = gemm_smem(128);
    const int sm64  = gemm_smem(64);
    cudaFuncSetAttribute(mma_gemm<128, 2, false, true,  false, false>, cudaFuncAttributeMaxDynamicSharedMemorySize, sm128);
    cudaFuncSetAttribute(mma_gemm<128, 1, false, true,  false, false>, cudaFuncAttributeMaxDynamicSharedMemorySize, sm128);
    cudaFuncSetAttribute(mma_gemm<144, 1, true,  true,  true,  false>, cudaFuncAttributeMaxDynamicSharedMemorySize, sm144);
    cudaFuncSetAttribute(mma_gemm<144, 1, true,  true,  true,  true >, cudaFuncAttributeMaxDynamicSharedMemorySize, sm144);
    cudaFuncSetAttribute(mma_gemm<64,  1, false, false, true,  false>, cudaFuncAttributeMaxDynamicSharedMemorySize, sm64);

    const int TP = (NPAPER + 127) / 128;
    const int TA = (NAUTHOR + 127) / 128;

    // ---- prep fp16 weights + V + merged CSR build ----
    prep_w_k<<<608, 256>>>(Wp, Wa, W0, W1, Wlin, Hh + H_WP);
    prep_v_k<<<40, 256>>>(W0, as0, ad0, W1, as1, ad1, HV);
    cudaMemsetAsync(DEGS, 0, (size_t)NTOT * sizeof(int));
    hist3_k<<<(ETOT + 255) / 256, 256>>>(dst_c, dst_w, dst_b, DEGS);
    const int NB = (NTOT + 2047) / 2048;  // 245 <= 256
    scanA_k<<<NB, 256>>>(DEGS, OFFS, BS, NTOT);
    scanB_k<<<1, 256>>>(BS, NB);
    scanC_k<<<(NTOT + 255) / 256, 256>>>(OFFS, CURS, BS, NTOT);
    scatter3_k<<<(ETOT + 255) / 256, 256>>>(src_c, dst_c, src_w, dst_w, src_b, dst_b,
                                            CURS, SRCS);

    // ---- input projections (fp32 A in, fp16 W, fp16 X out) ----
    mma_gemm<128, 2, false, true, false, false><<<TP, 256, sm128>>>(
        x_paper, HWP, nullptr, XPA, nullptr,
        nullptr, nullptr, nullptr, nullptr, bp, NPAPER);
    mma_gemm<128, 1, false, true, false, false><<<TA, 256, sm128>>>(
        x_author, HWA, nullptr, XAA, nullptr,
        nullptr, nullptr, nullptr, nullptr, ba, NAUTHOR);

    for (int l = 0; l < 2; l++) {
        const __half* W  = l ? HW1 : HW0;
        const float*  bb = l ? b1 : b0;
        const __half* xp = l ? XPB : XPA;
        const __half* xa = l ? XAB : XAA;

        if (!l) {
            // DUAL: HP0 (+LP1 logits) and HP2 (+LP2 logits) share staged A=xp
            mma_gemm<144, 1, true, true, true, true><<<TP, 256, sm144>>>(
                xp, W + 0 * HID * HID, HV + 0 * 2048, HP0, LP1,
                W + 2 * HID * HID, HV + 2 * 2048, HP2, LP2, nullptr, NPAPER);
        } else {
            mma_gemm<144, 1, true, true, true, false><<<TP, 256, sm144>>>(
                xp, W + 0 * HID * HID, HV + 1 * 2048, HP0, LP1,
                nullptr, nullptr, nullptr, nullptr, nullptr, NPAPER);
        }
        mma_gemm<144, 1, true, true, true, false><<<TA, 256, sm144>>>(
            xa, W + 1 * HID * HID, HV + (l ? 4 : 3) * 2048, HA1, LA,
            nullptr, nullptr, nullptr, nullptr, nullptr, NAUTHOR);

        agg_paper_k<<<(NPAPER * 16 + 255) / 256, 256>>>(
            SRCS, OFFS, DEGS, LP1, HP0, LA, HA1, bb, l ? XPA : XPB, l == 0);
        if (!l)
            agg_author_k<<<(NAUTHOR * 16 + 255) / 256, 256>>>(
                SRCS, OFFS, DEGS, LP2, LA, HP2, bb + 256, XAB);
    }

    // final classifier: [200000,128] fp16 @ [128,64] fp16 + blin -> fp32 out
    mma_gemm<64, 1, false, false, true, false><<<TP, 256, sm64>>>(
        XPA, HWL, nullptr, d_out, nullptr,
        nullptr, nullptr, nullptr, nullptr, blin, NPAPER);
}

// round 14
// speedup vs baseline: 5.3282x; 1.0335x over previous
#include <cuda_runtime.h>
#include <cuda_fp16.h>
#include <cstdint>

// ---------------------------------------------------------------------------
// Problem constants
// ---------------------------------------------------------------------------
static constexpr int NPAPER  = 200000;
static constexpr int NAUTHOR = 100000;
static constexpr int HID     = 128;     // 4 heads x 32 channels
static constexpr int ECITES  = 1000000;
static constexpr int EWRITES = 500000;
static constexpr int EWB     = 500000;
static constexpr int ETOT    = ECITES + EWRITES + EWB;   // 2,000,000
static constexpr int NTOT    = 2 * NPAPER + NAUTHOR;     // 500,000

static constexpr size_t SZ_P = (size_t)NPAPER * HID;
static constexpr size_t SZ_A = (size_t)NAUTHOR * HID;

// float scratch: logits + fp32 V + folded layer-0 biases
static constexpr size_t O_LP1  = 0;
static constexpr size_t O_LP2  = O_LP1 + (size_t)NPAPER * 16;
static constexpr size_t O_LA   = O_LP2 + (size_t)NPAPER * 16;
static constexpr size_t O_VF   = O_LA  + (size_t)NAUTHOR * 16;   // 5 x [128][16] fp32
static constexpr size_t O_BB   = O_VF + 5 * 2048;                // [384] folded L0 biases
static constexpr size_t SCRATCH_FLOATS = O_BB + 384;

__device__ float g_scratch[SCRATCH_FLOATS];

// half scratch
static constexpr size_t H_XPA  = 0;                 // layer-1 paper out / classifier in
static constexpr size_t H_XPB  = H_XPA + SZ_P;      // layer-0 paper out
static constexpr size_t H_XAB  = H_XPB + SZ_P;      // layer-0 author out
static constexpr size_t H_HP0  = H_XAB + SZ_A;
static constexpr size_t H_HP2  = H_HP0 + SZ_P;
static constexpr size_t H_HA1  = H_HP2 + SZ_P;
static constexpr size_t H_W1   = H_HA1 + SZ_A;      // 3 x [128,128] fp16 (layer-1)
static constexpr size_t H_WLIN = H_W1 + 49152;      // [128,64]
static constexpr size_t H_CWP0 = H_WLIN + 8192;     // Wp@W0[0]  [256,128]
static constexpr size_t H_CWP2 = H_CWP0 + 32768;    // Wp@W0[2]  [256,128]
static constexpr size_t H_CWA  = H_CWP2 + 32768;    // Wa@W0[1]  [128,128]
static constexpr size_t H_CV0  = H_CWA + 16384;     // Wp@V_m0   [256,16]
static constexpr size_t H_CV2  = H_CV0 + 4096;      // Wp@V_m2   [256,16]
static constexpr size_t H_CVA  = H_CV2 + 4096;      // Wa@V_m3   [128,16]
static constexpr size_t H_V16  = H_CVA + 2048;      // V m1, m4 fp16 (layer-1)
static constexpr size_t SCRATCH_HALF = H_V16 + 2 * 2048;

__device__ __half g_hscratch[SCRATCH_HALF];

// int scratch: merged CSR
static constexpr size_t I_DEGS = 0;
static constexpr size_t I_OFFS = I_DEGS + NTOT;
static constexpr size_t I_CURS = I_OFFS + NTOT;
static constexpr size_t I_SRCS = I_CURS + NTOT;
static constexpr size_t I_BS   = I_SRCS + ETOT;
static constexpr size_t SCRATCH_INTS = I_BS + 256;

__device__ int g_iscratch[SCRATCH_INTS];

// ---------------------------------------------------------------------------
// fp16 mma + ldmatrix helpers
// ---------------------------------------------------------------------------
__device__ __forceinline__ void mma_f16(float* c, uint32_t a0, uint32_t a1,
                                        uint32_t a2, uint32_t a3,
                                        uint32_t b0, uint32_t b1) {
    asm volatile(
        "mma.sync.aligned.m16n8k16.row.col.f32.f16.f16.f32 "
        "{%0,%1,%2,%3}, {%4,%5,%6,%7}, {%8,%9}, {%0,%1,%2,%3};"
        : "+f"(c[0]), "+f"(c[1]), "+f"(c[2]), "+f"(c[3])
        : "r"(a0), "r"(a1), "r"(a2), "r"(a3), "r"(b0), "r"(b1));
}

__device__ __forceinline__ void ldm_x4(uint32_t* r, uint32_t addr) {
    asm volatile("ldmatrix.sync.aligned.m8n8.x4.shared.b16 {%0,%1,%2,%3}, [%4];"
                 : "=r"(r[0]), "=r"(r[1]), "=r"(r[2]), "=r"(r[3]) : "r"(addr));
}
__device__ __forceinline__ void ldm_x4t(uint32_t* r, uint32_t addr) {
    asm volatile("ldmatrix.sync.aligned.m8n8.x4.trans.shared.b16 {%0,%1,%2,%3}, [%4];"
                 : "=r"(r[0]), "=r"(r[1]), "=r"(r[2]), "=r"(r[3]) : "r"(addr));
}
__device__ __forceinline__ void ldm_x2t(uint32_t* r, uint32_t addr) {
    asm volatile("ldmatrix.sync.aligned.m8n8.x2.trans.shared.b16 {%0,%1}, [%2];"
                 : "=r"(r[0]), "=r"(r[1]) : "r"(addr));
}

// ---------------------------------------------------------------------------
// Prep 1: fp16 conversion of layer-1 weights + classifier.
// ---------------------------------------------------------------------------
__global__ void prep_w_k(const float* __restrict__ W1, const float* __restrict__ Wlin,
                         __half* __restrict__ hw1, __half* __restrict__ hwl) {
    int idx = blockIdx.x * blockDim.x + threadIdx.x;
    if (idx >= 57344) return;
    if (idx < 49152) hw1[idx] = __float2half_rn(W1[idx]);
    else             hwl[idx - 49152] = __float2half_rn(Wlin[idx - 49152]);
}

// ---------------------------------------------------------------------------
// Prep 2: V matrices = W @ att (per head), fp32. 5 x [128][16]:
//  m0: L0 paper  j0-3=W0[0]·as0[0]  j4-7=W0[0]·ad0[0]  j8-11=W0[1]·ad0[1]
//  m1: L1 paper  (W1/as1/ad1)
//  m2: L0 paper2 j0-3=W0[2]·as0[2]
//  m3: L0 author j0-3=W0[1]·as0[1]  j4-7=W0[2]·ad0[2]
//  m4: L1 author j0-3=W1[1]·as1[1]
// ---------------------------------------------------------------------------
__global__ void prep_v_k(const float* __restrict__ W0, const float* __restrict__ as0,
                         const float* __restrict__ ad0, const float* __restrict__ W1,
                         const float* __restrict__ as1, const float* __restrict__ ad1,
                         float* __restrict__ V) {
    int idx = blockIdx.x * blockDim.x + threadIdx.x;
    if (idx >= 5 * 2048) return;
    int m = idx >> 11;
    int r = idx & 2047;
    int k = r >> 4;
    int j = r & 15;
    int h = j & 3;
    int q = j >> 2;

    const float* Wm = nullptr;
    const float* at = nullptr;
    if (m == 0 || m == 1) {
        const float* W  = m ? W1 : W0;
        const float* as_ = m ? as1 : as0;
        const float* ad_ = m ? ad1 : ad0;
        if (q == 0)      { Wm = W;          at = as_; }
        else if (q == 1) { Wm = W;          at = ad_; }
        else if (q == 2) { Wm = W + 16384;  at = ad_ + 128; }
    } else if (m == 2) {
        if (q == 0) { Wm = W0 + 2 * 16384; at = as0 + 256; }
    } else if (m == 3) {
        if (q == 0)      { Wm = W0 + 16384;     at = as0 + 128; }
        else if (q == 1) { Wm = W0 + 2 * 16384; at = ad0 + 256; }
    } else {
        if (q == 0) { Wm = W1 + 16384; at = as1 + 128; }
    }
    float v = 0.f;
    if (Wm) {
#pragma unroll
        for (int c = 0; c < 32; c++)
            v += Wm[k * 128 + h * 32 + c] * at[h * 32 + c];
    }
    V[m * 2048 + k * 16 + j] = v;
}

// ---------------------------------------------------------------------------
// Prep 3: combined layer-0 operators (projection folded).
//  CWP0 = Wp@W0[0], CWP2 = Wp@W0[2] [256,128]; CWA = Wa@W0[1] [128,128];
//  CV0 = Wp@Vm0, CV2 = Wp@Vm2 [256,16]; CVA = Wa@Vm3 [128,16];
//  V16 = fp16(Vm1, Vm4);  BB = folded L0 biases (bias@W + b0).
// ---------------------------------------------------------------------------
__global__ void prep_cw_k(const float* __restrict__ Wp, const float* __restrict__ Wa,
                          const float* __restrict__ W0, const float* __restrict__ bp,
                          const float* __restrict__ ba, const float* __restrict__ b0,
                          const float* __restrict__ Vf,
                          __half* __restrict__ CWP0, __half* __restrict__ CWP2,
                          __half* __restrict__ CWA,  __half* __restrict__ CV0,
                          __half* __restrict__ CV2,  __half* __restrict__ CVA,
                          __half* __restrict__ V16,  float* __restrict__ BB) {
    int idx = blockIdx.x * blockDim.x + threadIdx.x;
    if (idx >= 96640) return;
    if (idx < 32768) {                       // CWP0
        int i = idx >> 7, n = idx & 127;
        float s = 0.f;
        for (int c = 0; c < 128; c++) s += Wp[i * 128 + c] * W0[c * 128 + n];
        CWP0[idx] = __float2half_rn(s);
    } else if (idx < 65536) {                // CWP2
        int r = idx - 32768, i = r >> 7, n = r & 127;
        float s = 0.f;
        for (int c = 0; c < 128; c++) s += Wp[i * 128 + c] * W0[2 * 16384 + c * 128 + n];
        CWP2[r] = __float2half_rn(s);
    } else if (idx < 81920) {                // CWA
        int r = idx - 65536, i = r >> 7, n = r & 127;
        float s = 0.f;
        for (int c = 0; c < 128; c++) s += Wa[i * 128 + c] * W0[16384 + c * 128 + n];
        CWA[r] = __float2half_rn(s);
    } else if (idx < 86016) {                // CV0
        int r = idx - 81920, i = r >> 4, j = r & 15;
        float s = 0.f;
        for (int c = 0; c < 128; c++) s += Wp[i * 128 + c] * Vf[c * 16 + j];
        CV0[r] = __float2half_rn(s);
    } else if (idx < 90112) {                // CV2
        int r = idx - 86016, i = r >> 4, j = r & 15;
        float s = 0.f;
        for (int c = 0; c < 128; c++) s += Wp[i * 128 + c] * Vf[2 * 2048 + c * 16 + j];
        CV2[r] = __float2half_rn(s);
    } else if (idx < 92160) {                // CVA
        int r = idx - 90112, i = r >> 4, j = r & 15;
        float s = 0.f;
        for (int c = 0; c < 128; c++) s += Wa[i * 128 + c] * Vf[3 * 2048 + c * 16 + j];
        CVA[r] = __float2half_rn(s);
    } else if (idx < 94208) {                // V16 m1
        int r = idx - 92160;
        V16[r] = __float2half_rn(Vf[1 * 2048 + r]);
    } else if (idx < 96256) {                // V16 m4
        int r = idx - 94208;
        V16[2048 + r] = __float2half_rn(Vf[4 * 2048 + r]);
    } else {                                 // folded biases BB[384]
        int r = idx - 96256;
        float s;
        if (r < 128) {
            s = b0[r];
            for (int c = 0; c < 128; c++) s += bp[c] * W0[c * 128 + r];
            BB[r] = s;
        } else if (r < 256) {
            int j = r - 128;
            s = b0[128 + j];
            for (int c = 0; c < 128; c++) s += ba[c] * W0[16384 + c * 128 + j];
            BB[r] = s;
        } else {
            int j = r - 256;
            s = b0[256 + j];
            for (int c = 0; c < 128; c++) s += bp[c] * W0[2 * 16384 + c * 128 + j];
            BB[r] = s;
        }
    }
}

// ---------------------------------------------------------------------------
// fp16 mma.sync GEMM (m16n8k16 + ldmatrix), optional DUAL (two B/C pairs
// sharing one staged A; A chunks stay resident across passes).
// ---------------------------------------------------------------------------
template <int N, int KCH, bool VEXT, bool HALF, bool AHALF, bool DUAL>
__global__ void __launch_bounds__(256, 2)
mma_gemm(const void* __restrict__ Av,
         const __half* __restrict__ W1p, const __half* __restrict__ V1,
         void* __restrict__ C1, float* __restrict__ L1,
         const __half* __restrict__ W2p, const __half* __restrict__ V2,
         void* __restrict__ C2, float* __restrict__ L2,
         const float* __restrict__ bias, int M) {
    constexpr int LDA_S = 136;
    constexpr int LDB_S = N + 8;
    constexpr int NF    = N / 16;
    constexpr int KTOT  = KCH * 128;
    constexpr int NC    = VEXT ? N - 16 : N;
    constexpr int ACH   = DUAL ? KCH : 1;   // resident A chunks

    extern __shared__ __half smh[];
    __half* As = smh;                        // [ACH][128][LDA_S]
    __half* Bs = smh + (size_t)ACH * 128 * LDA_S;

    const int tid  = threadIdx.x;
    const int wid  = tid >> 5;
    const int lane = tid & 31;
    const int wm   = wid >> 1;
    const int wn   = wid & 1;
    const int g    = lane >> 2;
    const int tg   = lane & 3;
    const int row0 = blockIdx.x * 128;

    const uint32_t asBase = (uint32_t)__cvta_generic_to_shared(As);
    const uint32_t bsBase = (uint32_t)__cvta_generic_to_shared(Bs);
    const int lrow = (lane & 7) + ((lane >> 3) & 1) * 8;
    const int lcol = (lane >> 4) * 8;

    float acc[2][NF][4];

    for (int pass = 0; pass < (DUAL ? 2 : 1); pass++) {
        const __half* W  = pass ? W2p : W1p;
        const __half* Vx = pass ? V2 : V1;
        void* Cv  = pass ? C2 : C1;
        float* Lb = pass ? L2 : L1;

#pragma unroll
        for (int mf = 0; mf < 2; mf++)
#pragma unroll
            for (int nf = 0; nf < NF; nf++)
#pragma unroll
                for (int j = 0; j < 4; j++) acc[mf][nf][j] = 0.f;

        for (int kc = 0; kc < KCH; kc++) {
            const int k0g = kc * 128;
            const int aslot = DUAL ? kc : 0;
            __half* Asl = As + (size_t)aslot * 128 * LDA_S;
            const uint32_t asB = asBase + (uint32_t)(aslot * 128 * LDA_S * 2);

            if (pass == 0) {
                if (AHALF) {
                    const __half* A = (const __half*)Av;
#pragma unroll
                    for (int i = tid; i < 128 * 16; i += 256) {
                        int r = i >> 4, c8 = i & 15;
                        int gr = row0 + r;
                        uint4 v = make_uint4(0u, 0u, 0u, 0u);
                        if (gr < M)
                            v = *reinterpret_cast<const uint4*>(A + (size_t)gr * KTOT + k0g + c8 * 8);
                        *reinterpret_cast<uint4*>(Asl + r * LDA_S + c8 * 8) = v;
                    }
                } else {
                    const float* A = (const float*)Av;
#pragma unroll
                    for (int i = tid; i < 128 * 32; i += 256) {
                        int r = i >> 5, c4 = i & 31;
                        int gr = row0 + r;
                        float4 v = make_float4(0.f, 0.f, 0.f, 0.f);
                        if (gr < M)
                            v = *reinterpret_cast<const float4*>(A + (size_t)gr * KTOT + k0g + c4 * 4);
                        __half2* dst = reinterpret_cast<__half2*>(Asl + r * LDA_S + c4 * 4);
                        dst[0] = __floats2half2_rn(v.x, v.y);
                        dst[1] = __floats2half2_rn(v.z, v.w);
                    }
                }
            }
            // ---- stage B chunk [128 x N] (pure fp16 copies; Vx row = k0g+k) ----
#pragma unroll
            for (int i = tid; i < 128 * (N / 8); i += 256) {
                int k = i / (N / 8), n8 = i % (N / 8);
                uint4 v;
                if (!VEXT || n8 < NC / 8)
                    v = *reinterpret_cast<const uint4*>(W + (size_t)(k0g + k) * NC + n8 * 8);
                else
                    v = reinterpret_cast<const uint4*>(Vx)[(k0g + k) * 2 + (n8 - NC / 8)];
                *reinterpret_cast<uint4*>(Bs + k * LDB_S + n8 * 8) = v;
            }
            __syncthreads();

            // ---- 8 k-steps of m16n8k16 ----
#pragma unroll
            for (int s = 0; s < 8; s++) {
                const int kk = s * 16;
                uint32_t a[2][4];
#pragma unroll
                for (int mf = 0; mf < 2; mf++) {
                    int row = wm * 32 + mf * 16 + lrow;
                    ldm_x4(a[mf], asB + (uint32_t)(row * LDA_S + kk + lcol) * 2);
                }
                uint32_t b[NF][2];
#pragma unroll
                for (int nf2 = 0; nf2 < NF / 2; nf2++) {
                    int n0 = wn * (N / 2) + nf2 * 16;
                    uint32_t r4[4];
                    ldm_x4t(r4, bsBase + (uint32_t)((kk + lrow) * LDB_S + n0 + lcol) * 2);
                    b[nf2 * 2][0] = r4[0]; b[nf2 * 2][1] = r4[1];
                    b[nf2 * 2 + 1][0] = r4[2]; b[nf2 * 2 + 1][1] = r4[3];
                }
                if (NF & 1) {
                    int n0 = wn * (N / 2) + (NF - 1) * 8;
                    ldm_x2t(b[NF - 1], bsBase + (uint32_t)((kk + lrow) * LDB_S + n0) * 2);
                }
#pragma unroll
                for (int mf = 0; mf < 2; mf++)
#pragma unroll
                    for (int nf = 0; nf < NF; nf++)
                        mma_f16(acc[mf][nf], a[mf][0], a[mf][1], a[mf][2], a[mf][3],
                                b[nf][0], b[nf][1]);
            }
            __syncthreads();
        }

        // ---- epilogue ----
#pragma unroll
        for (int mf = 0; mf < 2; mf++) {
            const int r0 = row0 + wm * 32 + mf * 16 + g;
            const int r1 = r0 + 8;
#pragma unroll
            for (int nf = 0; nf < NF; nf++) {
                const int col = wn * (N / 2) + nf * 8 + tg * 2;
                float c0 = acc[mf][nf][0], c1 = acc[mf][nf][1];
                float c2 = acc[mf][nf][2], c3 = acc[mf][nf][3];
                if (!VEXT || col < NC) {
                    if (bias) {
                        float b0v = bias[col], b1v = bias[col + 1];
                        c0 += b0v; c1 += b1v; c2 += b0v; c3 += b1v;
                    }
                    if (HALF) {
                        __half* C = (__half*)Cv;
                        if (r0 < M)
                            *reinterpret_cast<__half2*>(C + (size_t)r0 * NC + col) =
                                __floats2half2_rn(c0, c1);
                        if (r1 < M)
                            *reinterpret_cast<__half2*>(C + (size_t)r1 * NC + col) =
                                __floats2half2_rn(c2, c3);
                    } else {
                        float* C = (float*)Cv;
                        if (r0 < M)
                            *reinterpret_cast<float2*>(C + (size_t)r0 * NC + col) = make_float2(c0, c1);
                        if (r1 < M)
                            *reinterpret_cast<float2*>(C + (size_t)r1 * NC + col) = make_float2(c2, c3);
                    }
                } else {
                    const int lc = col - NC;
                    if (r0 < M)
                        *reinterpret_cast<float2*>(Lb + (size_t)r0 * 16 + lc) = make_float2(c0, c1);
                    if (r1 < M)
                        *reinterpret_cast<float2*>(Lb + (size_t)r1 * 16 + lc) = make_float2(c2, c3);
                }
            }
        }
        if (DUAL && pass == 0) __syncthreads();
    }
}

// ---------------------------------------------------------------------------
// Merged CSR build
// ---------------------------------------------------------------------------
__global__ void hist3_k(const int* __restrict__ dc, const int* __restrict__ dw,
                        const int* __restrict__ db, int* __restrict__ degs) {
    int e = blockIdx.x * blockDim.x + threadIdx.x;
    if (e >= ETOT) return;
    int slot;
    if (e < ECITES)                slot = dc[e];
    else if (e < ECITES + EWRITES) slot = NPAPER + dw[e - ECITES];
    else                           slot = 2 * NPAPER + db[e - ECITES - EWRITES];
    atomicAdd(&degs[slot], 1);
}

__global__ void scanA_k(const int* __restrict__ deg, int* __restrict__ off,
                        int* __restrict__ bsum, int n) {
    __shared__ int sh[256];
    const int t = threadIdx.x, b = blockIdx.x;
    const int base = b * 2048 + t * 8;
    int v[8], s = 0;
#pragma unroll
    for (int i = 0; i < 8; i++) {
        int idx = base + i;
        v[i] = (idx < n) ? deg[idx] : 0;
        s += v[i];
    }
    sh[t] = s;
    __syncthreads();
    for (int o = 1; o < 256; o <<= 1) {
        int y = (t >= o) ? sh[t - o] : 0;
        __syncthreads();
        sh[t] += y;
        __syncthreads();
    }
    int run = sh[t] - s;
    if (t == 255) bsum[b] = sh[255];
#pragma unroll
    for (int i = 0; i < 8; i++) {
        int idx = base + i;
        if (idx < n) off[idx] = run;
        run += v[i];
    }
}

__global__ void scanB_k(int* __restrict__ bsum, int nb) {
    __shared__ int sh[256];
    int t = threadIdx.x;
    int v = (t < nb) ? bsum[t] : 0;
    sh[t] = v;
    __syncthreads();
    for (int o = 1; o < 256; o <<= 1) {
        int y = (t >= o) ? sh[t - o] : 0;
        __syncthreads();
        sh[t] += y;
        __syncthreads();
    }
    if (t < nb) bsum[t] = sh[t] - v;
}

__global__ void scanC_k(int* __restrict__ off, int* __restrict__ cur,
                        const int* __restrict__ bsum, int n) {
    int i = blockIdx.x * blockDim.x + threadIdx.x;
    if (i >= n) return;
    int v = off[i] + bsum[i >> 11];
    off[i] = v;
    cur[i] = v;
}

__global__ void scatter3_k(const int* __restrict__ sc, const int* __restrict__ dc,
                           const int* __restrict__ sw, const int* __restrict__ dw,
                           const int* __restrict__ sb, const int* __restrict__ db,
                           int* __restrict__ curs, int* __restrict__ srcs) {
    int e = blockIdx.x * blockDim.x + threadIdx.x;
    if (e >= ETOT) return;
    int slot, sv;
    if (e < ECITES)                { slot = dc[e]; sv = sc[e]; }
    else if (e < ECITES + EWRITES) { int i = e - ECITES; slot = NPAPER + dw[i]; sv = sw[i]; }
    else                           { int i = e - ECITES - EWRITES; slot = 2 * NPAPER + db[i]; sv = sb[i]; }
    srcs[atomicAdd(&curs[slot], 1)] = sv;
}

// ---------------------------------------------------------------------------
// Dst-major GAT aggregation: 2 nodes per warp, lane owns 8 channels (uint4).
// ---------------------------------------------------------------------------
__device__ __forceinline__ float lrelu02(float v) { return v > 0.f ? v : 0.2f * v; }

struct F8 { float v[8]; };

__device__ __forceinline__ F8 gather_h8(const __half* __restrict__ hbuf,
                                        int sidx, int l16) {
    uint4 u = reinterpret_cast<const uint4*>(hbuf + (size_t)sidx * HID)[l16];
    F8 r;
    const uint32_t* p = &u.x;
#pragma unroll
    for (int i = 0; i < 4; i++) {
        __half2 h2 = *reinterpret_cast<const __half2*>(&p[i]);
        float2 f = __half22float2(h2);
        r.v[2 * i] = f.x;
        r.v[2 * i + 1] = f.y;
    }
    return r;
}

__device__ __forceinline__ void agg_rel(const int* __restrict__ srcs, int st, int d,
                                        const float* __restrict__ Lsrc, float ad,
                                        const __half* __restrict__ hbuf,
                                        int l16, int h, float* a, float& s) {
    int j = 0;
    for (; j + 2 <= d; j += 2) {
        int s0 = srcs[st + j];
        int s1 = srcs[st + j + 1];
        float l0 = Lsrc[(size_t)s0 * 16 + h];
        float l1 = Lsrc[(size_t)s1 * 16 + h];
        F8 h0 = gather_h8(hbuf, s0, l16);
        F8 h1 = gather_h8(hbuf, s1, l16);
        float x0 = __expf(lrelu02(l0 + ad));
        float x1 = __expf(lrelu02(l1 + ad));
        s += x0 + x1;
#pragma unroll
        for (int i = 0; i < 8; i++) a[i] += x0 * h0.v[i] + x1 * h1.v[i];
    }
    if (j < d) {
        int s0 = srcs[st + j];
        float x0 = __expf(lrelu02(Lsrc[(size_t)s0 * 16 + h] + ad));
        F8 h0 = gather_h8(hbuf, s0, l16);
        s += x0;
#pragma unroll
        for (int i = 0; i < 8; i++) a[i] += x0 * h0.v[i];
    }
}

__device__ __forceinline__ void store_h8(__half* __restrict__ out, int n, int l16,
                                         const float* o) {
    uint4 u;
    uint32_t* p = &u.x;
#pragma unroll
    for (int i = 0; i < 4; i++) {
        __half2 h2 = __floats2half2_rn(o[2 * i], o[2 * i + 1]);
        p[i] = *reinterpret_cast<uint32_t*>(&h2);
    }
    reinterpret_cast<uint4*>(out + (size_t)n * HID)[l16] = u;
}

__global__ void agg_paper_k(
    const int* __restrict__ srcs, const int* __restrict__ offs, const int* __restrict__ degs,
    const float* __restrict__ LP1, const __half* __restrict__ h1,
    const float* __restrict__ LA,  const __half* __restrict__ h2,
    const float* __restrict__ bb, __half* __restrict__ out, int act) {
    const int gid  = blockIdx.x * blockDim.x + threadIdx.x;
    const int lane = threadIdx.x & 31;
    const int l16  = lane & 15;
    const int n    = ((gid >> 5) << 1) + (lane >> 4);
    if (n >= NPAPER) return;
    const int h = l16 >> 2;

    float a1[8] = {0, 0, 0, 0, 0, 0, 0, 0};
    float s1 = 0.f;
    agg_rel(srcs, offs[n], degs[n], LP1, LP1[(size_t)n * 16 + 4 + h], h1, l16, h, a1, s1);

    float a2[8] = {0, 0, 0, 0, 0, 0, 0, 0};
    float s2 = 0.f;
    agg_rel(srcs, offs[NPAPER + n], degs[NPAPER + n], LA, LP1[(size_t)n * 16 + 8 + h],
            h2, l16, h, a2, s2);

    float i1 = 1.f / (s1 + 1e-16f);
    float i2 = 1.f / (s2 + 1e-16f);
    float4 bv1a = reinterpret_cast<const float4*>(bb)[l16 * 2];
    float4 bv1b = reinterpret_cast<const float4*>(bb)[l16 * 2 + 1];
    float4 bv2a = reinterpret_cast<const float4*>(bb + 128)[l16 * 2];
    float4 bv2b = reinterpret_cast<const float4*>(bb + 128)[l16 * 2 + 1];
    float bsum[8] = {bv1a.x + bv2a.x, bv1a.y + bv2a.y, bv1a.z + bv2a.z, bv1a.w + bv2a.w,
                     bv1b.x + bv2b.x, bv1b.y + bv2b.y, bv1b.z + bv2b.z, bv1b.w + bv2b.w};
    float o[8];
#pragma unroll
    for (int i = 0; i < 8; i++) {
        float v = a1[i] * i1 + a2[i] * i2 + bsum[i];
        o[i] = (act && v < 0.f) ? 0.01f * v : v;
    }
    store_h8(out, n, l16, o);
}

__global__ void agg_author_k(
    const int* __restrict__ srcs, const int* __restrict__ offs, const int* __restrict__ degs,
    const float* __restrict__ LP2, const float* __restrict__ LA,
    const __half* __restrict__ h1, const float* __restrict__ bb,
    __half* __restrict__ out) {
    const int gid  = blockIdx.x * blockDim.x + threadIdx.x;
    const int lane = threadIdx.x & 31;
    const int l16  = lane & 15;
    const int n    = ((gid >> 5) << 1) + (lane >> 4);
    if (n >= NAUTHOR) return;
    const int h = l16 >> 2;

    float a1[8] = {0, 0, 0, 0, 0, 0, 0, 0};
    float s1 = 0.f;
    agg_rel(srcs, offs[2 * NPAPER + n], degs[2 * NPAPER + n], LP2,
            LA[(size_t)n * 16 + 4 + h], h1, l16, h, a1, s1);

    float i1 = 1.f / (s1 + 1e-16f);
    float4 bva = reinterpret_cast<const float4*>(bb)[l16 * 2];
    float4 bvb = reinterpret_cast<const float4*>(bb)[l16 * 2 + 1];
    float bs[8] = {bva.x, bva.y, bva.z, bva.w, bvb.x, bvb.y, bvb.z, bvb.w};
    float o[8];
#pragma unroll
    for (int i = 0; i < 8; i++) {
        float v = a1[i] * i1 + bs[i];
        o[i] = (v < 0.f) ? 0.01f * v : v;
    }
    store_h8(out, n, l16, o);
}

// ---------------------------------------------------------------------------
// Host orchestration
// ---------------------------------------------------------------------------
static inline int gemm_smem(int N, int ach) {
    return (ach * 128 * 136 + 128 * (N + 8)) * 2;
}

extern "C" void kernel_launch(void* const* d_in, const int* in_sizes, int n_in,
                              void* d_out, int out_size) {
    const float* x_paper  = (const float*)d_in[0];
    const float* x_author = (const float*)d_in[1];
    const float* Wp   = (const float*)d_in[2];
    const float* bp   = (const float*)d_in[3];
    const float* Wa   = (const float*)d_in[4];
    const float* ba   = (const float*)d_in[5];
    const float* W0   = (const float*)d_in[6];
    const float* as0  = (const float*)d_in[7];
    const float* ad0  = (const float*)d_in[8];
    const float* b0   = (const float*)d_in[9];
    const float* W1   = (const float*)d_in[10];
    const float* as1  = (const float*)d_in[11];
    const float* ad1  = (const float*)d_in[12];
    const float* b1   = (const float*)d_in[13];
    const float* Wlin = (const float*)d_in[14];
    const float* blin = (const float*)d_in[15];
    const int* src_c  = (const int*)d_in[16];
    const int* dst_c  = (const int*)d_in[17];
    const int* src_w  = (const int*)d_in[18];
    const int* dst_w  = (const int*)d_in[19];
    const int* src_b  = (const int*)d_in[20];
    const int* dst_b  = (const int*)d_in[21];

    float* S = nullptr;
    cudaGetSymbolAddress((void**)&S, g_scratch);
    __half* Hh = nullptr;
    cudaGetSymbolAddress((void**)&Hh, g_hscratch);
    int* I = nullptr;
    cudaGetSymbolAddress((void**)&I, g_iscratch);

    float*  LP1 = S + O_LP1;
    float*  LP2 = S + O_LP2;
    float*  LA  = S + O_LA;
    float*  VF  = S + O_VF;
    float*  BB  = S + O_BB;
    __half* XPA = Hh + H_XPA;
    __half* XPB = Hh + H_XPB;
    __half* XAB = Hh + H_XAB;
    __half* HP0 = Hh + H_HP0;
    __half* HP2 = Hh + H_HP2;
    __half* HA1 = Hh + H_HA1;
    __half* HW1 = Hh + H_W1;
    __half* HWL = Hh + H_WLIN;
    __half* CWP0 = Hh + H_CWP0;
    __half* CWP2 = Hh + H_CWP2;
    __half* CWA  = Hh + H_CWA;
    __half* CV0  = Hh + H_CV0;
    __half* CV2  = Hh + H_CV2;
    __half* CVA  = Hh + H_CVA;
    __half* V16  = Hh + H_V16;

    int* DEGS = I + I_DEGS;
    int* OFFS = I + I_OFFS;
    int* CURS = I + I_CURS;
    int* SRCS = I + I_SRCS;
    int* BS   = I + I_BS;

    const int smDual = gemm_smem(144, 2);   // 108,544 B
    const int sm144  = gemm_smem(144, 1);
    const int sm64   = gemm_smem(64, 1);
    cudaFuncSetAttribute(mma_gemm<144, 2, true,  true,  false, true >, cudaFuncAttributeMaxDynamicSharedMemorySize, smDual);
    cudaFuncSetAttribute(mma_gemm<144, 1, true,  true,  false, false>, cudaFuncAttributeMaxDynamicSharedMemorySize, sm144);
    cudaFuncSetAttribute(mma_gemm<144, 1, true,  true,  true,  false>, cudaFuncAttributeMaxDynamicSharedMemorySize, sm144);
    cudaFuncSetAttribute(mma_gemm<64,  1, false, false, true,  false>, cudaFuncAttributeMaxDynamicSharedMemorySize, sm64);

    const int TP = (NPAPER + 127) / 128;
    const int TA = (NAUTHOR + 127) / 128;

    // ---- prep: fp16 W1/Wlin, fp32 V, combined L0 operators, merged CSR ----
    prep_w_k<<<224, 256>>>(W1, Wlin, HW1, HWL);
    prep_v_k<<<40, 256>>>(W0, as0, ad0, W1, as1, ad1, VF);
    prep_cw_k<<<378, 256>>>(Wp, Wa, W0, bp, ba, b0, VF,
                            CWP0, CWP2, CWA, CV0, CV2, CVA, V16, BB);
    cudaMemsetAsync(DEGS, 0, (size_t)NTOT * sizeof(int));
    hist3_k<<<(ETOT + 255) / 256, 256>>>(dst_c, dst_w, dst_b, DEGS);
    const int NB = (NTOT + 2047) / 2048;
    scanA_k<<<NB, 256>>>(DEGS, OFFS, BS, NTOT);
    scanB_k<<<1, 256>>>(BS, NB);
    scanC_k<<<(NTOT + 255) / 256, 256>>>(OFFS, CURS, BS, NTOT);
    scatter3_k<<<(ETOT + 255) / 256, 256>>>(src_c, dst_c, src_w, dst_w, src_b, dst_b,
                                            CURS, SRCS);

    // ---- layer 0 (projection folded): A = raw fp32 inputs ----
    // paper DUAL: x_paper @ CWP0 -> HP0,LP1 ; x_paper @ CWP2 -> HP2,LP2
    mma_gemm<144, 2, true, true, false, true><<<TP, 256, smDual>>>(
        x_paper, CWP0, CV0, HP0, LP1, CWP2, CV2, HP2, LP2, nullptr, NPAPER);
    // author: x_author @ CWA -> HA1,LA
    mma_gemm<144, 1, true, true, false, false><<<TA, 256, sm144>>>(
        x_author, CWA, CVA, HA1, LA,
        nullptr, nullptr, nullptr, nullptr, nullptr, NAUTHOR);

    agg_paper_k<<<(NPAPER * 16 + 255) / 256, 256>>>(
        SRCS, OFFS, DEGS, LP1, HP0, LA, HA1, BB, XPB, 1);
    agg_author_k<<<(NAUTHOR * 16 + 255) / 256, 256>>>(
        SRCS, OFFS, DEGS, LP2, LA, HP2, BB + 256, XAB);

    // ---- layer 1 ----
    mma_gemm<144, 1, true, true, true, false><<<TP, 256, sm144>>>(
        XPB, HW1 + 0 * HID * HID, V16 + 0 * 2048, HP0, LP1,
        nullptr, nullptr, nullptr, nullptr, nullptr, NPAPER);
    mma_gemm<144, 1, true, true, true, false><<<TA, 256, sm144>>>(
        XAB, HW1 + 1 * HID * HID, V16 + 1 * 2048, HA1, LA,
        nullptr, nullptr, nullptr, nullptr, nullptr, NAUTHOR);

    agg_paper_k<<<(NPAPER * 16 + 255) / 256, 256>>>(
        SRCS, OFFS, DEGS, LP1, HP0, LA, HA1, b1, XPA, 0);

    // ---- classifier: [200000,128] fp16 @ [128,64] fp16 + blin -> fp32 out ----
    mma_gemm<64, 1, false, false, true, false><<<TP, 256, sm64>>>(
        XPA, HWL, nullptr, d_out, nullptr,
        nullptr, nullptr, nullptr, nullptr, blin, NPAPER);
}

// round 15
// speedup vs baseline: 5.5263x; 1.0372x over previous
#include <cuda_runtime.h>
#include <cuda_fp16.h>
#include <cstdint>

// ---------------------------------------------------------------------------
// Problem constants
// ---------------------------------------------------------------------------
static constexpr int NPAPER  = 200000;
static constexpr int NAUTHOR = 100000;
static constexpr int HID     = 128;     // 4 heads x 32 channels
static constexpr int ECITES  = 1000000;
static constexpr int EWRITES = 500000;
static constexpr int EWB     = 500000;
static constexpr int ETOT    = ECITES + EWRITES + EWB;   // 2,000,000
static constexpr int NTOT    = 2 * NPAPER + NAUTHOR;     // 500,000

static constexpr size_t SZ_P = (size_t)NPAPER * HID;
static constexpr size_t SZ_A = (size_t)NAUTHOR * HID;

// float scratch: logits + fp32 V + folded layer-0 biases
static constexpr size_t O_LP1  = 0;
static constexpr size_t O_LP2  = O_LP1 + (size_t)NPAPER * 16;
static constexpr size_t O_LA   = O_LP2 + (size_t)NPAPER * 16;
static constexpr size_t O_VF   = O_LA  + (size_t)NAUTHOR * 16;   // 5 x [128][16] fp32
static constexpr size_t O_BB   = O_VF + 5 * 2048;                // [384] folded L0 biases
static constexpr size_t SCRATCH_FLOATS = O_BB + 384;

__device__ float g_scratch[SCRATCH_FLOATS];

// half scratch
static constexpr size_t H_XPA  = 0;                 // layer-1 paper out / classifier in
static constexpr size_t H_XPB  = H_XPA + SZ_P;      // layer-0 paper out
static constexpr size_t H_XAB  = H_XPB + SZ_P;      // layer-0 author out
static constexpr size_t H_HP0  = H_XAB + SZ_A;
static constexpr size_t H_HP2  = H_HP0 + SZ_P;
static constexpr size_t H_HA1  = H_HP2 + SZ_P;
static constexpr size_t H_W1   = H_HA1 + SZ_A;      // 3 x [128,128] fp16 (layer-1)
static constexpr size_t H_WLIN = H_W1 + 49152;      // [128,64]
static constexpr size_t H_CWP0 = H_WLIN + 8192;     // Wp@W0[0]  [256,128]
static constexpr size_t H_CWP2 = H_CWP0 + 32768;    // Wp@W0[2]  [256,128]
static constexpr size_t H_CWA  = H_CWP2 + 32768;    // Wa@W0[1]  [128,128]
static constexpr size_t H_CV0  = H_CWA + 16384;     // Wp@V_m0   [256,16]
static constexpr size_t H_CV2  = H_CV0 + 4096;      // Wp@V_m2   [256,16]
static constexpr size_t H_CVA  = H_CV2 + 4096;      // Wa@V_m3   [128,16]
static constexpr size_t H_V16  = H_CVA + 2048;      // V m1, m4 fp16 (layer-1)
static constexpr size_t SCRATCH_HALF = H_V16 + 2 * 2048;

__device__ __half g_hscratch[SCRATCH_HALF];

// int scratch: merged CSR
static constexpr size_t I_DEGS = 0;
static constexpr size_t I_OFFS = I_DEGS + NTOT;
static constexpr size_t I_CURS = I_OFFS + NTOT;
static constexpr size_t I_SRCS = I_CURS + NTOT;
static constexpr size_t I_BS   = I_SRCS + ETOT;
static constexpr size_t SCRATCH_INTS = I_BS + 256;

__device__ int g_iscratch[SCRATCH_INTS];

// ---------------------------------------------------------------------------
// fp16 mma + ldmatrix + cp.async helpers (sm_80+ PTX)
// ---------------------------------------------------------------------------
__device__ __forceinline__ void mma_f16(float* c, uint32_t a0, uint32_t a1,
                                        uint32_t a2, uint32_t a3,
                                        uint32_t b0, uint32_t b1) {
    asm volatile(
        "mma.sync.aligned.m16n8k16.row.col.f32.f16.f16.f32 "
        "{%0,%1,%2,%3}, {%4,%5,%6,%7}, {%8,%9}, {%0,%1,%2,%3};"
        : "+f"(c[0]), "+f"(c[1]), "+f"(c[2]), "+f"(c[3])
        : "r"(a0), "r"(a1), "r"(a2), "r"(a3), "r"(b0), "r"(b1));
}

__device__ __forceinline__ void ldm_x4(uint32_t* r, uint32_t addr) {
    asm volatile("ldmatrix.sync.aligned.m8n8.x4.shared.b16 {%0,%1,%2,%3}, [%4];"
                 : "=r"(r[0]), "=r"(r[1]), "=r"(r[2]), "=r"(r[3]) : "r"(addr));
}
__device__ __forceinline__ void ldm_x4t(uint32_t* r, uint32_t addr) {
    asm volatile("ldmatrix.sync.aligned.m8n8.x4.trans.shared.b16 {%0,%1,%2,%3}, [%4];"
                 : "=r"(r[0]), "=r"(r[1]), "=r"(r[2]), "=r"(r[3]) : "r"(addr));
}
__device__ __forceinline__ void ldm_x2t(uint32_t* r, uint32_t addr) {
    asm volatile("ldmatrix.sync.aligned.m8n8.x2.trans.shared.b16 {%0,%1}, [%2];"
                 : "=r"(r[0]), "=r"(r[1]) : "r"(addr));
}

__device__ __forceinline__ void cp16_zfill(uint32_t daddr, const void* g, int sz) {
    asm volatile("cp.async.cg.shared.global [%0], [%1], 16, %2;"
                 :: "r"(daddr), "l"(g), "r"(sz));
}
__device__ __forceinline__ void cp16(uint32_t daddr, const void* g) {
    asm volatile("cp.async.ca.shared.global [%0], [%1], 16;"
                 :: "r"(daddr), "l"(g));
}
__device__ __forceinline__ void cp_wait_all() {
    asm volatile("cp.async.commit_group;");
    asm volatile("cp.async.wait_group 0;");
}

// ---------------------------------------------------------------------------
// Prep 1: fp16 conversion of layer-1 weights + classifier.
// ---------------------------------------------------------------------------
__global__ void prep_w_k(const float* __restrict__ W1, const float* __restrict__ Wlin,
                         __half* __restrict__ hw1, __half* __restrict__ hwl) {
    int idx = blockIdx.x * blockDim.x + threadIdx.x;
    if (idx >= 57344) return;
    if (idx < 49152) hw1[idx] = __float2half_rn(W1[idx]);
    else             hwl[idx - 49152] = __float2half_rn(Wlin[idx - 49152]);
}

// ---------------------------------------------------------------------------
// Prep 2: V matrices = W @ att (per head), fp32. 5 x [128][16] (see R7/R14).
// ---------------------------------------------------------------------------
__global__ void prep_v_k(const float* __restrict__ W0, const float* __restrict__ as0,
                         const float* __restrict__ ad0, const float* __restrict__ W1,
                         const float* __restrict__ as1, const float* __restrict__ ad1,
                         float* __restrict__ V) {
    int idx = blockIdx.x * blockDim.x + threadIdx.x;
    if (idx >= 5 * 2048) return;
    int m = idx >> 11;
    int r = idx & 2047;
    int k = r >> 4;
    int j = r & 15;
    int h = j & 3;
    int q = j >> 2;

    const float* Wm = nullptr;
    const float* at = nullptr;
    if (m == 0 || m == 1) {
        const float* W  = m ? W1 : W0;
        const float* as_ = m ? as1 : as0;
        const float* ad_ = m ? ad1 : ad0;
        if (q == 0)      { Wm = W;          at = as_; }
        else if (q == 1) { Wm = W;          at = ad_; }
        else if (q == 2) { Wm = W + 16384;  at = ad_ + 128; }
    } else if (m == 2) {
        if (q == 0) { Wm = W0 + 2 * 16384; at = as0 + 256; }
    } else if (m == 3) {
        if (q == 0)      { Wm = W0 + 16384;     at = as0 + 128; }
        else if (q == 1) { Wm = W0 + 2 * 16384; at = ad0 + 256; }
    } else {
        if (q == 0) { Wm = W1 + 16384; at = as1 + 128; }
    }
    float v = 0.f;
    if (Wm) {
#pragma unroll
        for (int c = 0; c < 32; c++)
            v += Wm[k * 128 + h * 32 + c] * at[h * 32 + c];
    }
    V[m * 2048 + k * 16 + j] = v;
}

// ---------------------------------------------------------------------------
// Prep 3: combined layer-0 operators (projection folded). See R14.
// ---------------------------------------------------------------------------
__global__ void prep_cw_k(const float* __restrict__ Wp, const float* __restrict__ Wa,
                          const float* __restrict__ W0, const float* __restrict__ bp,
                          const float* __restrict__ ba, const float* __restrict__ b0,
                          const float* __restrict__ Vf,
                          __half* __restrict__ CWP0, __half* __restrict__ CWP2,
                          __half* __restrict__ CWA,  __half* __restrict__ CV0,
                          __half* __restrict__ CV2,  __half* __restrict__ CVA,
                          __half* __restrict__ V16,  float* __restrict__ BB) {
    int idx = blockIdx.x * blockDim.x + threadIdx.x;
    if (idx >= 96640) return;
    if (idx < 32768) {
        int i = idx >> 7, n = idx & 127;
        float s = 0.f;
        for (int c = 0; c < 128; c++) s += Wp[i * 128 + c] * W0[c * 128 + n];
        CWP0[idx] = __float2half_rn(s);
    } else if (idx < 65536) {
        int r = idx - 32768, i = r >> 7, n = r & 127;
        float s = 0.f;
        for (int c = 0; c < 128; c++) s += Wp[i * 128 + c] * W0[2 * 16384 + c * 128 + n];
        CWP2[r] = __float2half_rn(s);
    } else if (idx < 81920) {
        int r = idx - 65536, i = r >> 7, n = r & 127;
        float s = 0.f;
        for (int c = 0; c < 128; c++) s += Wa[i * 128 + c] * W0[16384 + c * 128 + n];
        CWA[r] = __float2half_rn(s);
    } else if (idx < 86016) {
        int r = idx - 81920, i = r >> 4, j = r & 15;
        float s = 0.f;
        for (int c = 0; c < 128; c++) s += Wp[i * 128 + c] * Vf[c * 16 + j];
        CV0[r] = __float2half_rn(s);
    } else if (idx < 90112) {
        int r = idx - 86016, i = r >> 4, j = r & 15;
        float s = 0.f;
        for (int c = 0; c < 128; c++) s += Wp[i * 128 + c] * Vf[2 * 2048 + c * 16 + j];
        CV2[r] = __float2half_rn(s);
    } else if (idx < 92160) {
        int r = idx - 90112, i = r >> 4, j = r & 15;
        float s = 0.f;
        for (int c = 0; c < 128; c++) s += Wa[i * 128 + c] * Vf[3 * 2048 + c * 16 + j];
        CVA[r] = __float2half_rn(s);
    } else if (idx < 94208) {
        int r = idx - 92160;
        V16[r] = __float2half_rn(Vf[1 * 2048 + r]);
    } else if (idx < 96256) {
        int r = idx - 94208;
        V16[2048 + r] = __float2half_rn(Vf[4 * 2048 + r]);
    } else {
        int r = idx - 96256;
        float s;
        if (r < 128) {
            s = b0[r];
            for (int c = 0; c < 128; c++) s += bp[c] * W0[c * 128 + r];
            BB[r] = s;
        } else if (r < 256) {
            int j = r - 128;
            s = b0[128 + j];
            for (int c = 0; c < 128; c++) s += ba[c] * W0[16384 + c * 128 + j];
            BB[r] = s;
        } else {
            int j = r - 256;
            s = b0[256 + j];
            for (int c = 0; c < 128; c++) s += bp[c] * W0[2 * 16384 + c * 128 + j];
            BB[r] = s;
        }
    }
}

// ---------------------------------------------------------------------------
// fp16 mma.sync GEMM (m16n8k16 + ldmatrix + cp.async staging).
// DUAL: two B/C pairs share one staged A (A chunks resident).
// PAIR: blocks >= gridA run a second independent problem (Avb/Mb with the
//       W2p/V2/C2/L2 parameter slots). DUAL and PAIR are mutually exclusive.
// ---------------------------------------------------------------------------
template <int N, int KCH, bool VEXT, bool HALF, bool AHALF, bool DUAL, bool PAIR>
__global__ void __launch_bounds__(256, 2)
mma_gemm(const void* __restrict__ Av_,
         const __half* __restrict__ W1p_, const __half* __restrict__ V1_,
         void* __restrict__ C1_, float* __restrict__ L1_,
         const __half* __restrict__ W2p, const __half* __restrict__ V2,
         void* __restrict__ C2, float* __restrict__ L2,
         const float* __restrict__ bias, int M_,
         const void* __restrict__ Avb, int Mb, int gridA) {
    constexpr int LDA_S = 136;
    constexpr int LDB_S = N + 8;
    constexpr int NF    = N / 16;
    constexpr int KTOT  = KCH * 128;
    constexpr int NC    = VEXT ? N - 16 : N;
    constexpr int ACH   = DUAL ? KCH : 1;

    extern __shared__ __half smh[];
    __half* As = smh;                        // [ACH][128][LDA_S]
    __half* Bs = smh + (size_t)ACH * 128 * LDA_S;

    const int tid  = threadIdx.x;
    const int wid  = tid >> 5;
    const int lane = tid & 31;
    const int wm   = wid >> 1;
    const int wn   = wid & 1;
    const int g    = lane >> 2;
    const int tg   = lane & 3;

    // problem selection (PAIR)
    const void* Av = Av_;
    const __half* Wsel = W1p_;
    const __half* Vsel = V1_;
    void* Csel = C1_;
    float* Lsel = L1_;
    int M = M_;
    int row0;
    if (PAIR && blockIdx.x >= gridA) {
        Av = Avb; Wsel = W2p; Vsel = V2; Csel = C2; Lsel = L2; M = Mb;
        row0 = (blockIdx.x - gridA) * 128;
    } else {
        row0 = blockIdx.x * 128;
    }

    const uint32_t asBase = (uint32_t)__cvta_generic_to_shared(As);
    const uint32_t bsBase = (uint32_t)__cvta_generic_to_shared(Bs);
    const int lrow = (lane & 7) + ((lane >> 3) & 1) * 8;
    const int lcol = (lane >> 4) * 8;

    float acc[2][NF][4];

    for (int pass = 0; pass < (DUAL ? 2 : 1); pass++) {
        const __half* W  = pass ? W2p : Wsel;
        const __half* Vx = pass ? V2 : Vsel;
        void* Cv  = pass ? C2 : Csel;
        float* Lb = pass ? L2 : Lsel;

#pragma unroll
        for (int mf = 0; mf < 2; mf++)
#pragma unroll
            for (int nf = 0; nf < NF; nf++)
#pragma unroll
                for (int j = 0; j < 4; j++) acc[mf][nf][j] = 0.f;

        for (int kc = 0; kc < KCH; kc++) {
            const int k0g = kc * 128;
            const int aslot = DUAL ? kc : 0;
            __half* Asl = As + (size_t)aslot * 128 * LDA_S;
            const uint32_t asB = asBase + (uint32_t)(aslot * 128 * LDA_S * 2);

            // ---- stage B chunk via cp.async (pure fp16 copies) ----
#pragma unroll
            for (int i = tid; i < 128 * (N / 8); i += 256) {
                int k = i / (N / 8), n8 = i % (N / 8);
                const void* gsrc;
                if (!VEXT || n8 < NC / 8)
                    gsrc = W + (size_t)(k0g + k) * NC + n8 * 8;
                else
                    gsrc = Vx + (size_t)((k0g + k) * 2 + (n8 - NC / 8)) * 8;
                cp16(bsBase + (uint32_t)(k * LDB_S + n8 * 8) * 2, gsrc);
            }
            // ---- stage A chunk ----
            if (pass == 0) {
                if (AHALF) {
                    const __half* A = (const __half*)Av;
#pragma unroll
                    for (int i = tid; i < 128 * 16; i += 256) {
                        int r = i >> 4, c8 = i & 15;
                        int gr = row0 + r;
                        const void* gsrc = A + (size_t)(gr < M ? gr : 0) * KTOT + k0g + c8 * 8;
                        cp16_zfill(asB + (uint32_t)(r * LDA_S + c8 * 8) * 2, gsrc,
                                   (gr < M) ? 16 : 0);
                    }
                } else {
                    const float* A = (const float*)Av;
#pragma unroll
                    for (int i = tid; i < 128 * 32; i += 256) {
                        int r = i >> 5, c4 = i & 31;
                        int gr = row0 + r;
                        float4 v = make_float4(0.f, 0.f, 0.f, 0.f);
                        if (gr < M)
                            v = *reinterpret_cast<const float4*>(A + (size_t)gr * KTOT + k0g + c4 * 4);
                        __half2* dst = reinterpret_cast<__half2*>(Asl + r * LDA_S + c4 * 4);
                        dst[0] = __floats2half2_rn(v.x, v.y);
                        dst[1] = __floats2half2_rn(v.z, v.w);
                    }
                }
            }
            cp_wait_all();
            __syncthreads();

            // ---- 8 k-steps of m16n8k16 ----
#pragma unroll
            for (int s = 0; s < 8; s++) {
                const int kk = s * 16;
                uint32_t a[2][4];
#pragma unroll
                for (int mf = 0; mf < 2; mf++) {
                    int row = wm * 32 + mf * 16 + lrow;
                    ldm_x4(a[mf], asB + (uint32_t)(row * LDA_S + kk + lcol) * 2);
                }
                uint32_t b[NF][2];
#pragma unroll
                for (int nf2 = 0; nf2 < NF / 2; nf2++) {
                    int n0 = wn * (N / 2) + nf2 * 16;
                    uint32_t r4[4];
                    ldm_x4t(r4, bsBase + (uint32_t)((kk + lrow) * LDB_S + n0 + lcol) * 2);
                    b[nf2 * 2][0] = r4[0]; b[nf2 * 2][1] = r4[1];
                    b[nf2 * 2 + 1][0] = r4[2]; b[nf2 * 2 + 1][1] = r4[3];
                }
                if (NF & 1) {
                    int n0 = wn * (N / 2) + (NF - 1) * 8;
                    ldm_x2t(b[NF - 1], bsBase + (uint32_t)((kk + lrow) * LDB_S + n0) * 2);
                }
#pragma unroll
                for (int mf = 0; mf < 2; mf++)
#pragma unroll
                    for (int nf = 0; nf < NF; nf++)
                        mma_f16(acc[mf][nf], a[mf][0], a[mf][1], a[mf][2], a[mf][3],
                                b[nf][0], b[nf][1]);
            }
            __syncthreads();
        }

        // ---- epilogue ----
#pragma unroll
        for (int mf = 0; mf < 2; mf++) {
            const int r0 = row0 + wm * 32 + mf * 16 + g;
            const int r1 = r0 + 8;
#pragma unroll
            for (int nf = 0; nf < NF; nf++) {
                const int col = wn * (N / 2) + nf * 8 + tg * 2;
                float c0 = acc[mf][nf][0], c1 = acc[mf][nf][1];
                float c2 = acc[mf][nf][2], c3 = acc[mf][nf][3];
                if (!VEXT || col < NC) {
                    if (bias) {
                        float b0v = bias[col], b1v = bias[col + 1];
                        c0 += b0v; c1 += b1v; c2 += b0v; c3 += b1v;
                    }
                    if (HALF) {
                        __half* C = (__half*)Cv;
                        if (r0 < M)
                            *reinterpret_cast<__half2*>(C + (size_t)r0 * NC + col) =
                                __floats2half2_rn(c0, c1);
                        if (r1 < M)
                            *reinterpret_cast<__half2*>(C + (size_t)r1 * NC + col) =
                                __floats2half2_rn(c2, c3);
                    } else {
                        float* C = (float*)Cv;
                        if (r0 < M)
                            *reinterpret_cast<float2*>(C + (size_t)r0 * NC + col) = make_float2(c0, c1);
                        if (r1 < M)
                            *reinterpret_cast<float2*>(C + (size_t)r1 * NC + col) = make_float2(c2, c3);
                    }
                } else {
                    const int lc = col - NC;
                    if (r0 < M)
                        *reinterpret_cast<float2*>(Lb + (size_t)r0 * 16 + lc) = make_float2(c0, c1);
                    if (r1 < M)
                        *reinterpret_cast<float2*>(Lb + (size_t)r1 * 16 + lc) = make_float2(c2, c3);
                }
            }
        }
        if (DUAL && pass == 0) __syncthreads();
    }
}

// ---------------------------------------------------------------------------
// Merged CSR build
// ---------------------------------------------------------------------------
__global__ void hist3_k(const int* __restrict__ dc, const int* __restrict__ dw,
                        const int* __restrict__ db, int* __restrict__ degs) {
    int e = blockIdx.x * blockDim.x + threadIdx.x;
    if (e >= ETOT) return;
    int slot;
    if (e < ECITES)                slot = dc[e];
    else if (e < ECITES + EWRITES) slot = NPAPER + dw[e - ECITES];
    else                           slot = 2 * NPAPER + db[e - ECITES - EWRITES];
    atomicAdd(&degs[slot], 1);
}

__global__ void scanA_k(const int* __restrict__ deg, int* __restrict__ off,
                        int* __restrict__ bsum, int n) {
    __shared__ int sh[256];
    const int t = threadIdx.x, b = blockIdx.x;
    const int base = b * 2048 + t * 8;
    int v[8], s = 0;
#pragma unroll
    for (int i = 0; i < 8; i++) {
        int idx = base + i;
        v[i] = (idx < n) ? deg[idx] : 0;
        s += v[i];
    }
    sh[t] = s;
    __syncthreads();
    for (int o = 1; o < 256; o <<= 1) {
        int y = (t >= o) ? sh[t - o] : 0;
        __syncthreads();
        sh[t] += y;
        __syncthreads();
    }
    int run = sh[t] - s;
    if (t == 255) bsum[b] = sh[255];
#pragma unroll
    for (int i = 0; i < 8; i++) {
        int idx = base + i;
        if (idx < n) off[idx] = run;
        run += v[i];
    }
}

__global__ void scanB_k(int* __restrict__ bsum, int nb) {
    __shared__ int sh[256];
    int t = threadIdx.x;
    int v = (t < nb) ? bsum[t] : 0;
    sh[t] = v;
    __syncthreads();
    for (int o = 1; o < 256; o <<= 1) {
        int y = (t >= o) ? sh[t - o] : 0;
        __syncthreads();
        sh[t] += y;
        __syncthreads();
    }
    if (t < nb) bsum[t] = sh[t] - v;
}

__global__ void scanC_k(int* __restrict__ off, int* __restrict__ cur,
                        const int* __restrict__ bsum, int n) {
    int i = blockIdx.x * blockDim.x + threadIdx.x;
    if (i >= n) return;
    int v = off[i] + bsum[i >> 11];
    off[i] = v;
    cur[i] = v;
}

__global__ void scatter3_k(const int* __restrict__ sc, const int* __restrict__ dc,
                           const int* __restrict__ sw, const int* __restrict__ dw,
                           const int* __restrict__ sb, const int* __restrict__ db,
                           int* __restrict__ curs, int* __restrict__ srcs) {
    int e = blockIdx.x * blockDim.x + threadIdx.x;
    if (e >= ETOT) return;
    int slot, sv;
    if (e < ECITES)                { slot = dc[e]; sv = sc[e]; }
    else if (e < ECITES + EWRITES) { int i = e - ECITES; slot = NPAPER + dw[i]; sv = sw[i]; }
    else                           { int i = e - ECITES - EWRITES; slot = 2 * NPAPER + db[i]; sv = sb[i]; }
    srcs[atomicAdd(&curs[slot], 1)] = sv;
}

// ---------------------------------------------------------------------------
// Dst-major GAT aggregation: 2 nodes per warp, lane owns 8 channels (uint4).
// ---------------------------------------------------------------------------
__device__ __forceinline__ float lrelu02(float v) { return v > 0.f ? v : 0.2f * v; }

struct F8 { float v[8]; };

__device__ __forceinline__ F8 gather_h8(const __half* __restrict__ hbuf,
                                        int sidx, int l16) {
    uint4 u = reinterpret_cast<const uint4*>(hbuf + (size_t)sidx * HID)[l16];
    F8 r;
    const uint32_t* p = &u.x;
#pragma unroll
    for (int i = 0; i < 4; i++) {
        __half2 h2 = *reinterpret_cast<const __half2*>(&p[i]);
        float2 f = __half22float2(h2);
        r.v[2 * i] = f.x;
        r.v[2 * i + 1] = f.y;
    }
    return r;
}

__device__ __forceinline__ void agg_rel(const int* __restrict__ srcs, int st, int d,
                                        const float* __restrict__ Lsrc, float ad,
                                        const __half* __restrict__ hbuf,
                                        int l16, int h, float* a, float& s) {
    int j = 0;
    for (; j + 2 <= d; j += 2) {
        int s0 = srcs[st + j];
        int s1 = srcs[st + j + 1];
        float l0 = Lsrc[(size_t)s0 * 16 + h];
        float l1 = Lsrc[(size_t)s1 * 16 + h];
        F8 h0 = gather_h8(hbuf, s0, l16);
        F8 h1 = gather_h8(hbuf, s1, l16);
        float x0 = __expf(lrelu02(l0 + ad));
        float x1 = __expf(lrelu02(l1 + ad));
        s += x0 + x1;
#pragma unroll
        for (int i = 0; i < 8; i++) a[i] += x0 * h0.v[i] + x1 * h1.v[i];
    }
    if (j < d) {
        int s0 = srcs[st + j];
        float x0 = __expf(lrelu02(Lsrc[(size_t)s0 * 16 + h] + ad));
        F8 h0 = gather_h8(hbuf, s0, l16);
        s += x0;
#pragma unroll
        for (int i = 0; i < 8; i++) a[i] += x0 * h0.v[i];
    }
}

__device__ __forceinline__ void store_h8(__half* __restrict__ out, int n, int l16,
                                         const float* o) {
    uint4 u;
    uint32_t* p = &u.x;
#pragma unroll
    for (int i = 0; i < 4; i++) {
        __half2 h2 = __floats2half2_rn(o[2 * i], o[2 * i + 1]);
        p[i] = *reinterpret_cast<uint32_t*>(&h2);
    }
    reinterpret_cast<uint4*>(out + (size_t)n * HID)[l16] = u;
}

// Merged layer-0 aggregation: paper (2 relations) + author (1 relation).
__global__ void agg_l0_k(
    const int* __restrict__ srcs, const int* __restrict__ offs, const int* __restrict__ degs,
    const float* __restrict__ LP1, const __half* __restrict__ HP0,
    const float* __restrict__ LA,  const __half* __restrict__ HA1,
    const float* __restrict__ LP2, const __half* __restrict__ HP2,
    const float* __restrict__ BB, __half* __restrict__ XPB, __half* __restrict__ XAB) {
    const int gid  = blockIdx.x * blockDim.x + threadIdx.x;
    const int lane = threadIdx.x & 31;
    const int l16  = lane & 15;
    const int n    = ((gid >> 5) << 1) + (lane >> 4);
    if (n >= NPAPER + NAUTHOR) return;
    const int h = l16 >> 2;

    if (n < NPAPER) {
        float a1[8] = {0, 0, 0, 0, 0, 0, 0, 0};
        float s1 = 0.f;
        agg_rel(srcs, offs[n], degs[n], LP1, LP1[(size_t)n * 16 + 4 + h], HP0, l16, h, a1, s1);
        float a2[8] = {0, 0, 0, 0, 0, 0, 0, 0};
        float s2 = 0.f;
        agg_rel(srcs, offs[NPAPER + n], degs[NPAPER + n], LA, LP1[(size_t)n * 16 + 8 + h],
                HA1, l16, h, a2, s2);
        float i1 = 1.f / (s1 + 1e-16f);
        float i2 = 1.f / (s2 + 1e-16f);
        float4 ba_ = reinterpret_cast<const float4*>(BB)[l16 * 2];
        float4 bb_ = reinterpret_cast<const float4*>(BB)[l16 * 2 + 1];
        float4 ca_ = reinterpret_cast<const float4*>(BB + 128)[l16 * 2];
        float4 cb_ = reinterpret_cast<const float4*>(BB + 128)[l16 * 2 + 1];
        float bsum[8] = {ba_.x + ca_.x, ba_.y + ca_.y, ba_.z + ca_.z, ba_.w + ca_.w,
                         bb_.x + cb_.x, bb_.y + cb_.y, bb_.z + cb_.z, bb_.w + cb_.w};
        float o[8];
#pragma unroll
        for (int i = 0; i < 8; i++) {
            float v = a1[i] * i1 + a2[i] * i2 + bsum[i];
            o[i] = (v < 0.f) ? 0.01f * v : v;
        }
        store_h8(XPB, n, l16, o);
    } else {
        const int m = n - NPAPER;
        float a1[8] = {0, 0, 0, 0, 0, 0, 0, 0};
        float s1 = 0.f;
        agg_rel(srcs, offs[2 * NPAPER + m], degs[2 * NPAPER + m], LP2,
                LA[(size_t)m * 16 + 4 + h], HP2, l16, h, a1, s1);
        float i1 = 1.f / (s1 + 1e-16f);
        float4 ba_ = reinterpret_cast<const float4*>(BB + 256)[l16 * 2];
        float4 bb_ = reinterpret_cast<const float4*>(BB + 256)[l16 * 2 + 1];
        float bs[8] = {ba_.x, ba_.y, ba_.z, ba_.w, bb_.x, bb_.y, bb_.z, bb_.w};
        float o[8];
#pragma unroll
        for (int i = 0; i < 8; i++) {
            float v = a1[i] * i1 + bs[i];
            o[i] = (v < 0.f) ? 0.01f * v : v;
        }
        store_h8(XAB, m, l16, o);
    }
}

// Layer-1 paper aggregation (no activation).
__global__ void agg_paper_k(
    const int* __restrict__ srcs, const int* __restrict__ offs, const int* __restrict__ degs,
    const float* __restrict__ LP1, const __half* __restrict__ h1,
    const float* __restrict__ LA,  const __half* __restrict__ h2,
    const float* __restrict__ bb, __half* __restrict__ out) {
    const int gid  = blockIdx.x * blockDim.x + threadIdx.x;
    const int lane = threadIdx.x & 31;
    const int l16  = lane & 15;
    const int n    = ((gid >> 5) << 1) + (lane >> 4);
    if (n >= NPAPER) return;
    const int h = l16 >> 2;

    float a1[8] = {0, 0, 0, 0, 0, 0, 0, 0};
    float s1 = 0.f;
    agg_rel(srcs, offs[n], degs[n], LP1, LP1[(size_t)n * 16 + 4 + h], h1, l16, h, a1, s1);
    float a2[8] = {0, 0, 0, 0, 0, 0, 0, 0};
    float s2 = 0.f;
    agg_rel(srcs, offs[NPAPER + n], degs[NPAPER + n], LA, LP1[(size_t)n * 16 + 8 + h],
            h2, l16, h, a2, s2);

    float i1 = 1.f / (s1 + 1e-16f);
    float i2 = 1.f / (s2 + 1e-16f);
    float4 bv1a = reinterpret_cast<const float4*>(bb)[l16 * 2];
    float4 bv1b = reinterpret_cast<const float4*>(bb)[l16 * 2 + 1];
    float4 bv2a = reinterpret_cast<const float4*>(bb + 128)[l16 * 2];
    float4 bv2b = reinterpret_cast<const float4*>(bb + 128)[l16 * 2 + 1];
    float bsum[8] = {bv1a.x + bv2a.x, bv1a.y + bv2a.y, bv1a.z + bv2a.z, bv1a.w + bv2a.w,
                     bv1b.x + bv2b.x, bv1b.y + bv2b.y, bv1b.z + bv2b.z, bv1b.w + bv2b.w};
    float o[8];
#pragma unroll
    for (int i = 0; i < 8; i++)
        o[i] = a1[i] * i1 + a2[i] * i2 + bsum[i];
    store_h8(out, n, l16, o);
}

// ---------------------------------------------------------------------------
// Host orchestration
// ---------------------------------------------------------------------------
static inline int gemm_smem(int N, int ach) {
    return (ach * 128 * 136 + 128 * (N + 8)) * 2;
}

extern "C" void kernel_launch(void* const* d_in, const int* in_sizes, int n_in,
                              void* d_out, int out_size) {
    const float* x_paper  = (const float*)d_in[0];
    const float* x_author = (const float*)d_in[1];
    const float* Wp   = (const float*)d_in[2];
    const float* bp   = (const float*)d_in[3];
    const float* Wa   = (const float*)d_in[4];
    const float* ba   = (const float*)d_in[5];
    const float* W0   = (const float*)d_in[6];
    const float* as0  = (const float*)d_in[7];
    const float* ad0  = (const float*)d_in[8];
    const float* b0   = (const float*)d_in[9];
    const float* W1   = (const float*)d_in[10];
    const float* as1  = (const float*)d_in[11];
    const float* ad1  = (const float*)d_in[12];
    const float* b1   = (const float*)d_in[13];
    const float* Wlin = (const float*)d_in[14];
    const float* blin = (const float*)d_in[15];
    const int* src_c  = (const int*)d_in[16];
    const int* dst_c  = (const int*)d_in[17];
    const int* src_w  = (const int*)d_in[18];
    const int* dst_w  = (const int*)d_in[19];
    const int* src_b  = (const int*)d_in[20];
    const int* dst_b  = (const int*)d_in[21];

    float* S = nullptr;
    cudaGetSymbolAddress((void**)&S, g_scratch);
    __half* Hh = nullptr;
    cudaGetSymbolAddress((void**)&Hh, g_hscratch);
    int* I = nullptr;
    cudaGetSymbolAddress((void**)&I, g_iscratch);

    float*  LP1 = S + O_LP1;
    float*  LP2 = S + O_LP2;
    float*  LA  = S + O_LA;
    float*  VF  = S + O_VF;
    float*  BB  = S + O_BB;
    __half* XPA = Hh + H_XPA;
    __half* XPB = Hh + H_XPB;
    __half* XAB = Hh + H_XAB;
    __half* HP0 = Hh + H_HP0;
    __half* HP2 = Hh + H_HP2;
    __half* HA1 = Hh + H_HA1;
    __half* HW1 = Hh + H_W1;
    __half* HWL = Hh + H_WLIN;
    __half* CWP0 = Hh + H_CWP0;
    __half* CWP2 = Hh + H_CWP2;
    __half* CWA  = Hh + H_CWA;
    __half* CV0  = Hh + H_CV0;
    __half* CV2  = Hh + H_CV2;
    __half* CVA  = Hh + H_CVA;
    __half* V16  = Hh + H_V16;

    int* DEGS = I + I_DEGS;
    int* OFFS = I + I_OFFS;
    int* CURS = I + I_CURS;
    int* SRCS = I + I_SRCS;
    int* BS   = I + I_BS;

    const int smDual = gemm_smem(144, 2);
    const int sm144  = gemm_smem(144, 1);
    const int sm64   = gemm_smem(64, 1);
    cudaFuncSetAttribute(mma_gemm<144, 2, true,  true,  false, true,  false>, cudaFuncAttributeMaxDynamicSharedMemorySize, smDual);
    cudaFuncSetAttribute(mma_gemm<144, 1, true,  true,  false, false, false>, cudaFuncAttributeMaxDynamicSharedMemorySize, sm144);
    cudaFuncSetAttribute(mma_gemm<144, 1, true,  true,  true,  false, true >, cudaFuncAttributeMaxDynamicSharedMemorySize, sm144);
    cudaFuncSetAttribute(mma_gemm<64,  1, false, false, true,  false, false>, cudaFuncAttributeMaxDynamicSharedMemorySize, sm64);

    const int TP = (NPAPER + 127) / 128;
    const int TA = (NAUTHOR + 127) / 128;

    // ---- prep + merged CSR build ----
    prep_w_k<<<224, 256>>>(W1, Wlin, HW1, HWL);
    prep_v_k<<<40, 256>>>(W0, as0, ad0, W1, as1, ad1, VF);
    prep_cw_k<<<378, 256>>>(Wp, Wa, W0, bp, ba, b0, VF,
                            CWP0, CWP2, CWA, CV0, CV2, CVA, V16, BB);
    cudaMemsetAsync(DEGS, 0, (size_t)NTOT * sizeof(int));
    hist3_k<<<(ETOT + 255) / 256, 256>>>(dst_c, dst_w, dst_b, DEGS);
    const int NB = (NTOT + 2047) / 2048;
    scanA_k<<<NB, 256>>>(DEGS, OFFS, BS, NTOT);
    scanB_k<<<1, 256>>>(BS, NB);
    scanC_k<<<(NTOT + 255) / 256, 256>>>(OFFS, CURS, BS, NTOT);
    scatter3_k<<<(ETOT + 255) / 256, 256>>>(src_c, dst_c, src_w, dst_w, src_b, dst_b,
                                            CURS, SRCS);

    // ---- layer 0 (projection folded): A = raw fp32 inputs ----
    mma_gemm<144, 2, true, true, false, true, false><<<TP, 256, smDual>>>(
        x_paper, CWP0, CV0, HP0, LP1, CWP2, CV2, HP2, LP2, nullptr, NPAPER,
        nullptr, 0, 0);
    mma_gemm<144, 1, true, true, false, false, false><<<TA, 256, sm144>>>(
        x_author, CWA, CVA, HA1, LA,
        nullptr, nullptr, nullptr, nullptr, nullptr, NAUTHOR, nullptr, 0, 0);

    agg_l0_k<<<((NPAPER + NAUTHOR) * 16 + 255) / 256, 256>>>(
        SRCS, OFFS, DEGS, LP1, HP0, LA, HA1, LP2, HP2, BB, XPB, XAB);

    // ---- layer 1: paper + author GEMMs paired in one launch ----
    mma_gemm<144, 1, true, true, true, false, true><<<TP + TA, 256, sm144>>>(
        XPB, HW1 + 0 * HID * HID, V16 + 0 * 2048, HP0, LP1,
        HW1 + 1 * HID * HID, V16 + 1 * 2048, HA1, LA,
        nullptr, NPAPER, XAB, NAUTHOR, TP);

    agg_paper_k<<<(NPAPER * 16 + 255) / 256, 256>>>(
        SRCS, OFFS, DEGS, LP1, HP0, LA, HA1, b1, XPA);

    // ---- classifier: [200000,128] fp16 @ [128,64] fp16 + blin -> fp32 out ----
    mma_gemm<64, 1, false, false, true, false, false><<<TP, 256, sm64>>>(
        XPA, HWL, nullptr, d_out, nullptr,
        nullptr, nullptr, nullptr, nullptr, blin, NPAPER, nullptr, 0, 0);
}